// round 4
// baseline (speedup 1.0000x reference)
#include <cuda_runtime.h>
#include <math.h>
#include <stdint.h>

#define NNODES 50000
#define NHALF  25000
#define NEDGES 400000
#define F512   512
#define H8     8

// ---------------- scratch (device globals; no allocation allowed) ----------------
__device__ float g_h0[NNODES * 64];
__device__ float g_ft[NNODES * F512];
__device__ float g_h1[NNODES * F512];
__device__ float g_el[NNODES * H8];
__device__ float g_er[NNODES * H8];
__device__ float g_e[NEDGES * H8];
__device__ float g_ft2[NNODES * 16];
__device__ float g_res2[NNODES * 16];
__device__ int   g_deg[NNODES];
__device__ int   g_cur[NNODES];
__device__ int   g_rowoff[NNODES + 1];
__device__ int   g_eid[NEDGES];

__device__ __forceinline__ float* bufsel(int id) {
    switch (id) {
        case 0: return g_h0;
        case 1: return g_ft;
        case 2: return g_h1;
    }
    return nullptr;
}

// ---------------- CSR build ----------------
__global__ void k_zero_counts() {
    int i = blockIdx.x * blockDim.x + threadIdx.x;
    if (i < NNODES) { g_deg[i] = 0; g_cur[i] = 0; }
}

__global__ void k_count(const int* __restrict__ dst) {
    int i = blockIdx.x * blockDim.x + threadIdx.x;
    if (i < NEDGES) {
        int d = dst[i];
        if (d >= 0 && d < NNODES) atomicAdd(&g_deg[d], 1);
    }
}

__global__ void k_scan() {
    __shared__ int warp_sums[32];
    __shared__ int carry_sh;
    int t = threadIdx.x;
    if (t == 0) carry_sh = 0;
    __syncthreads();
    for (int base = 0; base < NNODES; base += 1024) {
        int i = base + t;
        int v = (i < NNODES) ? g_deg[i] : 0;
        int x = v;
        #pragma unroll
        for (int o = 1; o < 32; o <<= 1) {
            int y = __shfl_up_sync(0xffffffffu, x, o);
            if ((t & 31) >= o) x += y;
        }
        if ((t & 31) == 31) warp_sums[t >> 5] = x;
        __syncthreads();
        if (t < 32) {
            int w = warp_sums[t];
            #pragma unroll
            for (int o = 1; o < 32; o <<= 1) {
                int y = __shfl_up_sync(0xffffffffu, w, o);
                if (t >= o) w += y;
            }
            warp_sums[t] = w;
        }
        __syncthreads();
        int pref = (t >= 32) ? warp_sums[(t >> 5) - 1] : 0;
        int incl = x + pref;
        int carry = carry_sh;
        if (i < NNODES) g_rowoff[i] = carry + incl - v;
        __syncthreads();
        if (t == 1023) carry_sh = carry + incl;
        __syncthreads();
    }
    if (t == 0) g_rowoff[NNODES] = carry_sh;
}

__global__ void k_scatter(const int* __restrict__ dst) {
    int i = blockIdx.x * blockDim.x + threadIdx.x;
    if (i < NEDGES) {
        int d = dst[i];
        if (d >= 0 && d < NNODES) {
            int p = g_rowoff[d] + atomicAdd(&g_cur[d], 1);
            g_eid[p] = i;
        }
    }
}

__global__ void k_sortseg() {
    int n = blockIdx.x * blockDim.x + threadIdx.x;
    if (n >= NNODES) return;
    int s = g_rowoff[n], e = g_rowoff[n + 1];
    for (int i = s + 1; i < e; i++) {
        int key = g_eid[i];
        int j = i - 1;
        while (j >= s && g_eid[j] > key) { g_eid[j + 1] = g_eid[j]; j--; }
        g_eid[j + 1] = key;
    }
}

// ---------------- 3xTF32 tensor-core GEMM ----------------
// C[M,N] = A[M,K] @ B[K,N] (+ bias). Block tile 128x64, BK=32, 256 thr (8 warps 4x2).
// Warp tile 32x32 = 2(m16) x 4(n8) fragments of mma.sync.m16n8k8.tf32.
// Requires K%32==0, N%64==0. A/C selectable from scratch via ids.
__device__ __forceinline__ uint32_t f2tf32(float x) {
    uint32_t r;
    asm("cvt.rna.tf32.f32 %0, %1;" : "=r"(r) : "f"(x));
    return r;
}

__device__ __forceinline__ void mma8(float* c, const uint32_t* a, const uint32_t* b) {
    asm("mma.sync.aligned.m16n8k8.row.col.f32.tf32.tf32.f32 "
        "{%0,%1,%2,%3}, {%4,%5,%6,%7}, {%8,%9}, {%0,%1,%2,%3};"
        : "+f"(c[0]), "+f"(c[1]), "+f"(c[2]), "+f"(c[3])
        : "r"(a[0]), "r"(a[1]), "r"(a[2]), "r"(a[3]), "r"(b[0]), "r"(b[1]));
}

__global__ __launch_bounds__(256) void gemm_tf32(
    const float* __restrict__ Aext, int a_id,
    float* __restrict__ Cext, int c_id, size_t c_off,
    const float* __restrict__ B,
    int M, int N, int K, const float* __restrict__ bias)
{
    // fragment-order smem: As[hl][F(8)][s(4)][lane(32)][reg(4)], Bs[hl][nf(8)][s(4)][lane(32)][reg(2)]
    __shared__ uint32_t As[2][4096];   // 32 KB
    __shared__ uint32_t Bs[2][2048];   // 16 KB

    const float* A = Aext ? Aext : bufsel(a_id);
    float* C = (Cext ? Cext : bufsel(c_id)) + c_off;

    int tid  = threadIdx.x;
    int lane = tid & 31;
    int w    = tid >> 5;
    int wm   = w & 3;          // 0..3  (M dir, 32 rows each)
    int wn   = w >> 2;         // 0..1  (N dir, 32 cols each)
    int bm0  = blockIdx.y * 128;
    int bn0  = blockIdx.x * 64;

    float acc[2][4][4];
    #pragma unroll
    for (int mf = 0; mf < 2; mf++)
        #pragma unroll
        for (int nf = 0; nf < 4; nf++)
            #pragma unroll
            for (int i = 0; i < 4; i++) acc[mf][nf][i] = 0.f;

    for (int k0 = 0; k0 < K; k0 += 32) {
        // stage gmem -> regs
        float4 aval[4];
        #pragma unroll
        for (int i = 0; i < 4; i++) {
            int idx = tid + i * 256;
            int r   = idx >> 3;             // 0..127
            int kc  = (idx & 7) * 4;        // 0,4,...,28
            int gr  = bm0 + r;
            aval[i] = (gr < M) ? *(const float4*)&A[(size_t)gr * K + k0 + kc]
                               : make_float4(0.f, 0.f, 0.f, 0.f);
        }
        float4 bval[2];
        #pragma unroll
        for (int i = 0; i < 2; i++) {
            int idx = tid + i * 256;
            int kr  = idx >> 4;             // 0..31
            int nc  = (idx & 15) * 4;
            bval[i] = *(const float4*)&B[(size_t)(k0 + kr) * N + bn0 + nc];
        }
        __syncthreads();   // previous compute done before overwrite
        // A -> fragment-order smem (hi/lo)
        #pragma unroll
        for (int i = 0; i < 4; i++) {
            int idx = tid + i * 256;
            int r   = idx >> 3;
            int kc  = (idx & 7) * 4;
            int F   = r >> 4;
            int s   = kc >> 3;
            int reg = ((r >> 3) & 1) | (((kc >> 2) & 1) << 1);
            int base = (((F * 4 + s) * 32) + (r & 7) * 4) * 4 + reg;
            float v[4] = {aval[i].x, aval[i].y, aval[i].z, aval[i].w};
            #pragma unroll
            for (int j = 0; j < 4; j++) {
                uint32_t hi = f2tf32(v[j]);
                As[0][base + j * 4] = hi;
                As[1][base + j * 4] = f2tf32(v[j] - __uint_as_float(hi));
            }
        }
        // B -> fragment-order smem (hi/lo)
        #pragma unroll
        for (int i = 0; i < 2; i++) {
            int idx = tid + i * 256;
            int kr  = idx >> 4;
            int nc  = (idx & 15) * 4;
            int s   = kr >> 3;
            int reg = (kr >> 2) & 1;
            float v[4] = {bval[i].x, bval[i].y, bval[i].z, bval[i].w};
            #pragma unroll
            for (int j = 0; j < 4; j++) {
                int n   = nc + j;
                int pos = (((n >> 3) * 4 + s) * 32 + (n & 7) * 4 + (kr & 3)) * 2 + reg;
                uint32_t hi = f2tf32(v[j]);
                Bs[0][pos] = hi;
                Bs[1][pos] = f2tf32(v[j] - __uint_as_float(hi));
            }
        }
        __syncthreads();
        // compute: 4 k-steps of 8
        #pragma unroll
        for (int s = 0; s < 4; s++) {
            uint32_t ah[2][4], al[2][4], bh[4][2], bl[4][2];
            #pragma unroll
            for (int mf = 0; mf < 2; mf++) {
                int F   = wm * 2 + mf;
                int off = ((F * 4 + s) * 32 + lane) * 4;
                uint4 h = *(const uint4*)&As[0][off];
                uint4 l = *(const uint4*)&As[1][off];
                ah[mf][0] = h.x; ah[mf][1] = h.y; ah[mf][2] = h.z; ah[mf][3] = h.w;
                al[mf][0] = l.x; al[mf][1] = l.y; al[mf][2] = l.z; al[mf][3] = l.w;
            }
            #pragma unroll
            for (int nf = 0; nf < 4; nf++) {
                int NF  = wn * 4 + nf;
                int off = ((NF * 4 + s) * 32 + lane) * 2;
                uint2 h = *(const uint2*)&Bs[0][off];
                uint2 l = *(const uint2*)&Bs[1][off];
                bh[nf][0] = h.x; bh[nf][1] = h.y;
                bl[nf][0] = l.x; bl[nf][1] = l.y;
            }
            #pragma unroll
            for (int mf = 0; mf < 2; mf++)
                #pragma unroll
                for (int nf = 0; nf < 4; nf++) {
                    mma8(acc[mf][nf], ah[mf], bh[nf]);
                    mma8(acc[mf][nf], ah[mf], bl[nf]);
                    mma8(acc[mf][nf], al[mf], bh[nf]);
                }
        }
    }
    // epilogue
    #pragma unroll
    for (int mf = 0; mf < 2; mf++) {
        int r0 = bm0 + wm * 32 + mf * 16 + (lane >> 2);
        #pragma unroll
        for (int nf = 0; nf < 4; nf++) {
            int c0 = bn0 + wn * 32 + nf * 8 + (lane & 3) * 2;
            float bz0 = bias ? bias[c0] : 0.f;
            float bz1 = bias ? bias[c0 + 1] : 0.f;
            if (r0 < M) {
                C[(size_t)r0 * N + c0]     = acc[mf][nf][0] + bz0;
                C[(size_t)r0 * N + c0 + 1] = acc[mf][nf][1] + bz1;
            }
            if (r0 + 8 < M) {
                C[(size_t)(r0 + 8) * N + c0]     = acc[mf][nf][2] + bz0;
                C[(size_t)(r0 + 8) * N + c0 + 1] = acc[mf][nf][3] + bz1;
            }
        }
    }
}

// ---------------- attention coefficients (H=8, D=64) ----------------
__global__ __launch_bounds__(256) void k_elr8(
    const float* __restrict__ al, const float* __restrict__ ar)
{
    int gw = (blockIdx.x * blockDim.x + threadIdx.x) >> 5;   // n*8+h
    int lane = threadIdx.x & 31;
    int n = gw >> 3, h = gw & 7;
    const float* fb = g_ft + (size_t)n * 512 + h * 64;
    float a = fb[lane], b = fb[lane + 32];
    float vl = a * al[h * 64 + lane] + b * al[h * 64 + lane + 32];
    float vr = a * ar[h * 64 + lane] + b * ar[h * 64 + lane + 32];
    #pragma unroll
    for (int o = 16; o > 0; o >>= 1) {
        vl += __shfl_xor_sync(0xffffffffu, vl, o);
        vr += __shfl_xor_sync(0xffffffffu, vr, o);
    }
    if (lane == 0) { g_el[gw] = vl; g_er[gw] = vr; }
}

// ---------------- per-edge raw attention logits ----------------
template <int H>
__global__ void k_edge_e(const int* __restrict__ src, const int* __restrict__ dst)
{
    int t = blockIdx.x * blockDim.x + threadIdx.x;
    if (t >= NEDGES * H) return;
    int eid = t / H, h = t % H;
    int s = src[eid], d = dst[eid];
    float x = g_el[s * H + h] + g_er[d * H + h];
    g_e[t] = (x >= 0.f) ? x : 0.2f * x;
}

// ---------------- segment softmax over dst ----------------
template <int H>
__global__ void k_softmax()
{
    int t = blockIdx.x * blockDim.x + threadIdx.x;
    if (t >= NNODES * H) return;
    int n = t / H, h = t % H;
    int s0 = g_rowoff[n], s1 = g_rowoff[n + 1];
    float m = -1e30f;
    for (int p = s0; p < s1; p++) m = fmaxf(m, g_e[g_eid[p] * H + h]);
    float sum = 0.f;
    for (int p = s0; p < s1; p++) {
        int idx = g_eid[p] * H + h;
        float ex = expf(g_e[idx] - m);
        g_e[idx] = ex;
        sum += ex;
    }
    float inv = 1.f / (sum + 1e-16f);
    for (int p = s0; p < s1; p++) g_e[g_eid[p] * H + h] *= inv;
}

// ---------------- aggregation, F=512, H=8 ----------------
__global__ __launch_bounds__(128) void k_agg512(
    const int* __restrict__ src,
    const float* __restrict__ bias, int use_resid,
    float* __restrict__ out_ext)
{
    const float* ft = g_ft;
    float* out = out_ext ? out_ext : g_h1;
    int n = blockIdx.x;
    int t = threadIdx.x;
    int f = t * 4;
    int h = f >> 6;
    float4 acc = *(const float4*)&bias[f];
    if (use_resid) {
        float4 r = *(const float4*)&g_h1[(size_t)n * 512 + f];
        acc.x += r.x; acc.y += r.y; acc.z += r.z; acc.w += r.w;
    }
    int s0 = g_rowoff[n], s1 = g_rowoff[n + 1];
    for (int p = s0; p < s1; p++) {
        int eid = g_eid[p];
        float w = g_e[(size_t)eid * 8 + h];
        int s = src[eid];
        float4 v = *(const float4*)&ft[(size_t)s * 512 + f];
        acc.x = fmaf(w, v.x, acc.x);
        acc.y = fmaf(w, v.y, acc.y);
        acc.z = fmaf(w, v.z, acc.z);
        acc.w = fmaf(w, v.w, acc.w);
    }
    acc.x = (acc.x > 0.f) ? acc.x : expm1f(acc.x);
    acc.y = (acc.y > 0.f) ? acc.y : expm1f(acc.y);
    acc.z = (acc.z > 0.f) ? acc.z : expm1f(acc.z);
    acc.w = (acc.w > 0.f) ? acc.w : expm1f(acc.w);
    *(float4*)&out[(size_t)n * 512 + f] = acc;
}

// ---------------- layer-2 projections ----------------
__global__ __launch_bounds__(32) void k_l2proj(
    const float* __restrict__ h2, const float* __restrict__ W2,
    const float* __restrict__ resW2, const float* __restrict__ al2,
    const float* __restrict__ ar2)
{
    int n = blockIdx.x;
    int lane = threadIdx.x;
    float a1 = 0.f, a2 = 0.f;
    const float* hr = h2 + (size_t)n * 512;
    if (lane < 16) {
        #pragma unroll 8
        for (int k = 0; k < 512; k++) {
            float hv = hr[k];
            a1 = fmaf(hv, W2[k * 16 + lane], a1);
            a2 = fmaf(hv, resW2[k * 16 + lane], a2);
        }
    }
    float el_p = (lane < 16) ? a1 * al2[lane] : 0.f;
    float er_p = (lane < 16) ? a1 * ar2[lane] : 0.f;
    #pragma unroll
    for (int o = 16; o > 0; o >>= 1) {
        el_p += __shfl_xor_sync(0xffffffffu, el_p, o);
        er_p += __shfl_xor_sync(0xffffffffu, er_p, o);
    }
    if (lane == 0) { g_el[n] = el_p; g_er[n] = er_p; }
    if (lane < 16) { g_ft2[n * 16 + lane] = a1; g_res2[n * 16 + lane] = a2; }
}

// ---------------- aggregation F=16, H=1 ----------------
__global__ __launch_bounds__(32) void k_agg16(
    const int* __restrict__ src, const float* __restrict__ b2,
    float* __restrict__ logits)
{
    int n = blockIdx.x;
    int lane = threadIdx.x;
    if (lane >= 16) return;
    float acc = g_res2[n * 16 + lane] + b2[lane];
    int s0 = g_rowoff[n], s1 = g_rowoff[n + 1];
    for (int p = s0; p < s1; p++) {
        int eid = g_eid[p];
        float w = g_e[eid];
        int s = src[eid];
        acc = fmaf(w, g_ft2[s * 16 + lane], acc);
    }
    logits[n * 16 + lane] = acc;
}

// ---------------- launch ----------------
extern "C" void kernel_launch(void* const* d_in, const int* in_sizes, int n_in,
                              void* d_out, int out_size)
{
    const float* x0    = (const float*)d_in[0];
    const float* x1    = (const float*)d_in[1];
    const int*   src   = (const int*)d_in[2];
    const int*   dst   = (const int*)d_in[3];
    const float* fc0_W = (const float*)d_in[4];
    const float* fc0_b = (const float*)d_in[5];
    const float* fc1_W = (const float*)d_in[6];
    const float* fc1_b = (const float*)d_in[7];
    const float* W0  = (const float*)d_in[8];
    const float* al0 = (const float*)d_in[9];
    const float* ar0 = (const float*)d_in[10];
    const float* b0  = (const float*)d_in[11];
    const float* W1  = (const float*)d_in[12];
    const float* al1 = (const float*)d_in[13];
    const float* ar1 = (const float*)d_in[14];
    const float* b1  = (const float*)d_in[15];
    const float* W2  = (const float*)d_in[16];
    const float* al2 = (const float*)d_in[17];
    const float* ar2 = (const float*)d_in[18];
    const float* b2  = (const float*)d_in[19];
    const float* resW2 = (const float*)d_in[20];

    float* out    = (float*)d_out;
    float* logits = out;                         // [50000,16]
    float* enc    = out + (size_t)NNODES * 16;   // [50000,512]

    // ---- CSR build ----
    k_zero_counts<<<(NNODES + 255) / 256, 256>>>();
    k_count<<<(NEDGES + 255) / 256, 256>>>(dst);
    k_scan<<<1, 1024>>>();
    k_scatter<<<(NEDGES + 255) / 256, 256>>>(dst);
    k_sortseg<<<(NNODES + 255) / 256, 256>>>();

    // ---- per-type input projections (tensor cores) ----
    dim3 gfc(1, (NHALF + 127) / 128);
    gemm_tf32<<<gfc, 256>>>(x0, -1, nullptr, 0, 0,                  fc0_W, NHALF, 64, 256, fc0_b);
    gemm_tf32<<<gfc, 256>>>(x1, -1, nullptr, 0, (size_t)NHALF * 64, fc1_W, NHALF, 64, 256, fc1_b);

    // ---- layer 0: 64 -> 8x64, elu ----
    dim3 g0(512 / 64, (NNODES + 127) / 128);
    gemm_tf32<<<g0, 256>>>(nullptr, 0, nullptr, 1, 0, W0, NNODES, 512, 64, nullptr);
    k_elr8<<<NNODES, 256>>>(al0, ar0);
    k_edge_e<8><<<(NEDGES * 8 + 255) / 256, 256>>>(src, dst);
    k_softmax<8><<<(NNODES * 8 + 255) / 256, 256>>>();
    k_agg512<<<NNODES, 128>>>(src, b0, 0, nullptr);   // -> g_h1

    // ---- layer 1: 512 -> 8x64, id residual, elu -> encoded ----
    gemm_tf32<<<g0, 256>>>(nullptr, 2, nullptr, 1, 0, W1, NNODES, 512, 512, nullptr);
    k_elr8<<<NNODES, 256>>>(al1, ar1);
    k_edge_e<8><<<(NEDGES * 8 + 255) / 256, 256>>>(src, dst);
    k_softmax<8><<<(NNODES * 8 + 255) / 256, 256>>>();
    k_agg512<<<NNODES, 128>>>(src, b1, 1, enc);       // resid=g_h1 -> enc

    // ---- output layer: 512 -> 1x16, linear residual ----
    k_l2proj<<<NNODES, 32>>>(enc, W2, resW2, al2, ar2);
    k_edge_e<1><<<(NEDGES + 255) / 256, 256>>>(src, dst);
    k_softmax<1><<<(NNODES + 255) / 256, 256>>>();
    k_agg16<<<NNODES, 32>>>(src, b2, logits);
}

// round 5
// speedup vs baseline: 1.4463x; 1.4463x over previous
#include <cuda_runtime.h>
#include <math.h>
#include <stdint.h>

#define NNODES 50000
#define NHALF  25000
#define NEDGES 400000
#define F512   512
#define H8     8

// ---------------- scratch (device globals; no allocation allowed) ----------------
__device__ float g_h0[NNODES * 64];
__device__ float g_ft[NNODES * F512];
__device__ float g_h1[NNODES * F512];
__device__ float g_el[NNODES * H8];
__device__ float g_er[NNODES * H8];
__device__ float g_e[NEDGES * H8];
__device__ float g_ft2[NNODES * 16];
__device__ float g_res2[NNODES * 16];
__device__ int   g_deg[NNODES];
__device__ int   g_cur[NNODES];
__device__ int   g_rowoff[NNODES + 1];
__device__ int   g_eid[NEDGES];

__device__ __forceinline__ float* bufsel(int id) {
    switch (id) {
        case 0: return g_h0;
        case 1: return g_ft;
        case 2: return g_h1;
    }
    return nullptr;
}

// ---------------- CSR build ----------------
__global__ void k_zero_counts() {
    int i = blockIdx.x * blockDim.x + threadIdx.x;
    if (i < NNODES) { g_deg[i] = 0; g_cur[i] = 0; }
}

__global__ void k_count(const int* __restrict__ dst) {
    int i = blockIdx.x * blockDim.x + threadIdx.x;
    if (i < NEDGES) {
        int d = dst[i];
        if (d >= 0 && d < NNODES) atomicAdd(&g_deg[d], 1);
    }
}

__global__ void k_scan() {
    __shared__ int warp_sums[32];
    __shared__ int carry_sh;
    int t = threadIdx.x;
    if (t == 0) carry_sh = 0;
    __syncthreads();
    for (int base = 0; base < NNODES; base += 1024) {
        int i = base + t;
        int v = (i < NNODES) ? g_deg[i] : 0;
        int x = v;
        #pragma unroll
        for (int o = 1; o < 32; o <<= 1) {
            int y = __shfl_up_sync(0xffffffffu, x, o);
            if ((t & 31) >= o) x += y;
        }
        if ((t & 31) == 31) warp_sums[t >> 5] = x;
        __syncthreads();
        if (t < 32) {
            int w = warp_sums[t];
            #pragma unroll
            for (int o = 1; o < 32; o <<= 1) {
                int y = __shfl_up_sync(0xffffffffu, w, o);
                if (t >= o) w += y;
            }
            warp_sums[t] = w;
        }
        __syncthreads();
        int pref = (t >= 32) ? warp_sums[(t >> 5) - 1] : 0;
        int incl = x + pref;
        int carry = carry_sh;
        if (i < NNODES) g_rowoff[i] = carry + incl - v;
        __syncthreads();
        if (t == 1023) carry_sh = carry + incl;
        __syncthreads();
    }
    if (t == 0) g_rowoff[NNODES] = carry_sh;
}

__global__ void k_scatter(const int* __restrict__ dst) {
    int i = blockIdx.x * blockDim.x + threadIdx.x;
    if (i < NEDGES) {
        int d = dst[i];
        if (d >= 0 && d < NNODES) {
            int p = g_rowoff[d] + atomicAdd(&g_cur[d], 1);
            g_eid[p] = i;
        }
    }
}

__global__ void k_sortseg() {
    int n = blockIdx.x * blockDim.x + threadIdx.x;
    if (n >= NNODES) return;
    int s = g_rowoff[n], e = g_rowoff[n + 1];
    for (int i = s + 1; i < e; i++) {
        int key = g_eid[i];
        int j = i - 1;
        while (j >= s && g_eid[j] > key) { g_eid[j + 1] = g_eid[j]; j--; }
        g_eid[j + 1] = key;
    }
}

// ---------------- GEMM: C[M,N] = A[M,K] @ B[K,N] (+ bias) -----------------------
// 64x64 tile, BK=16, 256 threads, 4x4 per thread. K%16==0, N%64==0.
// Optional fused attention reduction: when attn_al != null (N=512, H=8 layers),
// each 64-col block tile == one head h = bn0/64; block reduces
// el[row,h] = sum_d ft[row,h,d]*al[h,d] (likewise er) and writes g_el/g_er.
__global__ __launch_bounds__(256) void gemm_kernel(
    const float* __restrict__ Aext, int a_id,
    float* __restrict__ Cext, int c_id, size_t c_off,
    const float* __restrict__ B,
    int M, int N, int K, const float* __restrict__ bias,
    const float* __restrict__ attn_al, const float* __restrict__ attn_ar)
{
    const float* A = Aext ? Aext : bufsel(a_id);
    float* C = (Cext ? Cext : bufsel(c_id)) + c_off;

    __shared__ float As[16][64];
    __shared__ float Bs[16][64];
    __shared__ float sl[64][17];
    __shared__ float sr[64][17];

    int t  = threadIdx.x;
    int tx = t & 15;
    int ty = t >> 4;
    int bm0 = blockIdx.y * 64;
    int bn0 = blockIdx.x * 64;
    float acc[4][4];
    #pragma unroll
    for (int i = 0; i < 4; i++)
        #pragma unroll
        for (int j = 0; j < 4; j++) acc[i][j] = 0.f;

    int ar_ = t >> 2, ac = (t & 3) * 4;
    int br = t >> 4, bc = (t & 15) * 4;

    for (int k0 = 0; k0 < K; k0 += 16) {
        float4 av = make_float4(0.f, 0.f, 0.f, 0.f);
        if (bm0 + ar_ < M) av = *(const float4*)&A[(size_t)(bm0 + ar_) * K + k0 + ac];
        As[ac + 0][ar_] = av.x; As[ac + 1][ar_] = av.y;
        As[ac + 2][ar_] = av.z; As[ac + 3][ar_] = av.w;
        float4 bv = *(const float4*)&B[(size_t)(k0 + br) * N + bn0 + bc];
        *(float4*)&Bs[br][bc] = bv;
        __syncthreads();
        #pragma unroll
        for (int kk = 0; kk < 16; kk++) {
            float4 a4 = *(float4*)&As[kk][ty * 4];
            float4 b4 = *(float4*)&Bs[kk][tx * 4];
            float ra[4] = {a4.x, a4.y, a4.z, a4.w};
            float rb[4] = {b4.x, b4.y, b4.z, b4.w};
            #pragma unroll
            for (int i = 0; i < 4; i++)
                #pragma unroll
                for (int j = 0; j < 4; j++)
                    acc[i][j] = fmaf(ra[i], rb[j], acc[i][j]);
        }
        __syncthreads();
    }
    #pragma unroll
    for (int i = 0; i < 4; i++) {
        int row = bm0 + ty * 4 + i;
        if (row < M) {
            #pragma unroll
            for (int j = 0; j < 4; j++) {
                int col = bn0 + tx * 4 + j;
                float bz = bias ? bias[col] : 0.f;
                C[(size_t)row * N + col] = acc[i][j] + bz;
            }
        }
    }
    // fused el/er reduction (H=8 layers)
    if (attn_al) {
        int h = bn0 >> 6;
        #pragma unroll
        for (int i = 0; i < 4; i++) {
            float suml = 0.f, sumr = 0.f;
            #pragma unroll
            for (int j = 0; j < 4; j++) {
                int dcol = tx * 4 + j;
                suml = fmaf(acc[i][j], attn_al[h * 64 + dcol], suml);
                sumr = fmaf(acc[i][j], attn_ar[h * 64 + dcol], sumr);
            }
            sl[ty * 4 + i][tx] = suml;
            sr[ty * 4 + i][tx] = sumr;
        }
        __syncthreads();
        if (t < 64) {
            float el = 0.f, er = 0.f;
            #pragma unroll
            for (int x = 0; x < 16; x++) { el += sl[t][x]; er += sr[t][x]; }
            int row = bm0 + t;
            if (row < M) { g_el[row * 8 + h] = el; g_er[row * 8 + h] = er; }
        }
    }
}

// ---------------- fused edge-logit + segment softmax over dst ----------------
// one thread per (node, head). er[d] is loop-invariant.
template <int H>
__global__ void k_attn(const int* __restrict__ src)
{
    int t = blockIdx.x * blockDim.x + threadIdx.x;
    if (t >= NNODES * H) return;
    int n = t / H, h = t % H;
    int s0 = g_rowoff[n], s1 = g_rowoff[n + 1];
    float ern = g_er[n * H + h];
    float m = -1e30f;
    for (int p = s0; p < s1; p++) {
        int eid = g_eid[p];
        float x = g_el[src[eid] * H + h] + ern;
        x = (x >= 0.f) ? x : 0.2f * x;
        g_e[(size_t)eid * H + h] = x;
        m = fmaxf(m, x);
    }
    float sum = 0.f;
    for (int p = s0; p < s1; p++) {
        size_t idx = (size_t)g_eid[p] * H + h;
        float ex = expf(g_e[idx] - m);
        g_e[idx] = ex;
        sum += ex;
    }
    float inv = 1.f / (sum + 1e-16f);
    for (int p = s0; p < s1; p++) g_e[(size_t)g_eid[p] * H + h] *= inv;
}

// ---------------- aggregation, F=512, H=8: block(128) per dst node ----------------
__global__ __launch_bounds__(128) void k_agg512(
    const int* __restrict__ src,
    const float* __restrict__ bias, int use_resid,
    float* __restrict__ out_ext)
{
    const float* ft = g_ft;
    float* out = out_ext ? out_ext : g_h1;
    int n = blockIdx.x;
    int t = threadIdx.x;
    int f = t * 4;
    int h = f >> 6;
    float4 acc = *(const float4*)&bias[f];
    if (use_resid) {
        float4 r = *(const float4*)&g_h1[(size_t)n * 512 + f];
        acc.x += r.x; acc.y += r.y; acc.z += r.z; acc.w += r.w;
    }
    int s0 = g_rowoff[n], s1 = g_rowoff[n + 1];
    for (int p = s0; p < s1; p++) {
        int eid = g_eid[p];
        float w = g_e[(size_t)eid * 8 + h];
        int s = src[eid];
        float4 v = *(const float4*)&ft[(size_t)s * 512 + f];
        acc.x = fmaf(w, v.x, acc.x);
        acc.y = fmaf(w, v.y, acc.y);
        acc.z = fmaf(w, v.z, acc.z);
        acc.w = fmaf(w, v.w, acc.w);
    }
    acc.x = (acc.x > 0.f) ? acc.x : expm1f(acc.x);
    acc.y = (acc.y > 0.f) ? acc.y : expm1f(acc.y);
    acc.z = (acc.z > 0.f) ? acc.z : expm1f(acc.z);
    acc.w = (acc.w > 0.f) ? acc.w : expm1f(acc.w);
    *(float4*)&out[(size_t)n * 512 + f] = acc;
}

// ---------------- layer-2 projections (tiled, smem weight reuse) ----------------
// block = 128 threads, one node per thread; W2/resW2 tiles staged in smem.
// Also fuses el/er (H=1) from the freshly computed ft2 registers.
__global__ __launch_bounds__(128) void k_l2proj2(
    const float* __restrict__ h2, const float* __restrict__ W2,
    const float* __restrict__ resW2, const float* __restrict__ al2,
    const float* __restrict__ ar2)
{
    __shared__ float sW[64 * 16];
    __shared__ float sR[64 * 16];
    int n = blockIdx.x * 128 + threadIdx.x;
    int nc = (n < NNODES) ? n : (NNODES - 1);          // clamp loads
    const float* hr = h2 + (size_t)nc * 512;

    float a1[16], a2[16];
    #pragma unroll
    for (int c = 0; c < 16; c++) { a1[c] = 0.f; a2[c] = 0.f; }

    for (int k0 = 0; k0 < 512; k0 += 64) {
        __syncthreads();
        #pragma unroll
        for (int i = 0; i < 8; i++) {
            int idx = threadIdx.x + i * 128;           // 0..1023
            sW[idx] = W2[k0 * 16 + idx];
            sR[idx] = resW2[k0 * 16 + idx];
        }
        __syncthreads();
        #pragma unroll
        for (int kk = 0; kk < 64; kk += 4) {
            float4 hv4 = *(const float4*)&hr[k0 + kk];
            float hv[4] = {hv4.x, hv4.y, hv4.z, hv4.w};
            #pragma unroll
            for (int q = 0; q < 4; q++) {
                float hq = hv[q];
                const float4* w4 = (const float4*)&sW[(kk + q) * 16];
                const float4* r4 = (const float4*)&sR[(kk + q) * 16];
                #pragma unroll
                for (int v = 0; v < 4; v++) {
                    float4 wv = w4[v], rv = r4[v];
                    a1[v * 4 + 0] = fmaf(hq, wv.x, a1[v * 4 + 0]);
                    a1[v * 4 + 1] = fmaf(hq, wv.y, a1[v * 4 + 1]);
                    a1[v * 4 + 2] = fmaf(hq, wv.z, a1[v * 4 + 2]);
                    a1[v * 4 + 3] = fmaf(hq, wv.w, a1[v * 4 + 3]);
                    a2[v * 4 + 0] = fmaf(hq, rv.x, a2[v * 4 + 0]);
                    a2[v * 4 + 1] = fmaf(hq, rv.y, a2[v * 4 + 1]);
                    a2[v * 4 + 2] = fmaf(hq, rv.z, a2[v * 4 + 2]);
                    a2[v * 4 + 3] = fmaf(hq, rv.w, a2[v * 4 + 3]);
                }
            }
        }
    }
    if (n < NNODES) {
        float el = 0.f, er = 0.f;
        #pragma unroll
        for (int c = 0; c < 16; c++) {
            el = fmaf(a1[c], al2[c], el);
            er = fmaf(a1[c], ar2[c], er);
        }
        g_el[n] = el;
        g_er[n] = er;
        #pragma unroll
        for (int v = 0; v < 4; v++) {
            *(float4*)&g_ft2[n * 16 + v * 4]  = make_float4(a1[v*4], a1[v*4+1], a1[v*4+2], a1[v*4+3]);
            *(float4*)&g_res2[n * 16 + v * 4] = make_float4(a2[v*4], a2[v*4+1], a2[v*4+2], a2[v*4+3]);
        }
    }
}

// ---------------- aggregation F=16, H=1 + linear residual + bias -> logits ----------------
__global__ __launch_bounds__(32) void k_agg16(
    const int* __restrict__ src, const float* __restrict__ b2,
    float* __restrict__ logits)
{
    int n = blockIdx.x;
    int lane = threadIdx.x;
    if (lane >= 16) return;
    float acc = g_res2[n * 16 + lane] + b2[lane];
    int s0 = g_rowoff[n], s1 = g_rowoff[n + 1];
    for (int p = s0; p < s1; p++) {
        int eid = g_eid[p];
        float w = g_e[eid];
        int s = src[eid];
        acc = fmaf(w, g_ft2[s * 16 + lane], acc);
    }
    logits[n * 16 + lane] = acc;
}

// ---------------- launch (ONLY kernel launches — graph-capturable) ----------------
extern "C" void kernel_launch(void* const* d_in, const int* in_sizes, int n_in,
                              void* d_out, int out_size)
{
    const float* x0    = (const float*)d_in[0];
    const float* x1    = (const float*)d_in[1];
    const int*   src   = (const int*)d_in[2];
    const int*   dst   = (const int*)d_in[3];
    const float* fc0_W = (const float*)d_in[4];
    const float* fc0_b = (const float*)d_in[5];
    const float* fc1_W = (const float*)d_in[6];
    const float* fc1_b = (const float*)d_in[7];
    const float* W0  = (const float*)d_in[8];
    const float* al0 = (const float*)d_in[9];
    const float* ar0 = (const float*)d_in[10];
    const float* b0  = (const float*)d_in[11];
    const float* W1  = (const float*)d_in[12];
    const float* al1 = (const float*)d_in[13];
    const float* ar1 = (const float*)d_in[14];
    const float* b1  = (const float*)d_in[15];
    const float* W2  = (const float*)d_in[16];
    const float* al2 = (const float*)d_in[17];
    const float* ar2 = (const float*)d_in[18];
    const float* b2  = (const float*)d_in[19];
    const float* resW2 = (const float*)d_in[20];

    float* out    = (float*)d_out;
    float* logits = out;                         // [50000,16]
    float* enc    = out + (size_t)NNODES * 16;   // [50000,512]

    // ---- CSR build ----
    k_zero_counts<<<(NNODES + 255) / 256, 256>>>();
    k_count<<<(NEDGES + 255) / 256, 256>>>(dst);
    k_scan<<<1, 1024>>>();
    k_scatter<<<(NEDGES + 255) / 256, 256>>>(dst);
    k_sortseg<<<(NNODES + 255) / 256, 256>>>();

    // ---- per-type input projections (write into g_h0) ----
    dim3 gfc(1, (NHALF + 63) / 64);
    gemm_kernel<<<gfc, 256>>>(x0, -1, nullptr, 0, 0,                  fc0_W, NHALF, 64, 256, fc0_b, nullptr, nullptr);
    gemm_kernel<<<gfc, 256>>>(x1, -1, nullptr, 0, (size_t)NHALF * 64, fc1_W, NHALF, 64, 256, fc1_b, nullptr, nullptr);

    // ---- layer 0: 64 -> 8x64, elu (el/er fused into GEMM epilogue) ----
    dim3 g0(512 / 64, (NNODES + 63) / 64);
    gemm_kernel<<<g0, 256>>>(nullptr, 0, nullptr, 1, 0, W0, NNODES, 512, 64, nullptr, al0, ar0);
    k_attn<8><<<(NNODES * 8 + 255) / 256, 256>>>(src);
    k_agg512<<<NNODES, 128>>>(src, b0, 0, nullptr);   // -> g_h1

    // ---- layer 1: 512 -> 8x64, id residual, elu -> encoded ----
    gemm_kernel<<<g0, 256>>>(nullptr, 2, nullptr, 1, 0, W1, NNODES, 512, 512, nullptr, al1, ar1);
    k_attn<8><<<(NNODES * 8 + 255) / 256, 256>>>(src);
    k_agg512<<<NNODES, 128>>>(src, b1, 1, enc);       // resid=g_h1 -> enc

    // ---- output layer: 512 -> 1x16, linear residual ----
    k_l2proj2<<<(NNODES + 127) / 128, 128>>>(enc, W2, resW2, al2, ar2);
    k_attn<1><<<(NNODES + 255) / 256, 256>>>(src);
    k_agg16<<<NNODES, 32>>>(src, b2, logits);
}

// round 7
// speedup vs baseline: 1.7808x; 1.2313x over previous
#include <cuda_runtime.h>
#include <cuda_bf16.h>
#include <math.h>
#include <stdint.h>

#define NNODES 50000
#define NHALF  25000
#define NEDGES 400000

// ---------------- scratch (device globals; no allocation allowed) ----------------
__device__ float g_h0[NNODES * 64];
__device__ float g_ft[NNODES * 512];
__device__ float g_h1[NNODES * 512];
__device__ float g_el[NNODES * 8];
__device__ float g_er[NNODES * 8];
__device__ float g_e[NEDGES * 8];
__device__ float g_ft2[NNODES * 16];
__device__ float g_res2[NNODES * 16];
__device__ int   g_deg[NNODES];
__device__ int   g_cur[NNODES];
__device__ int   g_rowoff[NNODES + 1];
__device__ int   g_eid[NEDGES];
// bf16 split operands
__device__ __nv_bfloat16 g_ah[NNODES * 512];
__device__ __nv_bfloat16 g_al[NNODES * 512];
__device__ __nv_bfloat16 g_bth[327680];   // transposed split weights [N,K]: fc0@0, fc1@16384, W0@32768, W1@65536
__device__ __nv_bfloat16 g_btl[327680];

__device__ __forceinline__ const float* srcsel(const float* ext, int id) {
    if (ext) return ext;
    return (id == 0) ? g_h0 : g_h1;
}

__device__ __forceinline__ float* csel(float* ext, int id) {
    if (ext) return ext;
    switch (id) {
        case 0: return g_h0;
        case 1: return g_ft;
    }
    return g_h1;
}

// ---------------- CSR build ----------------
__global__ void k_zero_counts() {
    int i = blockIdx.x * blockDim.x + threadIdx.x;
    if (i < NNODES) { g_deg[i] = 0; g_cur[i] = 0; }
}

__global__ void k_count(const int* __restrict__ dst) {
    int i = blockIdx.x * blockDim.x + threadIdx.x;
    if (i < NEDGES) {
        int d = dst[i];
        if (d >= 0 && d < NNODES) atomicAdd(&g_deg[d], 1);
    }
}

__global__ void k_scan() {
    __shared__ int warp_sums[32];
    __shared__ int carry_sh;
    int t = threadIdx.x;
    if (t == 0) carry_sh = 0;
    __syncthreads();
    for (int base = 0; base < NNODES; base += 1024) {
        int i = base + t;
        int v = (i < NNODES) ? g_deg[i] : 0;
        int x = v;
        #pragma unroll
        for (int o = 1; o < 32; o <<= 1) {
            int y = __shfl_up_sync(0xffffffffu, x, o);
            if ((t & 31) >= o) x += y;
        }
        if ((t & 31) == 31) warp_sums[t >> 5] = x;
        __syncthreads();
        if (t < 32) {
            int w = warp_sums[t];
            #pragma unroll
            for (int o = 1; o < 32; o <<= 1) {
                int y = __shfl_up_sync(0xffffffffu, w, o);
                if (t >= o) w += y;
            }
            warp_sums[t] = w;
        }
        __syncthreads();
        int pref = (t >= 32) ? warp_sums[(t >> 5) - 1] : 0;
        int incl = x + pref;
        int carry = carry_sh;
        if (i < NNODES) g_rowoff[i] = carry + incl - v;
        __syncthreads();
        if (t == 1023) carry_sh = carry + incl;
        __syncthreads();
    }
    if (t == 0) g_rowoff[NNODES] = carry_sh;
}

__global__ void k_scatter(const int* __restrict__ dst) {
    int i = blockIdx.x * blockDim.x + threadIdx.x;
    if (i < NEDGES) {
        int d = dst[i];
        if (d >= 0 && d < NNODES) {
            int p = g_rowoff[d] + atomicAdd(&g_cur[d], 1);
            g_eid[p] = i;
        }
    }
}

__global__ void k_sortseg() {
    int n = blockIdx.x * blockDim.x + threadIdx.x;
    if (n >= NNODES) return;
    int s = g_rowoff[n], e = g_rowoff[n + 1];
    for (int i = s + 1; i < e; i++) {
        int key = g_eid[i];
        int j = i - 1;
        while (j >= s && g_eid[j] > key) { g_eid[j + 1] = g_eid[j]; j--; }
        g_eid[j + 1] = key;
    }
}

// ---------------- bf16 split prep ----------------
__global__ void k_split_rows(const float* __restrict__ Xext, int x_id, int count, int a_off)
{
    const float* X = srcsel(Xext, x_id);
    int i = (blockIdx.x * blockDim.x + threadIdx.x) * 4;
    if (i >= count) return;
    float4 v = *(const float4*)&X[i];
    float xs[4] = {v.x, v.y, v.z, v.w};
    __nv_bfloat16 hs[4], ls[4];
    #pragma unroll
    for (int j = 0; j < 4; j++) {
        hs[j] = __float2bfloat16(xs[j]);
        ls[j] = __float2bfloat16(xs[j] - __bfloat162float(hs[j]));
    }
    *(uint2*)&g_ah[a_off + i] = *(uint2*)hs;
    *(uint2*)&g_al[a_off + i] = *(uint2*)ls;
}

// weights: W[K,N] fp32 -> transposed split g_bth/g_btl[b_off + n*K + k]
__global__ void k_split_w(const float* __restrict__ W, int K, int N, int b_off)
{
    int idx = blockIdx.x * blockDim.x + threadIdx.x;
    if (idx >= K * N) return;
    int k = idx / N, n = idx % N;
    float x = W[idx];
    __nv_bfloat16 h = __float2bfloat16(x);
    __nv_bfloat16 l = __float2bfloat16(x - __bfloat162float(h));
    g_bth[b_off + n * K + k] = h;
    g_btl[b_off + n * K + k] = l;
}

// ---------------- bf16 3-term tensor-core GEMM ----------------
__device__ __forceinline__ void mma_bf16(float* c, const uint32_t* a, const uint32_t* b) {
    asm("mma.sync.aligned.m16n8k16.row.col.f32.bf16.bf16.f32 "
        "{%0,%1,%2,%3}, {%4,%5,%6,%7}, {%8,%9}, {%0,%1,%2,%3};"
        : "+f"(c[0]), "+f"(c[1]), "+f"(c[2]), "+f"(c[3])
        : "r"(a[0]), "r"(a[1]), "r"(a[2]), "r"(a[3]), "r"(b[0]), "r"(b[1]));
}

__global__ __launch_bounds__(256) void gemm_bf16(
    int a_off, float* __restrict__ Cext, int c_id, size_t c_off,
    int b_off, int M, int N, int K,
    const float* __restrict__ bias,
    const float* __restrict__ attn_al, const float* __restrict__ attn_ar)
{
    // fragment-order smem: A: ((F*2+ks)*32 + lane)*4 + reg ; B: ((NF*2+ks)*32 + lane)*2 + reg
    __shared__ uint32_t As[2][2048];
    __shared__ uint32_t Bs[2][1024];
    __shared__ float sl[128][2], sr[128][2];

    float* C = csel(Cext, c_id) + c_off;
    const __nv_bfloat16* Ah = g_ah + a_off;
    const __nv_bfloat16* Al = g_al + a_off;
    const __nv_bfloat16* Bth = g_bth + b_off;
    const __nv_bfloat16* Btl = g_btl + b_off;

    int tid  = threadIdx.x;
    int lane = tid & 31;
    int w    = tid >> 5;
    int wm   = w & 3;
    int wn   = w >> 2;
    int bm0  = blockIdx.y * 128;
    int bn0  = blockIdx.x * 64;

    float acc[2][4][4];
    #pragma unroll
    for (int mf = 0; mf < 2; mf++)
        #pragma unroll
        for (int nf = 0; nf < 4; nf++)
            #pragma unroll
            for (int i = 0; i < 4; i++) acc[mf][nf][i] = 0.f;

    int ar_r[2], ar_c[2];
    #pragma unroll
    for (int i = 0; i < 2; i++) {
        int idx = tid + i * 256;
        ar_r[i] = idx >> 2;            // 0..127
        ar_c[i] = (idx & 3) * 8;       // 0,8,16,24
    }
    int bn_r = tid >> 2;               // 0..63
    int bn_c = (tid & 3) * 8;

    for (int k0 = 0; k0 < K; k0 += 32) {
        uint4 a_hi[2], a_lo[2], b_hi, b_lo;
        #pragma unroll
        for (int i = 0; i < 2; i++) {
            int gr = bm0 + ar_r[i];
            if (gr < M) {
                size_t off = (size_t)gr * K + k0 + ar_c[i];
                a_hi[i] = *(const uint4*)&Ah[off];
                a_lo[i] = *(const uint4*)&Al[off];
            } else {
                a_hi[i] = make_uint4(0, 0, 0, 0);
                a_lo[i] = make_uint4(0, 0, 0, 0);
            }
        }
        {
            size_t off = (size_t)(bn0 + bn_r) * K + k0 + bn_c;
            b_hi = *(const uint4*)&Bth[off];
            b_lo = *(const uint4*)&Btl[off];
        }
        __syncthreads();
        #pragma unroll
        for (int i = 0; i < 2; i++) {
            int r = ar_r[i], c0 = ar_c[i];
            int ks  = c0 >> 4;
            int reg = ((r >> 3) & 1) | (((c0 & 15) >> 3) << 1);
            // pair j -> lane (r&7)*4 + j, per-lane stride 4 regs
            int base = (((r >> 4) * 2 + ks) * 32 + (r & 7) * 4) * 4 + reg;
            uint32_t vh[4] = {a_hi[i].x, a_hi[i].y, a_hi[i].z, a_hi[i].w};
            uint32_t vl[4] = {a_lo[i].x, a_lo[i].y, a_lo[i].z, a_lo[i].w};
            #pragma unroll
            for (int j = 0; j < 4; j++) {
                As[0][base + j * 4] = vh[j];
                As[1][base + j * 4] = vl[j];
            }
        }
        {
            int ks  = bn_c >> 4;
            int reg = (bn_c & 15) >> 3;
            // pair j -> lane (n&7)*4 + j, per-lane stride 2 regs
            int base = (((bn_r >> 3) * 2 + ks) * 32 + (bn_r & 7) * 4) * 2 + reg;
            uint32_t vh[4] = {b_hi.x, b_hi.y, b_hi.z, b_hi.w};
            uint32_t vl[4] = {b_lo.x, b_lo.y, b_lo.z, b_lo.w};
            #pragma unroll
            for (int j = 0; j < 4; j++) {
                Bs[0][base + j * 2] = vh[j];
                Bs[1][base + j * 2] = vl[j];
            }
        }
        __syncthreads();
        #pragma unroll
        for (int ks = 0; ks < 2; ks++) {
            uint32_t ah[2][4], al2_[2][4], bh[4][2], bl[4][2];
            #pragma unroll
            for (int mf = 0; mf < 2; mf++) {
                int off = (((wm * 2 + mf) * 2 + ks) * 32 + lane) * 4;
                uint4 h = *(const uint4*)&As[0][off];
                uint4 l = *(const uint4*)&As[1][off];
                ah[mf][0] = h.x; ah[mf][1] = h.y; ah[mf][2] = h.z; ah[mf][3] = h.w;
                al2_[mf][0] = l.x; al2_[mf][1] = l.y; al2_[mf][2] = l.z; al2_[mf][3] = l.w;
            }
            #pragma unroll
            for (int nf = 0; nf < 4; nf++) {
                int off = (((wn * 4 + nf) * 2 + ks) * 32 + lane) * 2;
                uint2 h = *(const uint2*)&Bs[0][off];
                uint2 l = *(const uint2*)&Bs[1][off];
                bh[nf][0] = h.x; bh[nf][1] = h.y;
                bl[nf][0] = l.x; bl[nf][1] = l.y;
            }
            #pragma unroll
            for (int mf = 0; mf < 2; mf++)
                #pragma unroll
                for (int nf = 0; nf < 4; nf++) {
                    mma_bf16(acc[mf][nf], ah[mf], bh[nf]);
                    mma_bf16(acc[mf][nf], ah[mf], bl[nf]);
                    mma_bf16(acc[mf][nf], al2_[mf], bh[nf]);
                }
        }
    }
    // epilogue: C + bias
    #pragma unroll
    for (int mf = 0; mf < 2; mf++) {
        int r0 = bm0 + wm * 32 + mf * 16 + (lane >> 2);
        #pragma unroll
        for (int nf = 0; nf < 4; nf++) {
            int c0 = bn0 + wn * 32 + nf * 8 + (lane & 3) * 2;
            float bz0 = bias ? bias[c0] : 0.f;
            float bz1 = bias ? bias[c0 + 1] : 0.f;
            if (r0 < M) {
                C[(size_t)r0 * N + c0]     = acc[mf][nf][0] + bz0;
                C[(size_t)r0 * N + c0 + 1] = acc[mf][nf][1] + bz1;
            }
            if (r0 + 8 < M) {
                C[(size_t)(r0 + 8) * N + c0]     = acc[mf][nf][2] + bz0;
                C[(size_t)(r0 + 8) * N + c0 + 1] = acc[mf][nf][3] + bz1;
            }
        }
    }
    // fused el/er (H=8 layers: block col tile == one head)
    if (attn_al) {
        int h = bn0 >> 6;
        float pl[2][2] = {{0.f, 0.f}, {0.f, 0.f}};
        float pr[2][2] = {{0.f, 0.f}, {0.f, 0.f}};
        #pragma unroll
        for (int mf = 0; mf < 2; mf++)
            #pragma unroll
            for (int nf = 0; nf < 4; nf++)
                #pragma unroll
                for (int s = 0; s < 2; s++) {
                    int d = wn * 32 + nf * 8 + (lane & 3) * 2 + s;
                    float wl = attn_al[h * 64 + d];
                    float wr = attn_ar[h * 64 + d];
                    pl[mf][0] = fmaf(acc[mf][nf][s],     wl, pl[mf][0]);
                    pl[mf][1] = fmaf(acc[mf][nf][2 + s], wl, pl[mf][1]);
                    pr[mf][0] = fmaf(acc[mf][nf][s],     wr, pr[mf][0]);
                    pr[mf][1] = fmaf(acc[mf][nf][2 + s], wr, pr[mf][1]);
                }
        #pragma unroll
        for (int mf = 0; mf < 2; mf++)
            #pragma unroll
            for (int hf = 0; hf < 2; hf++) {
                float vl = pl[mf][hf], vr = pr[mf][hf];
                vl += __shfl_xor_sync(0xffffffffu, vl, 1);
                vl += __shfl_xor_sync(0xffffffffu, vl, 2);
                vr += __shfl_xor_sync(0xffffffffu, vr, 1);
                vr += __shfl_xor_sync(0xffffffffu, vr, 2);
                if ((lane & 3) == 0) {
                    int rl = wm * 32 + mf * 16 + hf * 8 + (lane >> 2);
                    sl[rl][wn] = vl;
                    sr[rl][wn] = vr;
                }
            }
        __syncthreads();
        if (tid < 128) {
            int row = bm0 + tid;
            if (row < M) {
                g_el[row * 8 + h] = sl[tid][0] + sl[tid][1];
                g_er[row * 8 + h] = sr[tid][0] + sr[tid][1];
            }
        }
    }
}

// ---------------- fused edge-logit + segment softmax over dst ----------------
template <int H>
__global__ void k_attn(const int* __restrict__ src)
{
    int t = blockIdx.x * blockDim.x + threadIdx.x;
    if (t >= NNODES * H) return;
    int n = t / H, h = t % H;
    int s0 = g_rowoff[n], s1 = g_rowoff[n + 1];
    float ern = g_er[n * H + h];
    float m = -1e30f;
    for (int p = s0; p < s1; p++) {
        int eid = g_eid[p];
        float x = g_el[src[eid] * H + h] + ern;
        x = (x >= 0.f) ? x : 0.2f * x;
        g_e[(size_t)eid * H + h] = x;
        m = fmaxf(m, x);
    }
    float sum = 0.f;
    for (int p = s0; p < s1; p++) {
        size_t idx = (size_t)g_eid[p] * H + h;
        float ex = expf(g_e[idx] - m);
        g_e[idx] = ex;
        sum += ex;
    }
    float inv = 1.f / (sum + 1e-16f);
    for (int p = s0; p < s1; p++) g_e[(size_t)g_eid[p] * H + h] *= inv;
}

// ---------------- aggregation, F=512, H=8 ----------------
__global__ __launch_bounds__(128) void k_agg512(
    const int* __restrict__ src,
    const float* __restrict__ bias, int use_resid,
    float* __restrict__ out_ext)
{
    const float* ft = g_ft;
    float* out = out_ext ? out_ext : g_h1;
    int n = blockIdx.x;
    int t = threadIdx.x;
    int f = t * 4;
    int h = f >> 6;
    float4 acc = *(const float4*)&bias[f];
    if (use_resid) {
        float4 r = *(const float4*)&g_h1[(size_t)n * 512 + f];
        acc.x += r.x; acc.y += r.y; acc.z += r.z; acc.w += r.w;
    }
    int s0 = g_rowoff[n], s1 = g_rowoff[n + 1];
    for (int p = s0; p < s1; p++) {
        int eid = g_eid[p];
        float w = g_e[(size_t)eid * 8 + h];
        int s = src[eid];
        float4 v = *(const float4*)&ft[(size_t)s * 512 + f];
        acc.x = fmaf(w, v.x, acc.x);
        acc.y = fmaf(w, v.y, acc.y);
        acc.z = fmaf(w, v.z, acc.z);
        acc.w = fmaf(w, v.w, acc.w);
    }
    acc.x = (acc.x > 0.f) ? acc.x : expm1f(acc.x);
    acc.y = (acc.y > 0.f) ? acc.y : expm1f(acc.y);
    acc.z = (acc.z > 0.f) ? acc.z : expm1f(acc.z);
    acc.w = (acc.w > 0.f) ? acc.w : expm1f(acc.w);
    *(float4*)&out[(size_t)n * 512 + f] = acc;
}

// ---------------- layer-2 projections (tiled, smem weight reuse) ----------------
__global__ __launch_bounds__(128) void k_l2proj2(
    const float* __restrict__ h2, const float* __restrict__ W2,
    const float* __restrict__ resW2, const float* __restrict__ al2,
    const float* __restrict__ ar2)
{
    __shared__ float sW[64 * 16];
    __shared__ float sR[64 * 16];
    int n = blockIdx.x * 128 + threadIdx.x;
    int nc = (n < NNODES) ? n : (NNODES - 1);
    const float* hr = h2 + (size_t)nc * 512;

    float a1[16], a2[16];
    #pragma unroll
    for (int c = 0; c < 16; c++) { a1[c] = 0.f; a2[c] = 0.f; }

    for (int k0 = 0; k0 < 512; k0 += 64) {
        __syncthreads();
        #pragma unroll
        for (int i = 0; i < 8; i++) {
            int idx = threadIdx.x + i * 128;
            sW[idx] = W2[k0 * 16 + idx];
            sR[idx] = resW2[k0 * 16 + idx];
        }
        __syncthreads();
        #pragma unroll
        for (int kk = 0; kk < 64; kk += 4) {
            float4 hv4 = *(const float4*)&hr[k0 + kk];
            float hv[4] = {hv4.x, hv4.y, hv4.z, hv4.w};
            #pragma unroll
            for (int q = 0; q < 4; q++) {
                float hq = hv[q];
                const float4* w4 = (const float4*)&sW[(kk + q) * 16];
                const float4* r4 = (const float4*)&sR[(kk + q) * 16];
                #pragma unroll
                for (int v = 0; v < 4; v++) {
                    float4 wv = w4[v], rv = r4[v];
                    a1[v * 4 + 0] = fmaf(hq, wv.x, a1[v * 4 + 0]);
                    a1[v * 4 + 1] = fmaf(hq, wv.y, a1[v * 4 + 1]);
                    a1[v * 4 + 2] = fmaf(hq, wv.z, a1[v * 4 + 2]);
                    a1[v * 4 + 3] = fmaf(hq, wv.w, a1[v * 4 + 3]);
                    a2[v * 4 + 0] = fmaf(hq, rv.x, a2[v * 4 + 0]);
                    a2[v * 4 + 1] = fmaf(hq, rv.y, a2[v * 4 + 1]);
                    a2[v * 4 + 2] = fmaf(hq, rv.z, a2[v * 4 + 2]);
                    a2[v * 4 + 3] = fmaf(hq, rv.w, a2[v * 4 + 3]);
                }
            }
        }
    }
    if (n < NNODES) {
        float el = 0.f, er = 0.f;
        #pragma unroll
        for (int c = 0; c < 16; c++) {
            el = fmaf(a1[c], al2[c], el);
            er = fmaf(a1[c], ar2[c], er);
        }
        g_el[n] = el;
        g_er[n] = er;
        #pragma unroll
        for (int v = 0; v < 4; v++) {
            *(float4*)&g_ft2[n * 16 + v * 4]  = make_float4(a1[v*4], a1[v*4+1], a1[v*4+2], a1[v*4+3]);
            *(float4*)&g_res2[n * 16 + v * 4] = make_float4(a2[v*4], a2[v*4+1], a2[v*4+2], a2[v*4+3]);
        }
    }
}

// ---------------- aggregation F=16, H=1 ----------------
__global__ __launch_bounds__(32) void k_agg16(
    const int* __restrict__ src, const float* __restrict__ b2,
    float* __restrict__ logits)
{
    int n = blockIdx.x;
    int lane = threadIdx.x;
    if (lane >= 16) return;
    float acc = g_res2[n * 16 + lane] + b2[lane];
    int s0 = g_rowoff[n], s1 = g_rowoff[n + 1];
    for (int p = s0; p < s1; p++) {
        int eid = g_eid[p];
        float w = g_e[eid];
        int s = src[eid];
        acc = fmaf(w, g_ft2[s * 16 + lane], acc);
    }
    logits[n * 16 + lane] = acc;
}

// ---------------- launch (ONLY kernel launches — graph-capturable) ----------------
extern "C" void kernel_launch(void* const* d_in, const int* in_sizes, int n_in,
                              void* d_out, int out_size)
{
    const float* x0    = (const float*)d_in[0];
    const float* x1    = (const float*)d_in[1];
    const int*   src   = (const int*)d_in[2];
    const int*   dst   = (const int*)d_in[3];
    const float* fc0_W = (const float*)d_in[4];
    const float* fc0_b = (const float*)d_in[5];
    const float* fc1_W = (const float*)d_in[6];
    const float* fc1_b = (const float*)d_in[7];
    const float* W0  = (const float*)d_in[8];
    const float* al0 = (const float*)d_in[9];
    const float* ar0 = (const float*)d_in[10];
    const float* b0  = (const float*)d_in[11];
    const float* W1  = (const float*)d_in[12];
    const float* al1 = (const float*)d_in[13];
    const float* ar1 = (const float*)d_in[14];
    const float* b1  = (const float*)d_in[15];
    const float* W2  = (const float*)d_in[16];
    const float* al2 = (const float*)d_in[17];
    const float* ar2 = (const float*)d_in[18];
    const float* b2  = (const float*)d_in[19];
    const float* resW2 = (const float*)d_in[20];

    float* out    = (float*)d_out;
    float* logits = out;                         // [50000,16]
    float* enc    = out + (size_t)NNODES * 16;   // [50000,512]

    const int FC0_BT = 0, FC1_BT = 16384, W0_BT = 32768, W1_BT = 65536;

    // ---- CSR build ----
    k_zero_counts<<<(NNODES + 255) / 256, 256>>>();
    k_count<<<(NEDGES + 255) / 256, 256>>>(dst);
    k_scan<<<1, 1024>>>();
    k_scatter<<<(NEDGES + 255) / 256, 256>>>(dst);
    k_sortseg<<<(NNODES + 255) / 256, 256>>>();

    // ---- split weights (once per launch) ----
    k_split_w<<<(256 * 64 + 255) / 256, 256>>>(fc0_W, 256, 64, FC0_BT);
    k_split_w<<<(256 * 64 + 255) / 256, 256>>>(fc1_W, 256, 64, FC1_BT);
    k_split_w<<<(64 * 512 + 255) / 256, 256>>>(W0, 64, 512, W0_BT);
    k_split_w<<<(512 * 512 + 255) / 256, 256>>>(W1, 512, 512, W1_BT);

    // ---- fc: split inputs, then per-type projections -> g_h0 ----
    k_split_rows<<<(NHALF * 256 / 4 + 255) / 256, 256>>>(x0, -1, NHALF * 256, 0);
    k_split_rows<<<(NHALF * 256 / 4 + 255) / 256, 256>>>(x1, -1, NHALF * 256, NHALF * 256);
    {
        dim3 g(1, (NHALF + 127) / 128);
        gemm_bf16<<<g, 256>>>(0,           nullptr, 0, 0,                  FC0_BT, NHALF, 64, 256, fc0_b, nullptr, nullptr);
        gemm_bf16<<<g, 256>>>(NHALF * 256, nullptr, 0, (size_t)NHALF * 64, FC1_BT, NHALF, 64, 256, fc1_b, nullptr, nullptr);
    }

    // ---- layer 0: 64 -> 8x64, elu (el/er fused) ----
    k_split_rows<<<(NNODES * 64 / 4 + 255) / 256, 256>>>(nullptr, 0, NNODES * 64, 0);
    {
        dim3 g(8, (NNODES + 127) / 128);
        gemm_bf16<<<g, 256>>>(0, nullptr, 1, 0, W0_BT, NNODES, 512, 64, nullptr, al0, ar0);
    }
    k_attn<8><<<(NNODES * 8 + 255) / 256, 256>>>(src);
    k_agg512<<<NNODES, 128>>>(src, b0, 0, nullptr);   // -> g_h1

    // ---- layer 1: 512 -> 8x64, id residual, elu -> encoded ----
    k_split_rows<<<(NNODES * 512 / 4 + 255) / 256, 256>>>(nullptr, 2, NNODES * 512, 0);
    {
        dim3 g(8, (NNODES + 127) / 128);
        gemm_bf16<<<g, 256>>>(0, nullptr, 1, 0, W1_BT, NNODES, 512, 512, nullptr, al1, ar1);
    }
    k_attn<8><<<(NNODES * 8 + 255) / 256, 256>>>(src);
    k_agg512<<<NNODES, 128>>>(src, b1, 1, enc);       // resid=g_h1 -> enc

    // ---- output layer: 512 -> 1x16, linear residual ----
    k_l2proj2<<<(NNODES + 127) / 128, 128>>>(enc, W2, resW2, al2, ar2);
    k_attn<1><<<(NNODES + 255) / 256, 256>>>(src);
    k_agg16<<<NNODES, 32>>>(src, b2, logits);
}

// round 9
// speedup vs baseline: 1.9418x; 1.0904x over previous
#include <cuda_runtime.h>
#include <cuda_fp16.h>
#include <math.h>
#include <stdint.h>

#define NNODES 50000
#define NHALF  25000
#define NEDGES 400000

// ---------------- scratch (device globals; no allocation allowed) ----------------
__device__ float g_h0[NNODES * 64];
__device__ float g_ft[NNODES * 512];
__device__ float g_h1[NNODES * 512];
__device__ float g_el[NNODES * 8];
__device__ float g_er[NNODES * 8];
__device__ float g_e[NEDGES * 8];
__device__ float g_ft2[NNODES * 16];
__device__ float g_res2[NNODES * 16];
__device__ int   g_deg[NNODES];
__device__ int   g_cur[NNODES];
__device__ int   g_rowoff[NNODES + 1];
__device__ int   g_eid[NEDGES];
// fp16 split operands: A = hi+lo, B (weights, [N,K]) = hi only
__device__ __half g_ah[NNODES * 512];
__device__ __half g_al[NNODES * 512];
__device__ __half g_bth[327680];   // fc0@0, fc1@16384, W0@32768, W1@65536

__device__ __forceinline__ const float* srcsel(const float* ext, int id) {
    if (ext) return ext;
    return (id == 0) ? g_h0 : g_h1;
}

__device__ __forceinline__ float* csel(float* ext, int id) {
    if (ext) return ext;
    switch (id) {
        case 0: return g_h0;
        case 1: return g_ft;
    }
    return g_h1;
}

// ---------------- CSR build ----------------
__global__ void k_zero_counts() {
    int i = blockIdx.x * blockDim.x + threadIdx.x;
    if (i < NNODES) { g_deg[i] = 0; g_cur[i] = 0; }
}

__global__ void k_count(const int* __restrict__ dst) {
    int i = blockIdx.x * blockDim.x + threadIdx.x;
    if (i < NEDGES) {
        int d = dst[i];
        if (d >= 0 && d < NNODES) atomicAdd(&g_deg[d], 1);
    }
}

__global__ void k_scan() {
    __shared__ int warp_sums[32];
    __shared__ int carry_sh;
    int t = threadIdx.x;
    if (t == 0) carry_sh = 0;
    __syncthreads();
    for (int base = 0; base < NNODES; base += 1024) {
        int i = base + t;
        int v = (i < NNODES) ? g_deg[i] : 0;
        int x = v;
        #pragma unroll
        for (int o = 1; o < 32; o <<= 1) {
            int y = __shfl_up_sync(0xffffffffu, x, o);
            if ((t & 31) >= o) x += y;
        }
        if ((t & 31) == 31) warp_sums[t >> 5] = x;
        __syncthreads();
        if (t < 32) {
            int w = warp_sums[t];
            #pragma unroll
            for (int o = 1; o < 32; o <<= 1) {
                int y = __shfl_up_sync(0xffffffffu, w, o);
                if (t >= o) w += y;
            }
            warp_sums[t] = w;
        }
        __syncthreads();
        int pref = (t >= 32) ? warp_sums[(t >> 5) - 1] : 0;
        int incl = x + pref;
        int carry = carry_sh;
        if (i < NNODES) g_rowoff[i] = carry + incl - v;
        __syncthreads();
        if (t == 1023) carry_sh = carry + incl;
        __syncthreads();
    }
    if (t == 0) g_rowoff[NNODES] = carry_sh;
}

__global__ void k_scatter(const int* __restrict__ dst) {
    int i = blockIdx.x * blockDim.x + threadIdx.x;
    if (i < NEDGES) {
        int d = dst[i];
        if (d >= 0 && d < NNODES) {
            int p = g_rowoff[d] + atomicAdd(&g_cur[d], 1);
            g_eid[p] = i;
        }
    }
}

__global__ void k_sortseg() {
    int n = blockIdx.x * blockDim.x + threadIdx.x;
    if (n >= NNODES) return;
    int s = g_rowoff[n], e = g_rowoff[n + 1];
    for (int i = s + 1; i < e; i++) {
        int key = g_eid[i];
        int j = i - 1;
        while (j >= s && g_eid[j] > key) { g_eid[j + 1] = g_eid[j]; j--; }
        g_eid[j + 1] = key;
    }
}

// ---------------- fp16 split prep ----------------
__global__ void k_split_rows(const float* __restrict__ Xext, int x_id, int count, int a_off)
{
    const float* X = srcsel(Xext, x_id);
    int i = (blockIdx.x * blockDim.x + threadIdx.x) * 4;
    if (i >= count) return;
    float4 v = *(const float4*)&X[i];
    float xs[4] = {v.x, v.y, v.z, v.w};
    __half hs[4], ls[4];
    #pragma unroll
    for (int j = 0; j < 4; j++) {
        hs[j] = __float2half_rn(xs[j]);
        ls[j] = __float2half_rn(xs[j] - __half2float(hs[j]));
    }
    *(uint2*)&g_ah[a_off + i] = *(uint2*)hs;
    *(uint2*)&g_al[a_off + i] = *(uint2*)ls;
}

// weights: W[K,N] fp32 -> transposed fp16 g_bth[b_off + n*K + k]
__global__ void k_split_w(const float* __restrict__ W, int K, int N, int b_off)
{
    int idx = blockIdx.x * blockDim.x + threadIdx.x;
    if (idx >= K * N) return;
    int k = idx / N, n = idx % N;
    g_bth[b_off + n * K + k] = __float2half_rn(W[idx]);
}

// ---------------- fp16 2-term tensor-core GEMM ----------------
// C = (Ah + Al) @ B : 2 mma per fragment pair. A [M,K] split fp16; B [N,K] fp16.
// Block tile 128x64, BK=32, 256 thr = 8 warps (4 wm x 2 wn), warp tile 32x32.
__device__ __forceinline__ void mma_f16(float* c, const uint32_t* a, const uint32_t* b) {
    asm("mma.sync.aligned.m16n8k16.row.col.f32.f16.f16.f32 "
        "{%0,%1,%2,%3}, {%4,%5,%6,%7}, {%8,%9}, {%0,%1,%2,%3};"
        : "+f"(c[0]), "+f"(c[1]), "+f"(c[2]), "+f"(c[3])
        : "r"(a[0]), "r"(a[1]), "r"(a[2]), "r"(a[3]), "r"(b[0]), "r"(b[1]));
}

__global__ __launch_bounds__(256) void gemm_f16(
    int a_off, float* __restrict__ Cext, int c_id, size_t c_off,
    int b_off, int M, int N, int K,
    const float* __restrict__ bias,
    const float* __restrict__ attn_al, const float* __restrict__ attn_ar)
{
    // fragment-order smem: A: ((F*2+ks)*32 + lane)*4 + reg ; B: ((NF*2+ks)*32 + lane)*2 + reg
    __shared__ uint32_t As[2][2048];
    __shared__ uint32_t Bs[1024];
    __shared__ float sl[128][2], sr[128][2];

    float* C = csel(Cext, c_id) + c_off;
    const __half* Ah = g_ah + a_off;
    const __half* Al = g_al + a_off;
    const __half* Bth = g_bth + b_off;

    int tid  = threadIdx.x;
    int lane = tid & 31;
    int w    = tid >> 5;
    int wm   = w & 3;
    int wn   = w >> 2;
    int bm0  = blockIdx.y * 128;
    int bn0  = blockIdx.x * 64;

    float acc[2][4][4];
    #pragma unroll
    for (int mf = 0; mf < 2; mf++)
        #pragma unroll
        for (int nf = 0; nf < 4; nf++)
            #pragma unroll
            for (int i = 0; i < 4; i++) acc[mf][nf][i] = 0.f;

    int ar_r[2], ar_c[2];
    #pragma unroll
    for (int i = 0; i < 2; i++) {
        int idx = tid + i * 256;
        ar_r[i] = idx >> 2;            // 0..127
        ar_c[i] = (idx & 3) * 8;       // 0,8,16,24
    }
    int bn_r = tid >> 2;               // 0..63
    int bn_c = (tid & 3) * 8;

    for (int k0 = 0; k0 < K; k0 += 32) {
        uint4 a_hi[2], a_lo[2], b_hi;
        #pragma unroll
        for (int i = 0; i < 2; i++) {
            int gr = bm0 + ar_r[i];
            if (gr < M) {
                size_t off = (size_t)gr * K + k0 + ar_c[i];
                a_hi[i] = *(const uint4*)&Ah[off];
                a_lo[i] = *(const uint4*)&Al[off];
            } else {
                a_hi[i] = make_uint4(0, 0, 0, 0);
                a_lo[i] = make_uint4(0, 0, 0, 0);
            }
        }
        {
            size_t off = (size_t)(bn0 + bn_r) * K + k0 + bn_c;
            b_hi = *(const uint4*)&Bth[off];
        }
        __syncthreads();
        #pragma unroll
        for (int i = 0; i < 2; i++) {
            int r = ar_r[i], c0 = ar_c[i];
            int ks  = c0 >> 4;
            int reg = ((r >> 3) & 1) | (((c0 & 15) >> 3) << 1);
            int base = (((r >> 4) * 2 + ks) * 32 + (r & 7) * 4) * 4 + reg;
            uint32_t vh[4] = {a_hi[i].x, a_hi[i].y, a_hi[i].z, a_hi[i].w};
            uint32_t vl[4] = {a_lo[i].x, a_lo[i].y, a_lo[i].z, a_lo[i].w};
            #pragma unroll
            for (int j = 0; j < 4; j++) {
                As[0][base + j * 4] = vh[j];
                As[1][base + j * 4] = vl[j];
            }
        }
        {
            int ks  = bn_c >> 4;
            int reg = (bn_c & 15) >> 3;
            int base = (((bn_r >> 3) * 2 + ks) * 32 + (bn_r & 7) * 4) * 2 + reg;
            uint32_t vh[4] = {b_hi.x, b_hi.y, b_hi.z, b_hi.w};
            #pragma unroll
            for (int j = 0; j < 4; j++)
                Bs[base + j * 2] = vh[j];
        }
        __syncthreads();
        #pragma unroll
        for (int ks = 0; ks < 2; ks++) {
            uint32_t ah[2][4], al2_[2][4], bh[4][2];
            #pragma unroll
            for (int mf = 0; mf < 2; mf++) {
                int off = (((wm * 2 + mf) * 2 + ks) * 32 + lane) * 4;
                uint4 h = *(const uint4*)&As[0][off];
                uint4 l = *(const uint4*)&As[1][off];
                ah[mf][0] = h.x; ah[mf][1] = h.y; ah[mf][2] = h.z; ah[mf][3] = h.w;
                al2_[mf][0] = l.x; al2_[mf][1] = l.y; al2_[mf][2] = l.z; al2_[mf][3] = l.w;
            }
            #pragma unroll
            for (int nf = 0; nf < 4; nf++) {
                int off = (((wn * 4 + nf) * 2 + ks) * 32 + lane) * 2;
                uint2 h = *(const uint2*)&Bs[off];
                bh[nf][0] = h.x; bh[nf][1] = h.y;
            }
            #pragma unroll
            for (int mf = 0; mf < 2; mf++)
                #pragma unroll
                for (int nf = 0; nf < 4; nf++) {
                    mma_f16(acc[mf][nf], ah[mf], bh[nf]);
                    mma_f16(acc[mf][nf], al2_[mf], bh[nf]);
                }
        }
    }
    // epilogue: C + bias
    #pragma unroll
    for (int mf = 0; mf < 2; mf++) {
        int r0 = bm0 + wm * 32 + mf * 16 + (lane >> 2);
        #pragma unroll
        for (int nf = 0; nf < 4; nf++) {
            int c0 = bn0 + wn * 32 + nf * 8 + (lane & 3) * 2;
            float bz0 = bias ? bias[c0] : 0.f;
            float bz1 = bias ? bias[c0 + 1] : 0.f;
            if (r0 < M) {
                C[(size_t)r0 * N + c0]     = acc[mf][nf][0] + bz0;
                C[(size_t)r0 * N + c0 + 1] = acc[mf][nf][1] + bz1;
            }
            if (r0 + 8 < M) {
                C[(size_t)(r0 + 8) * N + c0]     = acc[mf][nf][2] + bz0;
                C[(size_t)(r0 + 8) * N + c0 + 1] = acc[mf][nf][3] + bz1;
            }
        }
    }
    // fused el/er (H=8 layers: block col tile == one head)
    if (attn_al) {
        int h = bn0 >> 6;
        float pl[2][2] = {{0.f, 0.f}, {0.f, 0.f}};
        float pr[2][2] = {{0.f, 0.f}, {0.f, 0.f}};
        #pragma unroll
        for (int mf = 0; mf < 2; mf++)
            #pragma unroll
            for (int nf = 0; nf < 4; nf++)
                #pragma unroll
                for (int s = 0; s < 2; s++) {
                    int d = wn * 32 + nf * 8 + (lane & 3) * 2 + s;
                    float wl = attn_al[h * 64 + d];
                    float wr = attn_ar[h * 64 + d];
                    pl[mf][0] = fmaf(acc[mf][nf][s],     wl, pl[mf][0]);
                    pl[mf][1] = fmaf(acc[mf][nf][2 + s], wl, pl[mf][1]);
                    pr[mf][0] = fmaf(acc[mf][nf][s],     wr, pr[mf][0]);
                    pr[mf][1] = fmaf(acc[mf][nf][2 + s], wr, pr[mf][1]);
                }
        #pragma unroll
        for (int mf = 0; mf < 2; mf++)
            #pragma unroll
            for (int hf = 0; hf < 2; hf++) {
                float vl = pl[mf][hf], vr = pr[mf][hf];
                vl += __shfl_xor_sync(0xffffffffu, vl, 1);
                vl += __shfl_xor_sync(0xffffffffu, vl, 2);
                vr += __shfl_xor_sync(0xffffffffu, vr, 1);
                vr += __shfl_xor_sync(0xffffffffu, vr, 2);
                if ((lane & 3) == 0) {
                    int rl = wm * 32 + mf * 16 + hf * 8 + (lane >> 2);
                    sl[rl][wn] = vl;
                    sr[rl][wn] = vr;
                }
            }
        __syncthreads();
        if (tid < 128) {
            int row = bm0 + tid;
            if (row < M) {
                g_el[row * 8 + h] = sl[tid][0] + sl[tid][1];
                g_er[row * 8 + h] = sr[tid][0] + sr[tid][1];
            }
        }
    }
}

// ---------------- fused edge-logit + segment softmax over dst ----------------
template <int H>
__global__ void k_attn(const int* __restrict__ src)
{
    int t = blockIdx.x * blockDim.x + threadIdx.x;
    if (t >= NNODES * H) return;
    int n = t / H, h = t % H;
    int s0 = g_rowoff[n], s1 = g_rowoff[n + 1];
    float ern = g_er[n * H + h];
    float m = -1e30f;
    for (int p = s0; p < s1; p++) {
        int eid = g_eid[p];
        float x = g_el[src[eid] * H + h] + ern;
        x = (x >= 0.f) ? x : 0.2f * x;
        g_e[(size_t)eid * H + h] = x;
        m = fmaxf(m, x);
    }
    float sum = 0.f;
    for (int p = s0; p < s1; p++) {
        size_t idx = (size_t)g_eid[p] * H + h;
        float ex = expf(g_e[idx] - m);
        g_e[idx] = ex;
        sum += ex;
    }
    float inv = 1.f / (sum + 1e-16f);
    for (int p = s0; p < s1; p++) g_e[(size_t)g_eid[p] * H + h] *= inv;
}

// ---------------- aggregation, F=512, H=8 (optionally emits fp16 split of out) ----------------
__global__ __launch_bounds__(128) void k_agg512(
    const int* __restrict__ src,
    const float* __restrict__ bias, int use_resid, int write_split,
    float* __restrict__ out_ext)
{
    const float* ft = g_ft;
    float* out = out_ext ? out_ext : g_h1;
    int n = blockIdx.x;
    int t = threadIdx.x;
    int f = t * 4;
    int h = f >> 6;
    float4 acc = *(const float4*)&bias[f];
    if (use_resid) {
        float4 r = *(const float4*)&g_h1[(size_t)n * 512 + f];
        acc.x += r.x; acc.y += r.y; acc.z += r.z; acc.w += r.w;
    }
    int s0 = g_rowoff[n], s1 = g_rowoff[n + 1];
    for (int p = s0; p < s1; p++) {
        int eid = g_eid[p];
        float w = g_e[(size_t)eid * 8 + h];
        int s = src[eid];
        float4 v = *(const float4*)&ft[(size_t)s * 512 + f];
        acc.x = fmaf(w, v.x, acc.x);
        acc.y = fmaf(w, v.y, acc.y);
        acc.z = fmaf(w, v.z, acc.z);
        acc.w = fmaf(w, v.w, acc.w);
    }
    acc.x = (acc.x > 0.f) ? acc.x : expm1f(acc.x);
    acc.y = (acc.y > 0.f) ? acc.y : expm1f(acc.y);
    acc.z = (acc.z > 0.f) ? acc.z : expm1f(acc.z);
    acc.w = (acc.w > 0.f) ? acc.w : expm1f(acc.w);
    *(float4*)&out[(size_t)n * 512 + f] = acc;
    if (write_split) {
        float vv[4] = {acc.x, acc.y, acc.z, acc.w};
        __half hs[4], ls[4];
        #pragma unroll
        for (int j = 0; j < 4; j++) {
            hs[j] = __float2half_rn(vv[j]);
            ls[j] = __float2half_rn(vv[j] - __half2float(hs[j]));
        }
        *(uint2*)&g_ah[(size_t)n * 512 + f] = *(uint2*)hs;
        *(uint2*)&g_al[(size_t)n * 512 + f] = *(uint2*)ls;
    }
}

// ---------------- layer-2 projections (tiled, smem weight reuse) ----------------
__global__ __launch_bounds__(128) void k_l2proj2(
    const float* __restrict__ h2, const float* __restrict__ W2,
    const float* __restrict__ resW2, const float* __restrict__ al2,
    const float* __restrict__ ar2)
{
    __shared__ float sW[64 * 16];
    __shared__ float sR[64 * 16];
    int n = blockIdx.x * 128 + threadIdx.x;
    int nc = (n < NNODES) ? n : (NNODES - 1);
    const float* hr = h2 + (size_t)nc * 512;

    float a1[16], a2[16];
    #pragma unroll
    for (int c = 0; c < 16; c++) { a1[c] = 0.f; a2[c] = 0.f; }

    for (int k0 = 0; k0 < 512; k0 += 64) {
        __syncthreads();
        #pragma unroll
        for (int i = 0; i < 8; i++) {
            int idx = threadIdx.x + i * 128;
            sW[idx] = W2[k0 * 16 + idx];
            sR[idx] = resW2[k0 * 16 + idx];
        }
        __syncthreads();
        #pragma unroll
        for (int kk = 0; kk < 64; kk += 4) {
            float4 hv4 = *(const float4*)&hr[k0 + kk];
            float hv[4] = {hv4.x, hv4.y, hv4.z, hv4.w};
            #pragma unroll
            for (int q = 0; q < 4; q++) {
                float hq = hv[q];
                const float4* w4 = (const float4*)&sW[(kk + q) * 16];
                const float4* r4 = (const float4*)&sR[(kk + q) * 16];
                #pragma unroll
                for (int v = 0; v < 4; v++) {
                    float4 wv = w4[v], rv = r4[v];
                    a1[v * 4 + 0] = fmaf(hq, wv.x, a1[v * 4 + 0]);
                    a1[v * 4 + 1] = fmaf(hq, wv.y, a1[v * 4 + 1]);
                    a1[v * 4 + 2] = fmaf(hq, wv.z, a1[v * 4 + 2]);
                    a1[v * 4 + 3] = fmaf(hq, wv.w, a1[v * 4 + 3]);
                    a2[v * 4 + 0] = fmaf(hq, rv.x, a2[v * 4 + 0]);
                    a2[v * 4 + 1] = fmaf(hq, rv.y, a2[v * 4 + 1]);
                    a2[v * 4 + 2] = fmaf(hq, rv.z, a2[v * 4 + 2]);
                    a2[v * 4 + 3] = fmaf(hq, rv.w, a2[v * 4 + 3]);
                }
            }
        }
    }
    if (n < NNODES) {
        float el = 0.f, er = 0.f;
        #pragma unroll
        for (int c = 0; c < 16; c++) {
            el = fmaf(a1[c], al2[c], el);
            er = fmaf(a1[c], ar2[c], er);
        }
        g_el[n] = el;
        g_er[n] = er;
        #pragma unroll
        for (int v = 0; v < 4; v++) {
            *(float4*)&g_ft2[n * 16 + v * 4]  = make_float4(a1[v*4], a1[v*4+1], a1[v*4+2], a1[v*4+3]);
            *(float4*)&g_res2[n * 16 + v * 4] = make_float4(a2[v*4], a2[v*4+1], a2[v*4+2], a2[v*4+3]);
        }
    }
}

// ---------------- aggregation F=16, H=1 ----------------
__global__ __launch_bounds__(32) void k_agg16(
    const int* __restrict__ src, const float* __restrict__ b2,
    float* __restrict__ logits)
{
    int n = blockIdx.x;
    int lane = threadIdx.x;
    if (lane >= 16) return;
    float acc = g_res2[n * 16 + lane] + b2[lane];
    int s0 = g_rowoff[n], s1 = g_rowoff[n + 1];
    for (int p = s0; p < s1; p++) {
        int eid = g_eid[p];
        float w = g_e[eid];
        int s = src[eid];
        acc = fmaf(w, g_ft2[s * 16 + lane], acc);
    }
    logits[n * 16 + lane] = acc;
}

// ---------------- launch (ONLY kernel launches — graph-capturable) ----------------
extern "C" void kernel_launch(void* const* d_in, const int* in_sizes, int n_in,
                              void* d_out, int out_size)
{
    const float* x0    = (const float*)d_in[0];
    const float* x1    = (const float*)d_in[1];
    const int*   src   = (const int*)d_in[2];
    const int*   dst   = (const int*)d_in[3];
    const float* fc0_W = (const float*)d_in[4];
    const float* fc0_b = (const float*)d_in[5];
    const float* fc1_W = (const float*)d_in[6];
    const float* fc1_b = (const float*)d_in[7];
    const float* W0  = (const float*)d_in[8];
    const float* al0 = (const float*)d_in[9];
    const float* ar0 = (const float*)d_in[10];
    const float* b0  = (const float*)d_in[11];
    const float* W1  = (const float*)d_in[12];
    const float* al1 = (const float*)d_in[13];
    const float* ar1 = (const float*)d_in[14];
    const float* b1  = (const float*)d_in[15];
    const float* W2  = (const float*)d_in[16];
    const float* al2 = (const float*)d_in[17];
    const float* ar2 = (const float*)d_in[18];
    const float* b2  = (const float*)d_in[19];
    const float* resW2 = (const float*)d_in[20];

    float* out    = (float*)d_out;
    float* logits = out;                         // [50000,16]
    float* enc    = out + (size_t)NNODES * 16;   // [50000,512]

    const int FC0_BT = 0, FC1_BT = 16384, W0_BT = 32768, W1_BT = 65536;

    // ---- CSR build ----
    k_zero_counts<<<(NNODES + 255) / 256, 256>>>();
    k_count<<<(NEDGES + 255) / 256, 256>>>(dst);
    k_scan<<<1, 1024>>>();
    k_scatter<<<(NEDGES + 255) / 256, 256>>>(dst);
    k_sortseg<<<(NNODES + 255) / 256, 256>>>();

    // ---- fp16 weights + fc input splits ----
    k_split_w<<<(256 * 64 + 255) / 256, 256>>>(fc0_W, 256, 64, FC0_BT);
    k_split_w<<<(256 * 64 + 255) / 256, 256>>>(fc1_W, 256, 64, FC1_BT);
    k_split_w<<<(64 * 512 + 255) / 256, 256>>>(W0, 64, 512, W0_BT);
    k_split_w<<<(512 * 512 + 255) / 256, 256>>>(W1, 512, 512, W1_BT);
    k_split_rows<<<(NHALF * 256 / 4 + 255) / 256, 256>>>(x0, -1, NHALF * 256, 0);
    k_split_rows<<<(NHALF * 256 / 4 + 255) / 256, 256>>>(x1, -1, NHALF * 256, NHALF * 256);

    // ---- fc: per-type projections -> g_h0 ----
    {
        dim3 g(1, (NHALF + 127) / 128);
        gemm_f16<<<g, 256>>>(0,           nullptr, 0, 0,                  FC0_BT, NHALF, 64, 256, fc0_b, nullptr, nullptr);
        gemm_f16<<<g, 256>>>(NHALF * 256, nullptr, 0, (size_t)NHALF * 64, FC1_BT, NHALF, 64, 256, fc1_b, nullptr, nullptr);
    }

    // ---- layer 0: 64 -> 8x64, elu (el/er fused) ----
    k_split_rows<<<(NNODES * 64 / 4 + 255) / 256, 256>>>(nullptr, 0, NNODES * 64, 0);
    {
        dim3 g(8, (NNODES + 127) / 128);
        gemm_f16<<<g, 256>>>(0, nullptr, 1, 0, W0_BT, NNODES, 512, 64, nullptr, al0, ar0);
    }
    k_attn<8><<<(NNODES * 8 + 255) / 256, 256>>>(src);
    k_agg512<<<NNODES, 128>>>(src, b0, 0, 1, nullptr);   // -> g_h1 + fp16 split for L1

    // ---- layer 1: 512 -> 8x64, id residual, elu -> encoded ----
    {
        dim3 g(8, (NNODES + 127) / 128);
        gemm_f16<<<g, 256>>>(0, nullptr, 1, 0, W1_BT, NNODES, 512, 512, nullptr, al1, ar1);
    }
    k_attn<8><<<(NNODES * 8 + 255) / 256, 256>>>(src);
    k_agg512<<<NNODES, 128>>>(src, b1, 1, 0, enc);       // resid=g_h1 -> enc

    // ---- output layer: 512 -> 1x16, linear residual ----
    k_l2proj2<<<(NNODES + 127) / 128, 128>>>(enc, W2, resW2, al2, ar2);
    k_attn<1><<<(NNODES + 255) / 256, 256>>>(src);
    k_agg16<<<NNODES, 32>>>(src, b2, logits);
}

// round 10
// speedup vs baseline: 2.0344x; 1.0477x over previous
#include <cuda_runtime.h>
#include <cuda_fp16.h>
#include <math.h>
#include <stdint.h>

#define NNODES 50000
#define NHALF  25000
#define NEDGES 400000

// ---------------- scratch (device globals; no allocation allowed) ----------------
__device__ float g_h0[NNODES * 64];
__device__ float g_ft[NNODES * 512];
__device__ float g_h1[NNODES * 512];
__device__ float g_el[NNODES * 8];
__device__ float g_er[NNODES * 8];
__device__ float g_e[NEDGES * 8];
__device__ float g_ft2[NNODES * 16];
__device__ float g_res2[NNODES * 16];
__device__ int   g_deg[NNODES];
__device__ int   g_cur[NNODES];
__device__ int   g_rowoff[NNODES + 1];
__device__ int   g_eid[NEDGES];
// fp16 split operands: A = hi+lo, B (weights, [N,K]) = hi only
__device__ __half g_ah[NNODES * 512];
__device__ __half g_al[NNODES * 512];
__device__ __half g_bth[327680];   // fc0@0, fc1@16384, W0@32768, W1@65536

__device__ __forceinline__ const float* srcsel(const float* ext, int id) {
    if (ext) return ext;
    return (id == 0) ? g_h0 : g_h1;
}

__device__ __forceinline__ float* csel(float* ext, int id) {
    if (ext) return ext;
    switch (id) {
        case 0: return g_h0;
        case 1: return g_ft;
    }
    return g_h1;
}

// ---------------- CSR build ----------------
__global__ void k_count(const int* __restrict__ dst) {
    int i = blockIdx.x * blockDim.x + threadIdx.x;
    if (i < NEDGES) {
        int d = dst[i];
        if (d >= 0 && d < NNODES) atomicAdd(&g_deg[d], 1);
    }
}

__global__ void k_scan() {
    __shared__ int warp_sums[32];
    __shared__ int carry_sh;
    int t = threadIdx.x;
    if (t == 0) carry_sh = 0;
    __syncthreads();
    for (int base = 0; base < NNODES; base += 1024) {
        int i = base + t;
        int v = (i < NNODES) ? g_deg[i] : 0;
        int x = v;
        #pragma unroll
        for (int o = 1; o < 32; o <<= 1) {
            int y = __shfl_up_sync(0xffffffffu, x, o);
            if ((t & 31) >= o) x += y;
        }
        if ((t & 31) == 31) warp_sums[t >> 5] = x;
        __syncthreads();
        if (t < 32) {
            int w = warp_sums[t];
            #pragma unroll
            for (int o = 1; o < 32; o <<= 1) {
                int y = __shfl_up_sync(0xffffffffu, w, o);
                if (t >= o) w += y;
            }
            warp_sums[t] = w;
        }
        __syncthreads();
        int pref = (t >= 32) ? warp_sums[(t >> 5) - 1] : 0;
        int incl = x + pref;
        int carry = carry_sh;
        if (i < NNODES) g_rowoff[i] = carry + incl - v;
        __syncthreads();
        if (t == 1023) carry_sh = carry + incl;
        __syncthreads();
    }
    if (t == 0) g_rowoff[NNODES] = carry_sh;
}

__global__ void k_scatter(const int* __restrict__ dst) {
    int i = blockIdx.x * blockDim.x + threadIdx.x;
    if (i < NEDGES) {
        int d = dst[i];
        if (d >= 0 && d < NNODES) {
            int p = g_rowoff[d] + atomicAdd(&g_cur[d], 1);
            g_eid[p] = i;
        }
    }
}

__global__ void k_sortseg() {
    int n = blockIdx.x * blockDim.x + threadIdx.x;
    if (n >= NNODES) return;
    int s = g_rowoff[n], e = g_rowoff[n + 1];
    for (int i = s + 1; i < e; i++) {
        int key = g_eid[i];
        int j = i - 1;
        while (j >= s && g_eid[j] > key) { g_eid[j + 1] = g_eid[j]; j--; }
        g_eid[j + 1] = key;
    }
}

// ---------------- merged prep: zero counts + all weight converts ----------------
// regions: [0,50000) zero; then fc0 16384 (K=256,N=64), fc1 16384, W0 32768 (K=64,N=512), W1 262144 (K=512,N=512)
__global__ void k_prep(const float* __restrict__ fc0_W, const float* __restrict__ fc1_W,
                       const float* __restrict__ W0, const float* __restrict__ W1)
{
    int i = blockIdx.x * blockDim.x + threadIdx.x;
    if (i < NNODES) { g_deg[i] = 0; g_cur[i] = 0; }
    int idx = i - NNODES;
    const float* W;
    int K, N, b_off;
    if (idx < 0) return;
    if (idx < 16384)        { W = fc0_W; K = 256; N = 64;  b_off = 0;     }
    else if (idx < 32768)   { W = fc1_W; K = 256; N = 64;  b_off = 16384; idx -= 16384; }
    else if (idx < 65536)   { W = W0;    K = 64;  N = 512; b_off = 32768; idx -= 32768; }
    else if (idx < 327680)  { W = W1;    K = 512; N = 512; b_off = 65536; idx -= 65536; }
    else return;
    int k = idx / N, n = idx % N;
    g_bth[b_off + n * K + k] = __float2half_rn(W[k * N + n]);
}

// ---------------- fp16 split of both inputs (x0 then x1) ----------------
__global__ void k_split_x(const float* __restrict__ x0, const float* __restrict__ x1)
{
    int i = (blockIdx.x * blockDim.x + threadIdx.x) * 4;
    if (i >= NNODES * 256) return;
    const float* X = (i < NHALF * 256) ? (x0 + i) : (x1 + (i - NHALF * 256));
    float4 v = *(const float4*)X;
    float xs[4] = {v.x, v.y, v.z, v.w};
    __half hs[4], ls[4];
    #pragma unroll
    for (int j = 0; j < 4; j++) {
        hs[j] = __float2half_rn(xs[j]);
        ls[j] = __float2half_rn(xs[j] - __half2float(hs[j]));
    }
    *(uint2*)&g_ah[i] = *(uint2*)hs;
    *(uint2*)&g_al[i] = *(uint2*)ls;
}

__global__ void k_split_rows(const float* __restrict__ Xext, int x_id, int count, int a_off)
{
    const float* X = srcsel(Xext, x_id);
    int i = (blockIdx.x * blockDim.x + threadIdx.x) * 4;
    if (i >= count) return;
    float4 v = *(const float4*)&X[i];
    float xs[4] = {v.x, v.y, v.z, v.w};
    __half hs[4], ls[4];
    #pragma unroll
    for (int j = 0; j < 4; j++) {
        hs[j] = __float2half_rn(xs[j]);
        ls[j] = __float2half_rn(xs[j] - __half2float(hs[j]));
    }
    *(uint2*)&g_ah[a_off + i] = *(uint2*)hs;
    *(uint2*)&g_al[a_off + i] = *(uint2*)ls;
}

// ---------------- fp16 2-term tensor-core GEMM, BK=64 ----------------
// C = (Ah + Al) @ B. Block tile 128x64, BK=64, 256 thr = 8 warps (4 wm x 2 wn).
__device__ __forceinline__ void mma_f16(float* c, const uint32_t* a, const uint32_t* b) {
    asm("mma.sync.aligned.m16n8k16.row.col.f32.f16.f16.f32 "
        "{%0,%1,%2,%3}, {%4,%5,%6,%7}, {%8,%9}, {%0,%1,%2,%3};"
        : "+f"(c[0]), "+f"(c[1]), "+f"(c[2]), "+f"(c[3])
        : "r"(a[0]), "r"(a[1]), "r"(a[2]), "r"(a[3]), "r"(b[0]), "r"(b[1]));
}

__global__ __launch_bounds__(256) void gemm_f16(
    int a_off, float* __restrict__ Cext, int c_id, size_t c_off,
    int b_off, int M, int N, int K,
    const float* __restrict__ bias,
    const float* __restrict__ attn_al, const float* __restrict__ attn_ar)
{
    // fragment-order smem, 4 k-steps per stage:
    // A: ((F*4+ks)*32 + lane)*4 + reg   (F=0..7, ks=0..3)  -> 4096 u32 per hi/lo
    // B: ((NF*4+ks)*32 + lane)*2 + reg  (NF=0..7)          -> 2048 u32
    __shared__ uint32_t As[2][4096];
    __shared__ uint32_t Bs[2048];
    __shared__ float sl[128][2], sr[128][2];

    float* C = csel(Cext, c_id) + c_off;
    const __half* Ah = g_ah + a_off;
    const __half* Al = g_al + a_off;
    const __half* Bth = g_bth + b_off;

    int tid  = threadIdx.x;
    int lane = tid & 31;
    int w    = tid >> 5;
    int wm   = w & 3;
    int wn   = w >> 2;
    int bm0  = blockIdx.y * 128;
    int bn0  = blockIdx.x * 64;

    float acc[2][4][4];
    #pragma unroll
    for (int mf = 0; mf < 2; mf++)
        #pragma unroll
        for (int nf = 0; nf < 4; nf++)
            #pragma unroll
            for (int i = 0; i < 4; i++) acc[mf][nf][i] = 0.f;

    // A: 1024 16B-chunks (128 rows x 8); B: 512 chunks (64 rows x 8)
    int a_r[4], a_j[4];
    #pragma unroll
    for (int i = 0; i < 4; i++) {
        int idx = tid + i * 256;
        a_r[i] = idx >> 3;
        a_j[i] = idx & 7;
    }
    int b_r[2], b_j[2];
    #pragma unroll
    for (int i = 0; i < 2; i++) {
        int idx = tid + i * 256;
        b_r[i] = idx >> 3;
        b_j[i] = idx & 7;
    }

    for (int k0 = 0; k0 < K; k0 += 64) {
        uint4 a_hi[4], a_lo[4], b_hi[2];
        #pragma unroll
        for (int i = 0; i < 4; i++) {
            int gr = bm0 + a_r[i];
            if (gr < M) {
                size_t off = (size_t)gr * K + k0 + a_j[i] * 8;
                a_hi[i] = *(const uint4*)&Ah[off];
                a_lo[i] = *(const uint4*)&Al[off];
            } else {
                a_hi[i] = make_uint4(0, 0, 0, 0);
                a_lo[i] = make_uint4(0, 0, 0, 0);
            }
        }
        #pragma unroll
        for (int i = 0; i < 2; i++) {
            size_t off = (size_t)(bn0 + b_r[i]) * K + k0 + b_j[i] * 8;
            b_hi[i] = *(const uint4*)&Bth[off];
        }
        __syncthreads();
        #pragma unroll
        for (int i = 0; i < 4; i++) {
            int r = a_r[i], j = a_j[i];
            int ks  = j >> 1;
            int reg = ((r >> 3) & 1) | ((j & 1) << 1);
            int base = (((r >> 4) * 4 + ks) * 32 + (r & 7) * 4) * 4 + reg;
            uint32_t vh[4] = {a_hi[i].x, a_hi[i].y, a_hi[i].z, a_hi[i].w};
            uint32_t vl[4] = {a_lo[i].x, a_lo[i].y, a_lo[i].z, a_lo[i].w};
            #pragma unroll
            for (int p = 0; p < 4; p++) {
                As[0][base + p * 4] = vh[p];
                As[1][base + p * 4] = vl[p];
            }
        }
        #pragma unroll
        for (int i = 0; i < 2; i++) {
            int r = b_r[i], j = b_j[i];
            int ks  = j >> 1;
            int reg = j & 1;
            int base = (((r >> 3) * 4 + ks) * 32 + (r & 7) * 4) * 2 + reg;
            uint32_t vh[4] = {b_hi[i].x, b_hi[i].y, b_hi[i].z, b_hi[i].w};
            #pragma unroll
            for (int p = 0; p < 4; p++)
                Bs[base + p * 2] = vh[p];
        }
        __syncthreads();
        #pragma unroll
        for (int ks = 0; ks < 4; ks++) {
            uint32_t ah[2][4], al2_[2][4], bh[4][2];
            #pragma unroll
            for (int mf = 0; mf < 2; mf++) {
                int off = (((wm * 2 + mf) * 4 + ks) * 32 + lane) * 4;
                uint4 h = *(const uint4*)&As[0][off];
                uint4 l = *(const uint4*)&As[1][off];
                ah[mf][0] = h.x; ah[mf][1] = h.y; ah[mf][2] = h.z; ah[mf][3] = h.w;
                al2_[mf][0] = l.x; al2_[mf][1] = l.y; al2_[mf][2] = l.z; al2_[mf][3] = l.w;
            }
            #pragma unroll
            for (int nf = 0; nf < 4; nf++) {
                int off = (((wn * 4 + nf) * 4 + ks) * 32 + lane) * 2;
                uint2 h = *(const uint2*)&Bs[off];
                bh[nf][0] = h.x; bh[nf][1] = h.y;
            }
            #pragma unroll
            for (int mf = 0; mf < 2; mf++)
                #pragma unroll
                for (int nf = 0; nf < 4; nf++) {
                    mma_f16(acc[mf][nf], ah[mf], bh[nf]);
                    mma_f16(acc[mf][nf], al2_[mf], bh[nf]);
                }
        }
    }
    // epilogue: C + bias
    #pragma unroll
    for (int mf = 0; mf < 2; mf++) {
        int r0 = bm0 + wm * 32 + mf * 16 + (lane >> 2);
        #pragma unroll
        for (int nf = 0; nf < 4; nf++) {
            int c0 = bn0 + wn * 32 + nf * 8 + (lane & 3) * 2;
            float bz0 = bias ? bias[c0] : 0.f;
            float bz1 = bias ? bias[c0 + 1] : 0.f;
            if (r0 < M) {
                C[(size_t)r0 * N + c0]     = acc[mf][nf][0] + bz0;
                C[(size_t)r0 * N + c0 + 1] = acc[mf][nf][1] + bz1;
            }
            if (r0 + 8 < M) {
                C[(size_t)(r0 + 8) * N + c0]     = acc[mf][nf][2] + bz0;
                C[(size_t)(r0 + 8) * N + c0 + 1] = acc[mf][nf][3] + bz1;
            }
        }
    }
    // fused el/er (H=8 layers: block col tile == one head)
    if (attn_al) {
        int h = bn0 >> 6;
        float pl[2][2] = {{0.f, 0.f}, {0.f, 0.f}};
        float pr[2][2] = {{0.f, 0.f}, {0.f, 0.f}};
        #pragma unroll
        for (int mf = 0; mf < 2; mf++)
            #pragma unroll
            for (int nf = 0; nf < 4; nf++)
                #pragma unroll
                for (int s = 0; s < 2; s++) {
                    int d = wn * 32 + nf * 8 + (lane & 3) * 2 + s;
                    float wl = attn_al[h * 64 + d];
                    float wr = attn_ar[h * 64 + d];
                    pl[mf][0] = fmaf(acc[mf][nf][s],     wl, pl[mf][0]);
                    pl[mf][1] = fmaf(acc[mf][nf][2 + s], wl, pl[mf][1]);
                    pr[mf][0] = fmaf(acc[mf][nf][s],     wr, pr[mf][0]);
                    pr[mf][1] = fmaf(acc[mf][nf][2 + s], wr, pr[mf][1]);
                }
        #pragma unroll
        for (int mf = 0; mf < 2; mf++)
            #pragma unroll
            for (int hf = 0; hf < 2; hf++) {
                float vl = pl[mf][hf], vr = pr[mf][hf];
                vl += __shfl_xor_sync(0xffffffffu, vl, 1);
                vl += __shfl_xor_sync(0xffffffffu, vl, 2);
                vr += __shfl_xor_sync(0xffffffffu, vr, 1);
                vr += __shfl_xor_sync(0xffffffffu, vr, 2);
                if ((lane & 3) == 0) {
                    int rl = wm * 32 + mf * 16 + hf * 8 + (lane >> 2);
                    sl[rl][wn] = vl;
                    sr[rl][wn] = vr;
                }
            }
        __syncthreads();
        if (tid < 128) {
            int row = bm0 + tid;
            if (row < M) {
                g_el[row * 8 + h] = sl[tid][0] + sl[tid][1];
                g_er[row * 8 + h] = sr[tid][0] + sr[tid][1];
            }
        }
    }
}

// ---------------- fused edge-logit + segment softmax (no max pass; shift-invariant) ----------------
template <int H>
__global__ void k_attn(const int* __restrict__ src)
{
    int t = blockIdx.x * blockDim.x + threadIdx.x;
    if (t >= NNODES * H) return;
    int n = t / H, h = t % H;
    int s0 = g_rowoff[n], s1 = g_rowoff[n + 1];
    float ern = g_er[n * H + h];
    float sum = 0.f;
    for (int p = s0; p < s1; p++) {
        int eid = g_eid[p];
        float x = g_el[src[eid] * H + h] + ern;
        x = (x >= 0.f) ? x : 0.2f * x;
        float ex = expf(x);
        g_e[(size_t)eid * H + h] = ex;
        sum += ex;
    }
    float inv = 1.f / (sum + 1e-16f);
    for (int p = s0; p < s1; p++) g_e[(size_t)g_eid[p] * H + h] *= inv;
}

// ---------------- aggregation, F=512, H=8 (optionally emits fp16 split of out) ----------------
__global__ __launch_bounds__(128) void k_agg512(
    const int* __restrict__ src,
    const float* __restrict__ bias, int use_resid, int write_split,
    float* __restrict__ out_ext)
{
    const float* ft = g_ft;
    float* out = out_ext ? out_ext : g_h1;
    int n = blockIdx.x;
    int t = threadIdx.x;
    int f = t * 4;
    int h = f >> 6;
    float4 acc = *(const float4*)&bias[f];
    if (use_resid) {
        float4 r = *(const float4*)&g_h1[(size_t)n * 512 + f];
        acc.x += r.x; acc.y += r.y; acc.z += r.z; acc.w += r.w;
    }
    int s0 = g_rowoff[n], s1 = g_rowoff[n + 1];
    for (int p = s0; p < s1; p++) {
        int eid = g_eid[p];
        float w = g_e[(size_t)eid * 8 + h];
        int s = src[eid];
        float4 v = *(const float4*)&ft[(size_t)s * 512 + f];
        acc.x = fmaf(w, v.x, acc.x);
        acc.y = fmaf(w, v.y, acc.y);
        acc.z = fmaf(w, v.z, acc.z);
        acc.w = fmaf(w, v.w, acc.w);
    }
    acc.x = (acc.x > 0.f) ? acc.x : expm1f(acc.x);
    acc.y = (acc.y > 0.f) ? acc.y : expm1f(acc.y);
    acc.z = (acc.z > 0.f) ? acc.z : expm1f(acc.z);
    acc.w = (acc.w > 0.f) ? acc.w : expm1f(acc.w);
    *(float4*)&out[(size_t)n * 512 + f] = acc;
    if (write_split) {
        float vv[4] = {acc.x, acc.y, acc.z, acc.w};
        __half hs[4], ls[4];
        #pragma unroll
        for (int j = 0; j < 4; j++) {
            hs[j] = __float2half_rn(vv[j]);
            ls[j] = __float2half_rn(vv[j] - __half2float(hs[j]));
        }
        *(uint2*)&g_ah[(size_t)n * 512 + f] = *(uint2*)hs;
        *(uint2*)&g_al[(size_t)n * 512 + f] = *(uint2*)ls;
    }
}

// ---------------- layer-2 projections (tiled, smem weight reuse) ----------------
__global__ __launch_bounds__(128) void k_l2proj2(
    const float* __restrict__ h2, const float* __restrict__ W2,
    const float* __restrict__ resW2, const float* __restrict__ al2,
    const float* __restrict__ ar2)
{
    __shared__ float sW[64 * 16];
    __shared__ float sR[64 * 16];
    int n = blockIdx.x * 128 + threadIdx.x;
    int nc = (n < NNODES) ? n : (NNODES - 1);
    const float* hr = h2 + (size_t)nc * 512;

    float a1[16], a2[16];
    #pragma unroll
    for (int c = 0; c < 16; c++) { a1[c] = 0.f; a2[c] = 0.f; }

    for (int k0 = 0; k0 < 512; k0 += 64) {
        __syncthreads();
        #pragma unroll
        for (int i = 0; i < 8; i++) {
            int idx = threadIdx.x + i * 128;
            sW[idx] = W2[k0 * 16 + idx];
            sR[idx] = resW2[k0 * 16 + idx];
        }
        __syncthreads();
        #pragma unroll
        for (int kk = 0; kk < 64; kk += 4) {
            float4 hv4 = *(const float4*)&hr[k0 + kk];
            float hv[4] = {hv4.x, hv4.y, hv4.z, hv4.w};
            #pragma unroll
            for (int q = 0; q < 4; q++) {
                float hq = hv[q];
                const float4* w4 = (const float4*)&sW[(kk + q) * 16];
                const float4* r4 = (const float4*)&sR[(kk + q) * 16];
                #pragma unroll
                for (int v = 0; v < 4; v++) {
                    float4 wv = w4[v], rv = r4[v];
                    a1[v * 4 + 0] = fmaf(hq, wv.x, a1[v * 4 + 0]);
                    a1[v * 4 + 1] = fmaf(hq, wv.y, a1[v * 4 + 1]);
                    a1[v * 4 + 2] = fmaf(hq, wv.z, a1[v * 4 + 2]);
                    a1[v * 4 + 3] = fmaf(hq, wv.w, a1[v * 4 + 3]);
                    a2[v * 4 + 0] = fmaf(hq, rv.x, a2[v * 4 + 0]);
                    a2[v * 4 + 1] = fmaf(hq, rv.y, a2[v * 4 + 1]);
                    a2[v * 4 + 2] = fmaf(hq, rv.z, a2[v * 4 + 2]);
                    a2[v * 4 + 3] = fmaf(hq, rv.w, a2[v * 4 + 3]);
                }
            }
        }
    }
    if (n < NNODES) {
        float el = 0.f, er = 0.f;
        #pragma unroll
        for (int c = 0; c < 16; c++) {
            el = fmaf(a1[c], al2[c], el);
            er = fmaf(a1[c], ar2[c], er);
        }
        g_el[n] = el;
        g_er[n] = er;
        #pragma unroll
        for (int v = 0; v < 4; v++) {
            *(float4*)&g_ft2[n * 16 + v * 4]  = make_float4(a1[v*4], a1[v*4+1], a1[v*4+2], a1[v*4+3]);
            *(float4*)&g_res2[n * 16 + v * 4] = make_float4(a2[v*4], a2[v*4+1], a2[v*4+2], a2[v*4+3]);
        }
    }
}

// ---------------- aggregation F=16, H=1 ----------------
__global__ __launch_bounds__(32) void k_agg16(
    const int* __restrict__ src, const float* __restrict__ b2,
    float* __restrict__ logits)
{
    int n = blockIdx.x;
    int lane = threadIdx.x;
    if (lane >= 16) return;
    float acc = g_res2[n * 16 + lane] + b2[lane];
    int s0 = g_rowoff[n], s1 = g_rowoff[n + 1];
    for (int p = s0; p < s1; p++) {
        int eid = g_eid[p];
        float w = g_e[eid];
        int s = src[eid];
        acc = fmaf(w, g_ft2[s * 16 + lane], acc);
    }
    logits[n * 16 + lane] = acc;
}

// ---------------- launch (ONLY kernel launches — graph-capturable) ----------------
extern "C" void kernel_launch(void* const* d_in, const int* in_sizes, int n_in,
                              void* d_out, int out_size)
{
    const float* x0    = (const float*)d_in[0];
    const float* x1    = (const float*)d_in[1];
    const int*   src   = (const int*)d_in[2];
    const int*   dst   = (const int*)d_in[3];
    const float* fc0_W = (const float*)d_in[4];
    const float* fc0_b = (const float*)d_in[5];
    const float* fc1_W = (const float*)d_in[6];
    const float* fc1_b = (const float*)d_in[7];
    const float* W0  = (const float*)d_in[8];
    const float* al0 = (const float*)d_in[9];
    const float* ar0 = (const float*)d_in[10];
    const float* b0  = (const float*)d_in[11];
    const float* W1  = (const float*)d_in[12];
    const float* al1 = (const float*)d_in[13];
    const float* ar1 = (const float*)d_in[14];
    const float* b1  = (const float*)d_in[15];
    const float* W2  = (const float*)d_in[16];
    const float* al2 = (const float*)d_in[17];
    const float* ar2 = (const float*)d_in[18];
    const float* b2  = (const float*)d_in[19];
    const float* resW2 = (const float*)d_in[20];

    float* out    = (float*)d_out;
    float* logits = out;                         // [50000,16]
    float* enc    = out + (size_t)NNODES * 16;   // [50000,512]

    const int FC0_BT = 0, FC1_BT = 16384, W0_BT = 32768, W1_BT = 65536;

    // ---- prep (zero counts + all weight converts) + input splits ----
    k_prep<<<(NNODES + 327680 + 255) / 256, 256>>>(fc0_W, fc1_W, W0, W1);
    k_split_x<<<(NNODES * 256 / 4 + 255) / 256, 256>>>(x0, x1);

    // ---- CSR build ----
    k_count<<<(NEDGES + 255) / 256, 256>>>(dst);
    k_scan<<<1, 1024>>>();
    k_scatter<<<(NEDGES + 255) / 256, 256>>>(dst);
    k_sortseg<<<(NNODES + 255) / 256, 256>>>();

    // ---- fc: per-type projections -> g_h0 ----
    {
        dim3 g(1, (NHALF + 127) / 128);
        gemm_f16<<<g, 256>>>(0,           nullptr, 0, 0,                  FC0_BT, NHALF, 64, 256, fc0_b, nullptr, nullptr);
        gemm_f16<<<g, 256>>>(NHALF * 256, nullptr, 0, (size_t)NHALF * 64, FC1_BT, NHALF, 64, 256, fc1_b, nullptr, nullptr);
    }

    // ---- layer 0: 64 -> 8x64, elu (el/er fused) ----
    k_split_rows<<<(NNODES * 64 / 4 + 255) / 256, 256>>>(nullptr, 0, NNODES * 64, 0);
    {
        dim3 g(8, (NNODES + 127) / 128);
        gemm_f16<<<g, 256>>>(0, nullptr, 1, 0, W0_BT, NNODES, 512, 64, nullptr, al0, ar0);
    }
    k_attn<8><<<(NNODES * 8 + 255) / 256, 256>>>(src);
    k_agg512<<<NNODES, 128>>>(src, b0, 0, 1, nullptr);   // -> g_h1 + fp16 split for L1

    // ---- layer 1: 512 -> 8x64, id residual, elu -> encoded ----
    {
        dim3 g(8, (NNODES + 127) / 128);
        gemm_f16<<<g, 256>>>(0, nullptr, 1, 0, W1_BT, NNODES, 512, 512, nullptr, al1, ar1);
    }
    k_attn<8><<<(NNODES * 8 + 255) / 256, 256>>>(src);
    k_agg512<<<NNODES, 128>>>(src, b1, 1, 0, enc);       // resid=g_h1 -> enc

    // ---- output layer: 512 -> 1x16, linear residual ----
    k_l2proj2<<<(NNODES + 127) / 128, 128>>>(enc, W2, resW2, al2, ar2);
    k_attn<1><<<(NNODES + 255) / 256, 256>>>(src);
    k_agg16<<<NNODES, 32>>>(src, b2, logits);
}

// round 12
// speedup vs baseline: 2.1117x; 1.0380x over previous
#include <cuda_runtime.h>
#include <cuda_fp16.h>
#include <math.h>
#include <stdint.h>

#define NNODES 50000
#define NHALF  25000
#define NEDGES 400000
#define L0SPLIT 12800000   // fc-output split region in g_ah/g_al (disjoint from x0/x1 splits)

// ---------------- scratch (device globals; no allocation allowed) ----------------
__device__ float g_h0[NNODES * 64];
__device__ float g_ft[NNODES * 512];
__device__ float g_h1[NNODES * 512];
__device__ float g_el[NNODES * 8];
__device__ float g_er[NNODES * 8];
__device__ float g_e[NEDGES * 8];
__device__ float g_ft2[NNODES * 16];
__device__ float g_res2[NNODES * 16];
__device__ int   g_deg[NNODES];
__device__ int   g_cur[NNODES];
__device__ int   g_rowoff[NNODES + 1];
__device__ int   g_eid[NEDGES];
__device__ int   g_bsum[64];
// fp16 split operands: A = hi+lo, B (weights, [N,K]) = hi only
__device__ __half g_ah[NNODES * 512];
__device__ __half g_al[NNODES * 512];
__device__ __half g_bth[327680];   // fc0@0, fc1@16384, W0@32768, W1@65536

__device__ __forceinline__ float* csel(float* ext, int id) {
    if (ext) return ext;
    switch (id) {
        case 0: return g_h0;
        case 1: return g_ft;
    }
    return g_h1;
}

// ---------------- CSR build ----------------
__global__ void k_count(const int* __restrict__ dst) {
    int i = blockIdx.x * blockDim.x + threadIdx.x;
    if (i < NEDGES) {
        int d = dst[i];
        if (d >= 0 && d < NNODES) atomicAdd(&g_deg[d], 1);
    }
}

// parallel scan, phase A: per-1024-chunk local scan
__global__ void k_scanA() {
    __shared__ int ws[32];
    int t = threadIdx.x;
    int i = blockIdx.x * 1024 + t;
    int v = (i < NNODES) ? g_deg[i] : 0;
    int x = v;
    #pragma unroll
    for (int o = 1; o < 32; o <<= 1) {
        int y = __shfl_up_sync(0xffffffffu, x, o);
        if ((t & 31) >= o) x += y;
    }
    if ((t & 31) == 31) ws[t >> 5] = x;
    __syncthreads();
    if (t < 32) {
        int w = ws[t];
        #pragma unroll
        for (int o = 1; o < 32; o <<= 1) {
            int y = __shfl_up_sync(0xffffffffu, w, o);
            if (t >= o) w += y;
        }
        ws[t] = w;
    }
    __syncthreads();
    int incl = x + ((t >= 32) ? ws[(t >> 5) - 1] : 0);
    if (i < NNODES) g_rowoff[i] = incl - v;          // chunk-local exclusive
    if (t == 1023) g_bsum[blockIdx.x] = incl;        // chunk total
}

// phase B: scan 49 block totals (single block of 64)
__global__ void k_scanB() {
    __shared__ int s[64];
    int t = threadIdx.x;
    int nb = (NNODES + 1023) / 1024;                 // 49
    int v = (t < nb) ? g_bsum[t] : 0;
    s[t] = v;
    __syncthreads();
    #pragma unroll
    for (int o = 1; o < 64; o <<= 1) {
        int y = (t >= o) ? s[t - o] : 0;
        __syncthreads();
        s[t] += y;
        __syncthreads();
    }
    if (t < nb) g_bsum[t] = s[t] - v;                // exclusive block offset
    if (t == 63) g_rowoff[NNODES] = s[63];           // total
}

// phase C: add block offsets
__global__ void k_scanC() {
    int i = blockIdx.x * 1024 + threadIdx.x;
    if (i < NNODES) g_rowoff[i] += g_bsum[blockIdx.x];
}

__global__ void k_scatter(const int* __restrict__ dst) {
    int i = blockIdx.x * blockDim.x + threadIdx.x;
    if (i < NEDGES) {
        int d = dst[i];
        if (d >= 0 && d < NNODES) {
            int p = g_rowoff[d] + atomicAdd(&g_cur[d], 1);
            g_eid[p] = i;
        }
    }
}

__global__ void k_sortseg() {
    int n = blockIdx.x * blockDim.x + threadIdx.x;
    if (n >= NNODES) return;
    int s = g_rowoff[n], e = g_rowoff[n + 1];
    for (int i = s + 1; i < e; i++) {
        int key = g_eid[i];
        int j = i - 1;
        while (j >= s && g_eid[j] > key) { g_eid[j + 1] = g_eid[j]; j--; }
        g_eid[j + 1] = key;
    }
}

// ---------------- merged prep: zero counts + all weight converts ----------------
__global__ void k_prep(const float* __restrict__ fc0_W, const float* __restrict__ fc1_W,
                       const float* __restrict__ W0, const float* __restrict__ W1)
{
    int i = blockIdx.x * blockDim.x + threadIdx.x;
    if (i < NNODES) { g_deg[i] = 0; g_cur[i] = 0; }
    int idx = i - NNODES;
    const float* W;
    int K, N, b_off;
    if (idx < 0) return;
    if (idx < 16384)        { W = fc0_W; K = 256; N = 64;  b_off = 0;     }
    else if (idx < 32768)   { W = fc1_W; K = 256; N = 64;  b_off = 16384; idx -= 16384; }
    else if (idx < 65536)   { W = W0;    K = 64;  N = 512; b_off = 32768; idx -= 32768; }
    else if (idx < 327680)  { W = W1;    K = 512; N = 512; b_off = 65536; idx -= 65536; }
    else return;
    int k = idx / N, n = idx % N;
    g_bth[b_off + n * K + k] = __float2half_rn(W[k * N + n]);
}

// ---------------- fp16 split of both inputs (x0 then x1) ----------------
__global__ void k_split_x(const float* __restrict__ x0, const float* __restrict__ x1)
{
    int i = (blockIdx.x * blockDim.x + threadIdx.x) * 4;
    if (i >= NNODES * 256) return;
    const float* X = (i < NHALF * 256) ? (x0 + i) : (x1 + (i - NHALF * 256));
    float4 v = *(const float4*)X;
    float xs[4] = {v.x, v.y, v.z, v.w};
    __half hs[4], ls[4];
    #pragma unroll
    for (int j = 0; j < 4; j++) {
        hs[j] = __float2half_rn(xs[j]);
        ls[j] = __float2half_rn(xs[j] - __half2float(hs[j]));
    }
    *(uint2*)&g_ah[i] = *(uint2*)hs;
    *(uint2*)&g_al[i] = *(uint2*)ls;
}

// ---------------- fp16 2-term tensor-core GEMM, BK=64 ----------------
__device__ __forceinline__ void mma_f16(float* c, const uint32_t* a, const uint32_t* b) {
    asm("mma.sync.aligned.m16n8k16.row.col.f32.f16.f16.f32 "
        "{%0,%1,%2,%3}, {%4,%5,%6,%7}, {%8,%9}, {%0,%1,%2,%3};"
        : "+f"(c[0]), "+f"(c[1]), "+f"(c[2]), "+f"(c[3])
        : "r"(a[0]), "r"(a[1]), "r"(a[2]), "r"(a[3]), "r"(b[0]), "r"(b[1]));
}

__global__ __launch_bounds__(256) void gemm_f16(
    int a_off, float* __restrict__ Cext, int c_id, size_t c_off,
    int b_off, int M, int N, int K,
    const float* __restrict__ bias,
    const float* __restrict__ attn_al, const float* __restrict__ attn_ar,
    long long split_off)
{
    __shared__ uint32_t As[2][4096];
    __shared__ uint32_t Bs[2048];
    __shared__ float sl[128][2], sr[128][2];

    float* C = csel(Cext, c_id) + c_off;
    const __half* Ah = g_ah + a_off;
    const __half* Al = g_al + a_off;
    const __half* Bth = g_bth + b_off;

    int tid  = threadIdx.x;
    int lane = tid & 31;
    int w    = tid >> 5;
    int wm   = w & 3;
    int wn   = w >> 2;
    int bm0  = blockIdx.y * 128;
    int bn0  = blockIdx.x * 64;

    float acc[2][4][4];
    #pragma unroll
    for (int mf = 0; mf < 2; mf++)
        #pragma unroll
        for (int nf = 0; nf < 4; nf++)
            #pragma unroll
            for (int i = 0; i < 4; i++) acc[mf][nf][i] = 0.f;

    int a_r[4], a_j[4];
    #pragma unroll
    for (int i = 0; i < 4; i++) {
        int idx = tid + i * 256;
        a_r[i] = idx >> 3;
        a_j[i] = idx & 7;
    }
    int b_r[2], b_j[2];
    #pragma unroll
    for (int i = 0; i < 2; i++) {
        int idx = tid + i * 256;
        b_r[i] = idx >> 3;
        b_j[i] = idx & 7;
    }

    for (int k0 = 0; k0 < K; k0 += 64) {
        uint4 a_hi[4], a_lo[4], b_hi[2];
        #pragma unroll
        for (int i = 0; i < 4; i++) {
            int gr = bm0 + a_r[i];
            if (gr < M) {
                size_t off = (size_t)gr * K + k0 + a_j[i] * 8;
                a_hi[i] = *(const uint4*)&Ah[off];
                a_lo[i] = *(const uint4*)&Al[off];
            } else {
                a_hi[i] = make_uint4(0, 0, 0, 0);
                a_lo[i] = make_uint4(0, 0, 0, 0);
            }
        }
        #pragma unroll
        for (int i = 0; i < 2; i++) {
            size_t off = (size_t)(bn0 + b_r[i]) * K + k0 + b_j[i] * 8;
            b_hi[i] = *(const uint4*)&Bth[off];
        }
        __syncthreads();
        #pragma unroll
        for (int i = 0; i < 4; i++) {
            int r = a_r[i], j = a_j[i];
            int ks  = j >> 1;
            int reg = ((r >> 3) & 1) | ((j & 1) << 1);
            int base = (((r >> 4) * 4 + ks) * 32 + (r & 7) * 4) * 4 + reg;
            uint32_t vh[4] = {a_hi[i].x, a_hi[i].y, a_hi[i].z, a_hi[i].w};
            uint32_t vl[4] = {a_lo[i].x, a_lo[i].y, a_lo[i].z, a_lo[i].w};
            #pragma unroll
            for (int p = 0; p < 4; p++) {
                As[0][base + p * 4] = vh[p];
                As[1][base + p * 4] = vl[p];
            }
        }
        #pragma unroll
        for (int i = 0; i < 2; i++) {
            int r = b_r[i], j = b_j[i];
            int ks  = j >> 1;
            int reg = j & 1;
            int base = (((r >> 3) * 4 + ks) * 32 + (r & 7) * 4) * 2 + reg;
            uint32_t vh[4] = {b_hi[i].x, b_hi[i].y, b_hi[i].z, b_hi[i].w};
            #pragma unroll
            for (int p = 0; p < 4; p++)
                Bs[base + p * 2] = vh[p];
        }
        __syncthreads();
        #pragma unroll
        for (int ks = 0; ks < 4; ks++) {
            uint32_t ah[2][4], al2_[2][4], bh[4][2];
            #pragma unroll
            for (int mf = 0; mf < 2; mf++) {
                int off = (((wm * 2 + mf) * 4 + ks) * 32 + lane) * 4;
                uint4 h = *(const uint4*)&As[0][off];
                uint4 l = *(const uint4*)&As[1][off];
                ah[mf][0] = h.x; ah[mf][1] = h.y; ah[mf][2] = h.z; ah[mf][3] = h.w;
                al2_[mf][0] = l.x; al2_[mf][1] = l.y; al2_[mf][2] = l.z; al2_[mf][3] = l.w;
            }
            #pragma unroll
            for (int nf = 0; nf < 4; nf++) {
                int off = (((wn * 4 + nf) * 4 + ks) * 32 + lane) * 2;
                uint2 h = *(const uint2*)&Bs[off];
                bh[nf][0] = h.x; bh[nf][1] = h.y;
            }
            #pragma unroll
            for (int mf = 0; mf < 2; mf++)
                #pragma unroll
                for (int nf = 0; nf < 4; nf++) {
                    mma_f16(acc[mf][nf], ah[mf], bh[nf]);
                    mma_f16(acc[mf][nf], al2_[mf], bh[nf]);
                }
        }
    }
    // epilogue: C + bias (+ optional fused fp16 split of C, to a DISJOINT region)
    #pragma unroll
    for (int mf = 0; mf < 2; mf++) {
        int r0 = bm0 + wm * 32 + mf * 16 + (lane >> 2);
        #pragma unroll
        for (int nf = 0; nf < 4; nf++) {
            int c0 = bn0 + wn * 32 + nf * 8 + (lane & 3) * 2;
            float bz0 = bias ? bias[c0] : 0.f;
            float bz1 = bias ? bias[c0 + 1] : 0.f;
            #pragma unroll
            for (int half = 0; half < 2; half++) {
                int rr = r0 + half * 8;
                if (rr >= M) continue;
                float v0 = acc[mf][nf][half * 2]     + bz0;
                float v1 = acc[mf][nf][half * 2 + 1] + bz1;
                C[(size_t)rr * N + c0]     = v0;
                C[(size_t)rr * N + c0 + 1] = v1;
                if (split_off >= 0) {
                    __half h0 = __float2half_rn(v0);
                    __half h1 = __float2half_rn(v1);
                    __half l0 = __float2half_rn(v0 - __half2float(h0));
                    __half l1 = __float2half_rn(v1 - __half2float(h1));
                    __half hp[2] = {h0, h1}, lp[2] = {l0, l1};
                    *(uint32_t*)&g_ah[split_off + (size_t)rr * N + c0] = *(uint32_t*)hp;
                    *(uint32_t*)&g_al[split_off + (size_t)rr * N + c0] = *(uint32_t*)lp;
                }
            }
        }
    }
    // fused el/er (H=8 layers: block col tile == one head)
    if (attn_al) {
        int h = bn0 >> 6;
        float pl[2][2] = {{0.f, 0.f}, {0.f, 0.f}};
        float pr[2][2] = {{0.f, 0.f}, {0.f, 0.f}};
        #pragma unroll
        for (int mf = 0; mf < 2; mf++)
            #pragma unroll
            for (int nf = 0; nf < 4; nf++)
                #pragma unroll
                for (int s = 0; s < 2; s++) {
                    int d = wn * 32 + nf * 8 + (lane & 3) * 2 + s;
                    float wl = attn_al[h * 64 + d];
                    float wr = attn_ar[h * 64 + d];
                    pl[mf][0] = fmaf(acc[mf][nf][s],     wl, pl[mf][0]);
                    pl[mf][1] = fmaf(acc[mf][nf][2 + s], wl, pl[mf][1]);
                    pr[mf][0] = fmaf(acc[mf][nf][s],     wr, pr[mf][0]);
                    pr[mf][1] = fmaf(acc[mf][nf][2 + s], wr, pr[mf][1]);
                }
        #pragma unroll
        for (int mf = 0; mf < 2; mf++)
            #pragma unroll
            for (int hf = 0; hf < 2; hf++) {
                float vl = pl[mf][hf], vr = pr[mf][hf];
                vl += __shfl_xor_sync(0xffffffffu, vl, 1);
                vl += __shfl_xor_sync(0xffffffffu, vl, 2);
                vr += __shfl_xor_sync(0xffffffffu, vr, 1);
                vr += __shfl_xor_sync(0xffffffffu, vr, 2);
                if ((lane & 3) == 0) {
                    int rl = wm * 32 + mf * 16 + hf * 8 + (lane >> 2);
                    sl[rl][wn] = vl;
                    sr[rl][wn] = vr;
                }
            }
        __syncthreads();
        if (tid < 128) {
            int row = bm0 + tid;
            if (row < M) {
                g_el[row * 8 + h] = sl[tid][0] + sl[tid][1];
                g_er[row * 8 + h] = sr[tid][0] + sr[tid][1];
            }
        }
    }
}

// ---------------- fused edge-logit + segment softmax (no max pass; shift-invariant) ----------------
template <int H>
__global__ void k_attn(const int* __restrict__ src)
{
    int t = blockIdx.x * blockDim.x + threadIdx.x;
    if (t >= NNODES * H) return;
    int n = t / H, h = t % H;
    int s0 = g_rowoff[n], s1 = g_rowoff[n + 1];
    float ern = g_er[n * H + h];
    float sum = 0.f;
    for (int p = s0; p < s1; p++) {
        int eid = g_eid[p];
        float x = g_el[src[eid] * H + h] + ern;
        x = (x >= 0.f) ? x : 0.2f * x;
        float ex = expf(x);
        g_e[(size_t)eid * H + h] = ex;
        sum += ex;
    }
    float inv = 1.f / (sum + 1e-16f);
    for (int p = s0; p < s1; p++) g_e[(size_t)g_eid[p] * H + h] *= inv;
}

// ---------------- aggregation, F=512, H=8 (optionally emits fp16 split of out) ----------------
__global__ __launch_bounds__(128) void k_agg512(
    const int* __restrict__ src,
    const float* __restrict__ bias, int use_resid, int write_split,
    float* __restrict__ out_ext)
{
    const float* ft = g_ft;
    float* out = out_ext ? out_ext : g_h1;
    int n = blockIdx.x;
    int t = threadIdx.x;
    int f = t * 4;
    int h = f >> 6;
    float4 acc = *(const float4*)&bias[f];
    if (use_resid) {
        float4 r = *(const float4*)&g_h1[(size_t)n * 512 + f];
        acc.x += r.x; acc.y += r.y; acc.z += r.z; acc.w += r.w;
    }
    int s0 = g_rowoff[n], s1 = g_rowoff[n + 1];
    for (int p = s0; p < s1; p++) {
        int eid = g_eid[p];
        float w = g_e[(size_t)eid * 8 + h];
        int s = src[eid];
        float4 v = *(const float4*)&ft[(size_t)s * 512 + f];
        acc.x = fmaf(w, v.x, acc.x);
        acc.y = fmaf(w, v.y, acc.y);
        acc.z = fmaf(w, v.z, acc.z);
        acc.w = fmaf(w, v.w, acc.w);
    }
    acc.x = (acc.x > 0.f) ? acc.x : expm1f(acc.x);
    acc.y = (acc.y > 0.f) ? acc.y : expm1f(acc.y);
    acc.z = (acc.z > 0.f) ? acc.z : expm1f(acc.z);
    acc.w = (acc.w > 0.f) ? acc.w : expm1f(acc.w);
    *(float4*)&out[(size_t)n * 512 + f] = acc;
    if (write_split) {
        float vv[4] = {acc.x, acc.y, acc.z, acc.w};
        __half hs[4], ls[4];
        #pragma unroll
        for (int j = 0; j < 4; j++) {
            hs[j] = __float2half_rn(vv[j]);
            ls[j] = __float2half_rn(vv[j] - __half2float(hs[j]));
        }
        *(uint2*)&g_ah[(size_t)n * 512 + f] = *(uint2*)hs;
        *(uint2*)&g_al[(size_t)n * 512 + f] = *(uint2*)ls;
    }
}

// ---------------- layer-2 projections (tiled, smem weight reuse) ----------------
__global__ __launch_bounds__(128) void k_l2proj2(
    const float* __restrict__ h2, const float* __restrict__ W2,
    const float* __restrict__ resW2, const float* __restrict__ al2,
    const float* __restrict__ ar2)
{
    __shared__ float sW[64 * 16];
    __shared__ float sR[64 * 16];
    int n = blockIdx.x * 128 + threadIdx.x;
    int nc = (n < NNODES) ? n : (NNODES - 1);
    const float* hr = h2 + (size_t)nc * 512;

    float a1[16], a2[16];
    #pragma unroll
    for (int c = 0; c < 16; c++) { a1[c] = 0.f; a2[c] = 0.f; }

    for (int k0 = 0; k0 < 512; k0 += 64) {
        __syncthreads();
        #pragma unroll
        for (int i = 0; i < 8; i++) {
            int idx = threadIdx.x + i * 128;
            sW[idx] = W2[k0 * 16 + idx];
            sR[idx] = resW2[k0 * 16 + idx];
        }
        __syncthreads();
        #pragma unroll
        for (int kk = 0; kk < 64; kk += 4) {
            float4 hv4 = *(const float4*)&hr[k0 + kk];
            float hv[4] = {hv4.x, hv4.y, hv4.z, hv4.w};
            #pragma unroll
            for (int q = 0; q < 4; q++) {
                float hq = hv[q];
                const float4* w4 = (const float4*)&sW[(kk + q) * 16];
                const float4* r4 = (const float4*)&sR[(kk + q) * 16];
                #pragma unroll
                for (int v = 0; v < 4; v++) {
                    float4 wv = w4[v], rv = r4[v];
                    a1[v * 4 + 0] = fmaf(hq, wv.x, a1[v * 4 + 0]);
                    a1[v * 4 + 1] = fmaf(hq, wv.y, a1[v * 4 + 1]);
                    a1[v * 4 + 2] = fmaf(hq, wv.z, a1[v * 4 + 2]);
                    a1[v * 4 + 3] = fmaf(hq, wv.w, a1[v * 4 + 3]);
                    a2[v * 4 + 0] = fmaf(hq, rv.x, a2[v * 4 + 0]);
                    a2[v * 4 + 1] = fmaf(hq, rv.y, a2[v * 4 + 1]);
                    a2[v * 4 + 2] = fmaf(hq, rv.z, a2[v * 4 + 2]);
                    a2[v * 4 + 3] = fmaf(hq, rv.w, a2[v * 4 + 3]);
                }
            }
        }
    }
    if (n < NNODES) {
        float el = 0.f, er = 0.f;
        #pragma unroll
        for (int c = 0; c < 16; c++) {
            el = fmaf(a1[c], al2[c], el);
            er = fmaf(a1[c], ar2[c], er);
        }
        g_el[n] = el;
        g_er[n] = er;
        #pragma unroll
        for (int v = 0; v < 4; v++) {
            *(float4*)&g_ft2[n * 16 + v * 4]  = make_float4(a1[v*4], a1[v*4+1], a1[v*4+2], a1[v*4+3]);
            *(float4*)&g_res2[n * 16 + v * 4] = make_float4(a2[v*4], a2[v*4+1], a2[v*4+2], a2[v*4+3]);
        }
    }
}

// ---------------- aggregation F=16, H=1 ----------------
__global__ __launch_bounds__(32) void k_agg16(
    const int* __restrict__ src, const float* __restrict__ b2,
    float* __restrict__ logits)
{
    int n = blockIdx.x;
    int lane = threadIdx.x;
    if (lane >= 16) return;
    float acc = g_res2[n * 16 + lane] + b2[lane];
    int s0 = g_rowoff[n], s1 = g_rowoff[n + 1];
    for (int p = s0; p < s1; p++) {
        int eid = g_eid[p];
        float w = g_e[eid];
        int s = src[eid];
        acc = fmaf(w, g_ft2[s * 16 + lane], acc);
    }
    logits[n * 16 + lane] = acc;
}

// ---------------- launch (ONLY kernel launches — graph-capturable) ----------------
extern "C" void kernel_launch(void* const* d_in, const int* in_sizes, int n_in,
                              void* d_out, int out_size)
{
    const float* x0    = (const float*)d_in[0];
    const float* x1    = (const float*)d_in[1];
    const int*   src   = (const int*)d_in[2];
    const int*   dst   = (const int*)d_in[3];
    const float* fc0_W = (const float*)d_in[4];
    const float* fc0_b = (const float*)d_in[5];
    const float* fc1_W = (const float*)d_in[6];
    const float* fc1_b = (const float*)d_in[7];
    const float* W0  = (const float*)d_in[8];
    const float* al0 = (const float*)d_in[9];
    const float* ar0 = (const float*)d_in[10];
    const float* b0  = (const float*)d_in[11];
    const float* W1  = (const float*)d_in[12];
    const float* al1 = (const float*)d_in[13];
    const float* ar1 = (const float*)d_in[14];
    const float* b1  = (const float*)d_in[15];
    const float* W2  = (const float*)d_in[16];
    const float* al2 = (const float*)d_in[17];
    const float* ar2 = (const float*)d_in[18];
    const float* b2  = (const float*)d_in[19];
    const float* resW2 = (const float*)d_in[20];

    float* out    = (float*)d_out;
    float* logits = out;                         // [50000,16]
    float* enc    = out + (size_t)NNODES * 16;   // [50000,512]

    const int FC0_BT = 0, FC1_BT = 16384, W0_BT = 32768, W1_BT = 65536;
    const int NSCAN = (NNODES + 1023) / 1024;    // 49

    // ---- prep (zero counts + all weight converts) + input splits ----
    k_prep<<<(NNODES + 327680 + 255) / 256, 256>>>(fc0_W, fc1_W, W0, W1);
    k_split_x<<<(NNODES * 256 / 4 + 255) / 256, 256>>>(x0, x1);

    // ---- CSR build (parallel scan) ----
    k_count<<<(NEDGES + 255) / 256, 256>>>(dst);
    k_scanA<<<NSCAN, 1024>>>();
    k_scanB<<<1, 64>>>();
    k_scanC<<<NSCAN, 1024>>>();
    k_scatter<<<(NEDGES + 255) / 256, 256>>>(dst);
    k_sortseg<<<(NNODES + 255) / 256, 256>>>();

    // ---- fc: per-type projections -> g_h0 (+ fused L0-input split at L0SPLIT, disjoint) ----
    {
        dim3 g(1, (NHALF + 127) / 128);
        gemm_f16<<<g, 256>>>(0,           nullptr, 0, 0,                  FC0_BT, NHALF, 64, 256, fc0_b, nullptr, nullptr, (long long)L0SPLIT);
        gemm_f16<<<g, 256>>>(NHALF * 256, nullptr, 0, (size_t)NHALF * 64, FC1_BT, NHALF, 64, 256, fc1_b, nullptr, nullptr, (long long)L0SPLIT + NHALF * 64);
    }

    // ---- layer 0: 64 -> 8x64, elu (el/er fused) ----
    {
        dim3 g(8, (NNODES + 127) / 128);
        gemm_f16<<<g, 256>>>(L0SPLIT, nullptr, 1, 0, W0_BT, NNODES, 512, 64, nullptr, al0, ar0, -1);
    }
    k_attn<8><<<(NNODES * 8 + 255) / 256, 256>>>(src);
    k_agg512<<<NNODES, 128>>>(src, b0, 0, 1, nullptr);   // -> g_h1 + fp16 split for L1 @0

    // ---- layer 1: 512 -> 8x64, id residual, elu -> encoded ----
    {
        dim3 g(8, (NNODES + 127) / 128);
        gemm_f16<<<g, 256>>>(0, nullptr, 1, 0, W1_BT, NNODES, 512, 512, nullptr, al1, ar1, -1);
    }
    k_attn<8><<<(NNODES * 8 + 255) / 256, 256>>>(src);
    k_agg512<<<NNODES, 128>>>(src, b1, 1, 0, enc);       // resid=g_h1 -> enc

    // ---- output layer: 512 -> 1x16, linear residual ----
    k_l2proj2<<<(NNODES + 127) / 128, 128>>>(enc, W2, resW2, al2, ar2);
    k_attn<1><<<(NNODES + 255) / 256, 256>>>(src);
    k_agg16<<<NNODES, 32>>>(src, b2, logits);
}

// round 13
// speedup vs baseline: 2.1364x; 1.0117x over previous
#include <cuda_runtime.h>
#include <cuda_fp16.h>
#include <math.h>
#include <stdint.h>

#define NNODES 50000
#define NHALF  25000
#define NEDGES 400000
#define L0SPLIT 12800000   // fc-output split region in g_ah/g_al (disjoint from x0/x1 splits)

// ---------------- scratch (device globals; no allocation allowed) ----------------
__device__ float g_h0[NNODES * 64];
__device__ float g_ft[NNODES * 512];
__device__ float g_h1[NNODES * 512];
__device__ float g_el[NNODES * 8];
__device__ float g_er[NNODES * 8];
__device__ float g_e[NEDGES * 8];
__device__ float g_ft2[NNODES * 16];
__device__ float g_res2[NNODES * 16];
__device__ int   g_deg[NNODES];
__device__ int   g_cur[NNODES];
__device__ int   g_rowoff[NNODES + 1];
__device__ int   g_eid[NEDGES];
__device__ int   g_bsum[64];
// fp16 split operands: A = hi+lo, B (weights, [N,K]) = hi only
__device__ __half g_ah[NNODES * 512];
__device__ __half g_al[NNODES * 512];
__device__ __half g_bth[327680];   // fc0@0, fc1@16384, W0@32768, W1@65536

__device__ __forceinline__ float* csel(float* ext, int id) {
    if (ext) return ext;
    switch (id) {
        case 0: return g_h0;
        case 1: return g_ft;
    }
    return g_h1;
}

// ---------------- CSR build ----------------
__global__ void k_count(const int* __restrict__ dst) {
    int i = blockIdx.x * blockDim.x + threadIdx.x;
    if (i < NEDGES) {
        int d = dst[i];
        if (d >= 0 && d < NNODES) atomicAdd(&g_deg[d], 1);
    }
}

__global__ void k_scanA() {
    __shared__ int ws[32];
    int t = threadIdx.x;
    int i = blockIdx.x * 1024 + t;
    int v = (i < NNODES) ? g_deg[i] : 0;
    int x = v;
    #pragma unroll
    for (int o = 1; o < 32; o <<= 1) {
        int y = __shfl_up_sync(0xffffffffu, x, o);
        if ((t & 31) >= o) x += y;
    }
    if ((t & 31) == 31) ws[t >> 5] = x;
    __syncthreads();
    if (t < 32) {
        int w = ws[t];
        #pragma unroll
        for (int o = 1; o < 32; o <<= 1) {
            int y = __shfl_up_sync(0xffffffffu, w, o);
            if (t >= o) w += y;
        }
        ws[t] = w;
    }
    __syncthreads();
    int incl = x + ((t >= 32) ? ws[(t >> 5) - 1] : 0);
    if (i < NNODES) g_rowoff[i] = incl - v;
    if (t == 1023) g_bsum[blockIdx.x] = incl;
}

__global__ void k_scanB() {
    __shared__ int s[64];
    int t = threadIdx.x;
    int nb = (NNODES + 1023) / 1024;
    int v = (t < nb) ? g_bsum[t] : 0;
    s[t] = v;
    __syncthreads();
    #pragma unroll
    for (int o = 1; o < 64; o <<= 1) {
        int y = (t >= o) ? s[t - o] : 0;
        __syncthreads();
        s[t] += y;
        __syncthreads();
    }
    if (t < nb) g_bsum[t] = s[t] - v;
    if (t == 63) g_rowoff[NNODES] = s[63];
}

__global__ void k_scanC() {
    int i = blockIdx.x * 1024 + threadIdx.x;
    if (i < NNODES) g_rowoff[i] += g_bsum[blockIdx.x];
}

__global__ void k_scatter(const int* __restrict__ dst) {
    int i = blockIdx.x * blockDim.x + threadIdx.x;
    if (i < NEDGES) {
        int d = dst[i];
        if (d >= 0 && d < NNODES) {
            int p = g_rowoff[d] + atomicAdd(&g_cur[d], 1);
            g_eid[p] = i;
        }
    }
}

__global__ void k_sortseg() {
    int n = blockIdx.x * blockDim.x + threadIdx.x;
    if (n >= NNODES) return;
    int s = g_rowoff[n], e = g_rowoff[n + 1];
    for (int i = s + 1; i < e; i++) {
        int key = g_eid[i];
        int j = i - 1;
        while (j >= s && g_eid[j] > key) { g_eid[j + 1] = g_eid[j]; j--; }
        g_eid[j + 1] = key;
    }
}

// ---------------- merged prep: zero counts + all weight converts ----------------
__global__ void k_prep(const float* __restrict__ fc0_W, const float* __restrict__ fc1_W,
                       const float* __restrict__ W0, const float* __restrict__ W1)
{
    int i = blockIdx.x * blockDim.x + threadIdx.x;
    if (i < NNODES) { g_deg[i] = 0; g_cur[i] = 0; }
    int idx = i - NNODES;
    const float* W;
    int K, N, b_off;
    if (idx < 0) return;
    if (idx < 16384)        { W = fc0_W; K = 256; N = 64;  b_off = 0;     }
    else if (idx < 32768)   { W = fc1_W; K = 256; N = 64;  b_off = 16384; idx -= 16384; }
    else if (idx < 65536)   { W = W0;    K = 64;  N = 512; b_off = 32768; idx -= 32768; }
    else if (idx < 327680)  { W = W1;    K = 512; N = 512; b_off = 65536; idx -= 65536; }
    else return;
    int k = idx / N, n = idx % N;
    g_bth[b_off + n * K + k] = __float2half_rn(W[k * N + n]);
}

// ---------------- fp16 split of both inputs (x0 then x1) ----------------
__global__ void k_split_x(const float* __restrict__ x0, const float* __restrict__ x1)
{
    int i = (blockIdx.x * blockDim.x + threadIdx.x) * 4;
    if (i >= NNODES * 256) return;
    const float* X = (i < NHALF * 256) ? (x0 + i) : (x1 + (i - NHALF * 256));
    float4 v = *(const float4*)X;
    float xs[4] = {v.x, v.y, v.z, v.w};
    __half hs[4], ls[4];
    #pragma unroll
    for (int j = 0; j < 4; j++) {
        hs[j] = __float2half_rn(xs[j]);
        ls[j] = __float2half_rn(xs[j] - __half2float(hs[j]));
    }
    *(uint2*)&g_ah[i] = *(uint2*)hs;
    *(uint2*)&g_al[i] = *(uint2*)ls;
}

// ---------------- fp16 2-term tensor-core GEMM, BK=64, reg-prefetch pipeline ----------------
__device__ __forceinline__ void mma_f16(float* c, const uint32_t* a, const uint32_t* b) {
    asm("mma.sync.aligned.m16n8k16.row.col.f32.f16.f16.f32 "
        "{%0,%1,%2,%3}, {%4,%5,%6,%7}, {%8,%9}, {%0,%1,%2,%3};"
        : "+f"(c[0]), "+f"(c[1]), "+f"(c[2]), "+f"(c[3])
        : "r"(a[0]), "r"(a[1]), "r"(a[2]), "r"(a[3]), "r"(b[0]), "r"(b[1]));
}

__global__ __launch_bounds__(256) void gemm_f16(
    int a_off, float* __restrict__ Cext, int c_id, size_t c_off,
    int b_off, int M, int N, int K,
    const float* __restrict__ bias,
    const float* __restrict__ attn_al, const float* __restrict__ attn_ar,
    long long split_off)
{
    __shared__ uint32_t As[2][4096];
    __shared__ uint32_t Bs[2048];
    __shared__ float sl[128][2], sr[128][2];

    float* C = csel(Cext, c_id) + c_off;
    const __half* Ah = g_ah + a_off;
    const __half* Al = g_al + a_off;
    const __half* Bth = g_bth + b_off;

    int tid  = threadIdx.x;
    int lane = tid & 31;
    int w    = tid >> 5;
    int wm   = w & 3;
    int wn   = w >> 2;
    int bm0  = blockIdx.y * 128;
    int bn0  = blockIdx.x * 64;

    float acc[2][4][4];
    #pragma unroll
    for (int mf = 0; mf < 2; mf++)
        #pragma unroll
        for (int nf = 0; nf < 4; nf++)
            #pragma unroll
            for (int i = 0; i < 4; i++) acc[mf][nf][i] = 0.f;

    int a_r[4], a_j[4];
    #pragma unroll
    for (int i = 0; i < 4; i++) {
        int idx = tid + i * 256;
        a_r[i] = idx >> 3;
        a_j[i] = idx & 7;
    }
    int b_r[2], b_j[2];
    #pragma unroll
    for (int i = 0; i < 2; i++) {
        int idx = tid + i * 256;
        b_r[i] = idx >> 3;
        b_j[i] = idx & 7;
    }

    uint4 a_hi[4], a_lo[4], b_hi[2];

    // prologue: load chunk 0
    #pragma unroll
    for (int i = 0; i < 4; i++) {
        int gr = bm0 + a_r[i];
        if (gr < M) {
            size_t off = (size_t)gr * K + a_j[i] * 8;
            a_hi[i] = *(const uint4*)&Ah[off];
            a_lo[i] = *(const uint4*)&Al[off];
        } else {
            a_hi[i] = make_uint4(0, 0, 0, 0);
            a_lo[i] = make_uint4(0, 0, 0, 0);
        }
    }
    #pragma unroll
    for (int i = 0; i < 2; i++) {
        size_t off = (size_t)(bn0 + b_r[i]) * K + b_j[i] * 8;
        b_hi[i] = *(const uint4*)&Bth[off];
    }

    for (int k0 = 0; k0 < K; k0 += 64) {
        __syncthreads();   // previous compute done before overwrite
        // stage regs -> fragment-order smem
        #pragma unroll
        for (int i = 0; i < 4; i++) {
            int r = a_r[i], j = a_j[i];
            int ks  = j >> 1;
            int reg = ((r >> 3) & 1) | ((j & 1) << 1);
            int base = (((r >> 4) * 4 + ks) * 32 + (r & 7) * 4) * 4 + reg;
            uint32_t vh[4] = {a_hi[i].x, a_hi[i].y, a_hi[i].z, a_hi[i].w};
            uint32_t vl[4] = {a_lo[i].x, a_lo[i].y, a_lo[i].z, a_lo[i].w};
            #pragma unroll
            for (int p = 0; p < 4; p++) {
                As[0][base + p * 4] = vh[p];
                As[1][base + p * 4] = vl[p];
            }
        }
        #pragma unroll
        for (int i = 0; i < 2; i++) {
            int r = b_r[i], j = b_j[i];
            int ks  = j >> 1;
            int reg = j & 1;
            int base = (((r >> 3) * 4 + ks) * 32 + (r & 7) * 4) * 2 + reg;
            uint32_t vh[4] = {b_hi[i].x, b_hi[i].y, b_hi[i].z, b_hi[i].w};
            #pragma unroll
            for (int p = 0; p < 4; p++)
                Bs[base + p * 2] = vh[p];
        }
        __syncthreads();
        // prefetch next chunk (overlaps with compute below)
        int kn = k0 + 64;
        if (kn < K) {
            #pragma unroll
            for (int i = 0; i < 4; i++) {
                int gr = bm0 + a_r[i];
                if (gr < M) {
                    size_t off = (size_t)gr * K + kn + a_j[i] * 8;
                    a_hi[i] = *(const uint4*)&Ah[off];
                    a_lo[i] = *(const uint4*)&Al[off];
                } else {
                    a_hi[i] = make_uint4(0, 0, 0, 0);
                    a_lo[i] = make_uint4(0, 0, 0, 0);
                }
            }
            #pragma unroll
            for (int i = 0; i < 2; i++) {
                size_t off = (size_t)(bn0 + b_r[i]) * K + kn + b_j[i] * 8;
                b_hi[i] = *(const uint4*)&Bth[off];
            }
        }
        // compute current chunk from smem
        #pragma unroll
        for (int ks = 0; ks < 4; ks++) {
            uint32_t ah[2][4], al2_[2][4], bh[4][2];
            #pragma unroll
            for (int mf = 0; mf < 2; mf++) {
                int off = (((wm * 2 + mf) * 4 + ks) * 32 + lane) * 4;
                uint4 h = *(const uint4*)&As[0][off];
                uint4 l = *(const uint4*)&As[1][off];
                ah[mf][0] = h.x; ah[mf][1] = h.y; ah[mf][2] = h.z; ah[mf][3] = h.w;
                al2_[mf][0] = l.x; al2_[mf][1] = l.y; al2_[mf][2] = l.z; al2_[mf][3] = l.w;
            }
            #pragma unroll
            for (int nf = 0; nf < 4; nf++) {
                int off = (((wn * 4 + nf) * 4 + ks) * 32 + lane) * 2;
                uint2 h = *(const uint2*)&Bs[off];
                bh[nf][0] = h.x; bh[nf][1] = h.y;
            }
            #pragma unroll
            for (int mf = 0; mf < 2; mf++)
                #pragma unroll
                for (int nf = 0; nf < 4; nf++) {
                    mma_f16(acc[mf][nf], ah[mf], bh[nf]);
                    mma_f16(acc[mf][nf], al2_[mf], bh[nf]);
                }
        }
    }
    // epilogue: C + bias (+ optional fused fp16 split of C, to a DISJOINT region)
    #pragma unroll
    for (int mf = 0; mf < 2; mf++) {
        int r0 = bm0 + wm * 32 + mf * 16 + (lane >> 2);
        #pragma unroll
        for (int nf = 0; nf < 4; nf++) {
            int c0 = bn0 + wn * 32 + nf * 8 + (lane & 3) * 2;
            float bz0 = bias ? bias[c0] : 0.f;
            float bz1 = bias ? bias[c0 + 1] : 0.f;
            #pragma unroll
            for (int half = 0; half < 2; half++) {
                int rr = r0 + half * 8;
                if (rr >= M) continue;
                float v0 = acc[mf][nf][half * 2]     + bz0;
                float v1 = acc[mf][nf][half * 2 + 1] + bz1;
                C[(size_t)rr * N + c0]     = v0;
                C[(size_t)rr * N + c0 + 1] = v1;
                if (split_off >= 0) {
                    __half h0 = __float2half_rn(v0);
                    __half h1 = __float2half_rn(v1);
                    __half l0 = __float2half_rn(v0 - __half2float(h0));
                    __half l1 = __float2half_rn(v1 - __half2float(h1));
                    __half hp[2] = {h0, h1}, lp[2] = {l0, l1};
                    *(uint32_t*)&g_ah[split_off + (size_t)rr * N + c0] = *(uint32_t*)hp;
                    *(uint32_t*)&g_al[split_off + (size_t)rr * N + c0] = *(uint32_t*)lp;
                }
            }
        }
    }
    // fused el/er (H=8 layers: block col tile == one head)
    if (attn_al) {
        int h = bn0 >> 6;
        float pl[2][2] = {{0.f, 0.f}, {0.f, 0.f}};
        float pr[2][2] = {{0.f, 0.f}, {0.f, 0.f}};
        #pragma unroll
        for (int mf = 0; mf < 2; mf++)
            #pragma unroll
            for (int nf = 0; nf < 4; nf++)
                #pragma unroll
                for (int s = 0; s < 2; s++) {
                    int d = wn * 32 + nf * 8 + (lane & 3) * 2 + s;
                    float wl = attn_al[h * 64 + d];
                    float wr = attn_ar[h * 64 + d];
                    pl[mf][0] = fmaf(acc[mf][nf][s],     wl, pl[mf][0]);
                    pl[mf][1] = fmaf(acc[mf][nf][2 + s], wl, pl[mf][1]);
                    pr[mf][0] = fmaf(acc[mf][nf][s],     wr, pr[mf][0]);
                    pr[mf][1] = fmaf(acc[mf][nf][2 + s], wr, pr[mf][1]);
                }
        #pragma unroll
        for (int mf = 0; mf < 2; mf++)
            #pragma unroll
            for (int hf = 0; hf < 2; hf++) {
                float vl = pl[mf][hf], vr = pr[mf][hf];
                vl += __shfl_xor_sync(0xffffffffu, vl, 1);
                vl += __shfl_xor_sync(0xffffffffu, vl, 2);
                vr += __shfl_xor_sync(0xffffffffu, vr, 1);
                vr += __shfl_xor_sync(0xffffffffu, vr, 2);
                if ((lane & 3) == 0) {
                    int rl = wm * 32 + mf * 16 + hf * 8 + (lane >> 2);
                    sl[rl][wn] = vl;
                    sr[rl][wn] = vr;
                }
            }
        __syncthreads();
        if (tid < 128) {
            int row = bm0 + tid;
            if (row < M) {
                g_el[row * 8 + h] = sl[tid][0] + sl[tid][1];
                g_er[row * 8 + h] = sr[tid][0] + sr[tid][1];
            }
        }
    }
}

// ---------------- fused edge-logit + segment softmax (no max pass; shift-invariant) ----------------
template <int H>
__global__ void k_attn(const int* __restrict__ src)
{
    int t = blockIdx.x * blockDim.x + threadIdx.x;
    if (t >= NNODES * H) return;
    int n = t / H, h = t % H;
    int s0 = g_rowoff[n], s1 = g_rowoff[n + 1];
    float ern = g_er[n * H + h];
    float sum = 0.f;
    for (int p = s0; p < s1; p++) {
        int eid = g_eid[p];
        float x = g_el[src[eid] * H + h] + ern;
        x = (x >= 0.f) ? x : 0.2f * x;
        float ex = expf(x);
        g_e[(size_t)eid * H + h] = ex;
        sum += ex;
    }
    float inv = 1.f / (sum + 1e-16f);
    for (int p = s0; p < s1; p++) g_e[(size_t)g_eid[p] * H + h] *= inv;
}

// ---------------- aggregation, F=512, H=8 (optionally emits fp16 split of out) ----------------
__global__ __launch_bounds__(128) void k_agg512(
    const int* __restrict__ src,
    const float* __restrict__ bias, int use_resid, int write_split,
    float* __restrict__ out_ext)
{
    const float* ft = g_ft;
    float* out = out_ext ? out_ext : g_h1;
    int n = blockIdx.x;
    int t = threadIdx.x;
    int f = t * 4;
    int h = f >> 6;
    float4 acc = *(const float4*)&bias[f];
    if (use_resid) {
        float4 r = *(const float4*)&g_h1[(size_t)n * 512 + f];
        acc.x += r.x; acc.y += r.y; acc.z += r.z; acc.w += r.w;
    }
    int s0 = g_rowoff[n], s1 = g_rowoff[n + 1];
    for (int p = s0; p < s1; p++) {
        int eid = g_eid[p];
        float w = g_e[(size_t)eid * 8 + h];
        int s = src[eid];
        float4 v = *(const float4*)&ft[(size_t)s * 512 + f];
        acc.x = fmaf(w, v.x, acc.x);
        acc.y = fmaf(w, v.y, acc.y);
        acc.z = fmaf(w, v.z, acc.z);
        acc.w = fmaf(w, v.w, acc.w);
    }
    acc.x = (acc.x > 0.f) ? acc.x : expm1f(acc.x);
    acc.y = (acc.y > 0.f) ? acc.y : expm1f(acc.y);
    acc.z = (acc.z > 0.f) ? acc.z : expm1f(acc.z);
    acc.w = (acc.w > 0.f) ? acc.w : expm1f(acc.w);
    *(float4*)&out[(size_t)n * 512 + f] = acc;
    if (write_split) {
        float vv[4] = {acc.x, acc.y, acc.z, acc.w};
        __half hs[4], ls[4];
        #pragma unroll
        for (int j = 0; j < 4; j++) {
            hs[j] = __float2half_rn(vv[j]);
            ls[j] = __float2half_rn(vv[j] - __half2float(hs[j]));
        }
        *(uint2*)&g_ah[(size_t)n * 512 + f] = *(uint2*)hs;
        *(uint2*)&g_al[(size_t)n * 512 + f] = *(uint2*)ls;
    }
}

// ---------------- layer-2 projections (tiled, smem weight reuse) ----------------
__global__ __launch_bounds__(128) void k_l2proj2(
    const float* __restrict__ h2, const float* __restrict__ W2,
    const float* __restrict__ resW2, const float* __restrict__ al2,
    const float* __restrict__ ar2)
{
    __shared__ float sW[64 * 16];
    __shared__ float sR[64 * 16];
    int n = blockIdx.x * 128 + threadIdx.x;
    int nc = (n < NNODES) ? n : (NNODES - 1);
    const float* hr = h2 + (size_t)nc * 512;

    float a1[16], a2[16];
    #pragma unroll
    for (int c = 0; c < 16; c++) { a1[c] = 0.f; a2[c] = 0.f; }

    for (int k0 = 0; k0 < 512; k0 += 64) {
        __syncthreads();
        #pragma unroll
        for (int i = 0; i < 8; i++) {
            int idx = threadIdx.x + i * 128;
            sW[idx] = W2[k0 * 16 + idx];
            sR[idx] = resW2[k0 * 16 + idx];
        }
        __syncthreads();
        #pragma unroll
        for (int kk = 0; kk < 64; kk += 4) {
            float4 hv4 = *(const float4*)&hr[k0 + kk];
            float hv[4] = {hv4.x, hv4.y, hv4.z, hv4.w};
            #pragma unroll
            for (int q = 0; q < 4; q++) {
                float hq = hv[q];
                const float4* w4 = (const float4*)&sW[(kk + q) * 16];
                const float4* r4 = (const float4*)&sR[(kk + q) * 16];
                #pragma unroll
                for (int v = 0; v < 4; v++) {
                    float4 wv = w4[v], rv = r4[v];
                    a1[v * 4 + 0] = fmaf(hq, wv.x, a1[v * 4 + 0]);
                    a1[v * 4 + 1] = fmaf(hq, wv.y, a1[v * 4 + 1]);
                    a1[v * 4 + 2] = fmaf(hq, wv.z, a1[v * 4 + 2]);
                    a1[v * 4 + 3] = fmaf(hq, wv.w, a1[v * 4 + 3]);
                    a2[v * 4 + 0] = fmaf(hq, rv.x, a2[v * 4 + 0]);
                    a2[v * 4 + 1] = fmaf(hq, rv.y, a2[v * 4 + 1]);
                    a2[v * 4 + 2] = fmaf(hq, rv.z, a2[v * 4 + 2]);
                    a2[v * 4 + 3] = fmaf(hq, rv.w, a2[v * 4 + 3]);
                }
            }
        }
    }
    if (n < NNODES) {
        float el = 0.f, er = 0.f;
        #pragma unroll
        for (int c = 0; c < 16; c++) {
            el = fmaf(a1[c], al2[c], el);
            er = fmaf(a1[c], ar2[c], er);
        }
        g_el[n] = el;
        g_er[n] = er;
        #pragma unroll
        for (int v = 0; v < 4; v++) {
            *(float4*)&g_ft2[n * 16 + v * 4]  = make_float4(a1[v*4], a1[v*4+1], a1[v*4+2], a1[v*4+3]);
            *(float4*)&g_res2[n * 16 + v * 4] = make_float4(a2[v*4], a2[v*4+1], a2[v*4+2], a2[v*4+3]);
        }
    }
}

// ---------------- aggregation F=16, H=1 ----------------
__global__ __launch_bounds__(32) void k_agg16(
    const int* __restrict__ src, const float* __restrict__ b2,
    float* __restrict__ logits)
{
    int n = blockIdx.x;
    int lane = threadIdx.x;
    if (lane >= 16) return;
    float acc = g_res2[n * 16 + lane] + b2[lane];
    int s0 = g_rowoff[n], s1 = g_rowoff[n + 1];
    for (int p = s0; p < s1; p++) {
        int eid = g_eid[p];
        float w = g_e[eid];
        int s = src[eid];
        acc = fmaf(w, g_ft2[s * 16 + lane], acc);
    }
    logits[n * 16 + lane] = acc;
}

// ---------------- launch (ONLY kernel launches — graph-capturable) ----------------
extern "C" void kernel_launch(void* const* d_in, const int* in_sizes, int n_in,
                              void* d_out, int out_size)
{
    const float* x0    = (const float*)d_in[0];
    const float* x1    = (const float*)d_in[1];
    const int*   src   = (const int*)d_in[2];
    const int*   dst   = (const int*)d_in[3];
    const float* fc0_W = (const float*)d_in[4];
    const float* fc0_b = (const float*)d_in[5];
    const float* fc1_W = (const float*)d_in[6];
    const float* fc1_b = (const float*)d_in[7];
    const float* W0  = (const float*)d_in[8];
    const float* al0 = (const float*)d_in[9];
    const float* ar0 = (const float*)d_in[10];
    const float* b0  = (const float*)d_in[11];
    const float* W1  = (const float*)d_in[12];
    const float* al1 = (const float*)d_in[13];
    const float* ar1 = (const float*)d_in[14];
    const float* b1  = (const float*)d_in[15];
    const float* W2  = (const float*)d_in[16];
    const float* al2 = (const float*)d_in[17];
    const float* ar2 = (const float*)d_in[18];
    const float* b2  = (const float*)d_in[19];
    const float* resW2 = (const float*)d_in[20];

    float* out    = (float*)d_out;
    float* logits = out;                         // [50000,16]
    float* enc    = out + (size_t)NNODES * 16;   // [50000,512]

    const int FC0_BT = 0, FC1_BT = 16384, W0_BT = 32768, W1_BT = 65536;
    const int NSCAN = (NNODES + 1023) / 1024;    // 49

    // ---- prep (zero counts + all weight converts) + input splits ----
    k_prep<<<(NNODES + 327680 + 255) / 256, 256>>>(fc0_W, fc1_W, W0, W1);
    k_split_x<<<(NNODES * 256 / 4 + 255) / 256, 256>>>(x0, x1);

    // ---- CSR build (parallel scan) ----
    k_count<<<(NEDGES + 255) / 256, 256>>>(dst);
    k_scanA<<<NSCAN, 1024>>>();
    k_scanB<<<1, 64>>>();
    k_scanC<<<NSCAN, 1024>>>();
    k_scatter<<<(NEDGES + 255) / 256, 256>>>(dst);
    k_sortseg<<<(NNODES + 255) / 256, 256>>>();

    // ---- fc: per-type projections -> g_h0 (+ fused L0-input split at L0SPLIT, disjoint) ----
    {
        dim3 g(1, (NHALF + 127) / 128);
        gemm_f16<<<g, 256>>>(0,           nullptr, 0, 0,                  FC0_BT, NHALF, 64, 256, fc0_b, nullptr, nullptr, (long long)L0SPLIT);
        gemm_f16<<<g, 256>>>(NHALF * 256, nullptr, 0, (size_t)NHALF * 64, FC1_BT, NHALF, 64, 256, fc1_b, nullptr, nullptr, (long long)L0SPLIT + NHALF * 64);
    }

    // ---- layer 0: 64 -> 8x64, elu (el/er fused) ----
    {
        dim3 g(8, (NNODES + 127) / 128);
        gemm_f16<<<g, 256>>>(L0SPLIT, nullptr, 1, 0, W0_BT, NNODES, 512, 64, nullptr, al0, ar0, -1);
    }
    k_attn<8><<<(NNODES * 8 + 255) / 256, 256>>>(src);
    k_agg512<<<NNODES, 128>>>(src, b0, 0, 1, nullptr);   // -> g_h1 + fp16 split for L1 @0

    // ---- layer 1: 512 -> 8x64, id residual, elu -> encoded ----
    {
        dim3 g(8, (NNODES + 127) / 128);
        gemm_f16<<<g, 256>>>(0, nullptr, 1, 0, W1_BT, NNODES, 512, 512, nullptr, al1, ar1, -1);
    }
    k_attn<8><<<(NNODES * 8 + 255) / 256, 256>>>(src);
    k_agg512<<<NNODES, 128>>>(src, b1, 1, 0, enc);       // resid=g_h1 -> enc

    // ---- output layer: 512 -> 1x16, linear residual ----
    k_l2proj2<<<(NNODES + 127) / 128, 128>>>(enc, W2, resW2, al2, ar2);
    k_attn<1><<<(NNODES + 255) / 256, 256>>>(src);
    k_agg16<<<NNODES, 32>>>(src, b2, logits);
}

// round 14
// speedup vs baseline: 2.3050x; 1.0790x over previous
#include <cuda_runtime.h>
#include <cuda_fp16.h>
#include <math.h>
#include <stdint.h>

#define NNODES 50000
#define NHALF  25000
#define NEDGES 400000
#define L0SPLIT 12800000   // fc-output split region in g_ah/g_al (disjoint from x0/x1 splits)

// ---------------- scratch (device globals; no allocation allowed) ----------------
__device__ float g_h1[NNODES * 512];
__device__ float g_el[NNODES * 8];
__device__ float g_er[NNODES * 8];
__device__ float g_e[NEDGES * 8];
__device__ float g_ft2[NNODES * 16];
__device__ float g_res2[NNODES * 16];
__device__ int   g_deg[NNODES];
__device__ int   g_cur[NNODES];
__device__ int   g_rowoff[NNODES + 1];
__device__ int   g_eid[NEDGES];
__device__ int   g_bsum[64];
// fp16 operands
__device__ __half g_ah[NNODES * 512];    // A hi (x splits, L0 input split, L1 input split)
__device__ __half g_al[NNODES * 512];    // A lo
__device__ __half g_bth[327680];         // weights [N,K]: fc0@0, fc1@16384, W0@32768, W1@65536
__device__ __half g_fth[NNODES * 512];   // fp16-hi feature tensor (GEMM out, gathered by agg)

// ---------------- CSR build ----------------
__global__ void k_count(const int* __restrict__ dst) {
    int i = blockIdx.x * blockDim.x + threadIdx.x;
    if (i < NEDGES) {
        int d = dst[i];
        if (d >= 0 && d < NNODES) atomicAdd(&g_deg[d], 1);
    }
}

__global__ void k_scanA() {
    __shared__ int ws[32];
    int t = threadIdx.x;
    int i = blockIdx.x * 1024 + t;
    int v = (i < NNODES) ? g_deg[i] : 0;
    int x = v;
    #pragma unroll
    for (int o = 1; o < 32; o <<= 1) {
        int y = __shfl_up_sync(0xffffffffu, x, o);
        if ((t & 31) >= o) x += y;
    }
    if ((t & 31) == 31) ws[t >> 5] = x;
    __syncthreads();
    if (t < 32) {
        int w = ws[t];
        #pragma unroll
        for (int o = 1; o < 32; o <<= 1) {
            int y = __shfl_up_sync(0xffffffffu, w, o);
            if (t >= o) w += y;
        }
        ws[t] = w;
    }
    __syncthreads();
    int incl = x + ((t >= 32) ? ws[(t >> 5) - 1] : 0);
    if (i < NNODES) g_rowoff[i] = incl - v;
    if (t == 1023) g_bsum[blockIdx.x] = incl;
}

__global__ void k_scanB() {
    __shared__ int s[64];
    int t = threadIdx.x;
    int nb = (NNODES + 1023) / 1024;
    int v = (t < nb) ? g_bsum[t] : 0;
    s[t] = v;
    __syncthreads();
    #pragma unroll
    for (int o = 1; o < 64; o <<= 1) {
        int y = (t >= o) ? s[t - o] : 0;
        __syncthreads();
        s[t] += y;
        __syncthreads();
    }
    if (t < nb) g_bsum[t] = s[t] - v;
    if (t == 63) g_rowoff[NNODES] = s[63];
}

__global__ void k_scanC() {
    int i = blockIdx.x * 1024 + threadIdx.x;
    if (i < NNODES) g_rowoff[i] += g_bsum[blockIdx.x];
}

__global__ void k_scatter(const int* __restrict__ dst) {
    int i = blockIdx.x * blockDim.x + threadIdx.x;
    if (i < NEDGES) {
        int d = dst[i];
        if (d >= 0 && d < NNODES) {
            int p = g_rowoff[d] + atomicAdd(&g_cur[d], 1);
            g_eid[p] = i;
        }
    }
}

__global__ void k_sortseg() {
    int n = blockIdx.x * blockDim.x + threadIdx.x;
    if (n >= NNODES) return;
    int s = g_rowoff[n], e = g_rowoff[n + 1];
    for (int i = s + 1; i < e; i++) {
        int key = g_eid[i];
        int j = i - 1;
        while (j >= s && g_eid[j] > key) { g_eid[j + 1] = g_eid[j]; j--; }
        g_eid[j + 1] = key;
    }
}

// ---------------- merged prep: zero counts + all weight converts ----------------
__global__ void k_prep(const float* __restrict__ fc0_W, const float* __restrict__ fc1_W,
                       const float* __restrict__ W0, const float* __restrict__ W1)
{
    int i = blockIdx.x * blockDim.x + threadIdx.x;
    if (i < NNODES) { g_deg[i] = 0; g_cur[i] = 0; }
    int idx = i - NNODES;
    const float* W;
    int K, N, b_off;
    if (idx < 0) return;
    if (idx < 16384)        { W = fc0_W; K = 256; N = 64;  b_off = 0;     }
    else if (idx < 32768)   { W = fc1_W; K = 256; N = 64;  b_off = 16384; idx -= 16384; }
    else if (idx < 65536)   { W = W0;    K = 64;  N = 512; b_off = 32768; idx -= 32768; }
    else if (idx < 327680)  { W = W1;    K = 512; N = 512; b_off = 65536; idx -= 65536; }
    else return;
    int k = idx / N, n = idx % N;
    g_bth[b_off + n * K + k] = __float2half_rn(W[k * N + n]);
}

// ---------------- fp16 split of both inputs (x0 then x1) ----------------
__global__ void k_split_x(const float* __restrict__ x0, const float* __restrict__ x1)
{
    int i = (blockIdx.x * blockDim.x + threadIdx.x) * 4;
    if (i >= NNODES * 256) return;
    const float* X = (i < NHALF * 256) ? (x0 + i) : (x1 + (i - NHALF * 256));
    float4 v = *(const float4*)X;
    float xs[4] = {v.x, v.y, v.z, v.w};
    __half hs[4], ls[4];
    #pragma unroll
    for (int j = 0; j < 4; j++) {
        hs[j] = __float2half_rn(xs[j]);
        ls[j] = __float2half_rn(xs[j] - __half2float(hs[j]));
    }
    *(uint2*)&g_ah[i] = *(uint2*)hs;
    *(uint2*)&g_al[i] = *(uint2*)ls;
}

// ---------------- fp16 2-term tensor-core GEMM, BK=64, reg-prefetch pipeline ----------------
// store_mode: bit0 = store fp32 C (Cext), bit1 = store fp16-hi to g_fth (N must be 512)
__device__ __forceinline__ void mma_f16(float* c, const uint32_t* a, const uint32_t* b) {
    asm("mma.sync.aligned.m16n8k16.row.col.f32.f16.f16.f32 "
        "{%0,%1,%2,%3}, {%4,%5,%6,%7}, {%8,%9}, {%0,%1,%2,%3};"
        : "+f"(c[0]), "+f"(c[1]), "+f"(c[2]), "+f"(c[3])
        : "r"(a[0]), "r"(a[1]), "r"(a[2]), "r"(a[3]), "r"(b[0]), "r"(b[1]));
}

__global__ __launch_bounds__(256) void gemm_f16(
    int a_off, float* __restrict__ Cext, int store_mode,
    int b_off, int M, int N, int K,
    const float* __restrict__ bias,
    const float* __restrict__ attn_al, const float* __restrict__ attn_ar,
    long long split_off)
{
    __shared__ uint32_t As[2][4096];
    __shared__ uint32_t Bs[2048];
    __shared__ float sl[128][2], sr[128][2];

    const __half* Ah = g_ah + a_off;
    const __half* Al = g_al + a_off;
    const __half* Bth = g_bth + b_off;

    int tid  = threadIdx.x;
    int lane = tid & 31;
    int w    = tid >> 5;
    int wm   = w & 3;
    int wn   = w >> 2;
    int bm0  = blockIdx.y * 128;
    int bn0  = blockIdx.x * 64;

    float acc[2][4][4];
    #pragma unroll
    for (int mf = 0; mf < 2; mf++)
        #pragma unroll
        for (int nf = 0; nf < 4; nf++)
            #pragma unroll
            for (int i = 0; i < 4; i++) acc[mf][nf][i] = 0.f;

    int a_r[4], a_j[4];
    #pragma unroll
    for (int i = 0; i < 4; i++) {
        int idx = tid + i * 256;
        a_r[i] = idx >> 3;
        a_j[i] = idx & 7;
    }
    int b_r[2], b_j[2];
    #pragma unroll
    for (int i = 0; i < 2; i++) {
        int idx = tid + i * 256;
        b_r[i] = idx >> 3;
        b_j[i] = idx & 7;
    }

    uint4 a_hi[4], a_lo[4], b_hi[2];

    #pragma unroll
    for (int i = 0; i < 4; i++) {
        int gr = bm0 + a_r[i];
        if (gr < M) {
            size_t off = (size_t)gr * K + a_j[i] * 8;
            a_hi[i] = *(const uint4*)&Ah[off];
            a_lo[i] = *(const uint4*)&Al[off];
        } else {
            a_hi[i] = make_uint4(0, 0, 0, 0);
            a_lo[i] = make_uint4(0, 0, 0, 0);
        }
    }
    #pragma unroll
    for (int i = 0; i < 2; i++) {
        size_t off = (size_t)(bn0 + b_r[i]) * K + b_j[i] * 8;
        b_hi[i] = *(const uint4*)&Bth[off];
    }

    for (int k0 = 0; k0 < K; k0 += 64) {
        __syncthreads();
        #pragma unroll
        for (int i = 0; i < 4; i++) {
            int r = a_r[i], j = a_j[i];
            int ks  = j >> 1;
            int reg = ((r >> 3) & 1) | ((j & 1) << 1);
            int base = (((r >> 4) * 4 + ks) * 32 + (r & 7) * 4) * 4 + reg;
            uint32_t vh[4] = {a_hi[i].x, a_hi[i].y, a_hi[i].z, a_hi[i].w};
            uint32_t vl[4] = {a_lo[i].x, a_lo[i].y, a_lo[i].z, a_lo[i].w};
            #pragma unroll
            for (int p = 0; p < 4; p++) {
                As[0][base + p * 4] = vh[p];
                As[1][base + p * 4] = vl[p];
            }
        }
        #pragma unroll
        for (int i = 0; i < 2; i++) {
            int r = b_r[i], j = b_j[i];
            int ks  = j >> 1;
            int reg = j & 1;
            int base = (((r >> 3) * 4 + ks) * 32 + (r & 7) * 4) * 2 + reg;
            uint32_t vh[4] = {b_hi[i].x, b_hi[i].y, b_hi[i].z, b_hi[i].w};
            #pragma unroll
            for (int p = 0; p < 4; p++)
                Bs[base + p * 2] = vh[p];
        }
        __syncthreads();
        int kn = k0 + 64;
        if (kn < K) {
            #pragma unroll
            for (int i = 0; i < 4; i++) {
                int gr = bm0 + a_r[i];
                if (gr < M) {
                    size_t off = (size_t)gr * K + kn + a_j[i] * 8;
                    a_hi[i] = *(const uint4*)&Ah[off];
                    a_lo[i] = *(const uint4*)&Al[off];
                } else {
                    a_hi[i] = make_uint4(0, 0, 0, 0);
                    a_lo[i] = make_uint4(0, 0, 0, 0);
                }
            }
            #pragma unroll
            for (int i = 0; i < 2; i++) {
                size_t off = (size_t)(bn0 + b_r[i]) * K + kn + b_j[i] * 8;
                b_hi[i] = *(const uint4*)&Bth[off];
            }
        }
        #pragma unroll
        for (int ks = 0; ks < 4; ks++) {
            uint32_t ah[2][4], al2_[2][4], bh[4][2];
            #pragma unroll
            for (int mf = 0; mf < 2; mf++) {
                int off = (((wm * 2 + mf) * 4 + ks) * 32 + lane) * 4;
                uint4 h = *(const uint4*)&As[0][off];
                uint4 l = *(const uint4*)&As[1][off];
                ah[mf][0] = h.x; ah[mf][1] = h.y; ah[mf][2] = h.z; ah[mf][3] = h.w;
                al2_[mf][0] = l.x; al2_[mf][1] = l.y; al2_[mf][2] = l.z; al2_[mf][3] = l.w;
            }
            #pragma unroll
            for (int nf = 0; nf < 4; nf++) {
                int off = (((wn * 4 + nf) * 4 + ks) * 32 + lane) * 2;
                uint2 h = *(const uint2*)&Bs[off];
                bh[nf][0] = h.x; bh[nf][1] = h.y;
            }
            #pragma unroll
            for (int mf = 0; mf < 2; mf++)
                #pragma unroll
                for (int nf = 0; nf < 4; nf++) {
                    mma_f16(acc[mf][nf], ah[mf], bh[nf]);
                    mma_f16(acc[mf][nf], al2_[mf], bh[nf]);
                }
        }
    }
    // epilogue
    #pragma unroll
    for (int mf = 0; mf < 2; mf++) {
        int r0 = bm0 + wm * 32 + mf * 16 + (lane >> 2);
        #pragma unroll
        for (int nf = 0; nf < 4; nf++) {
            int c0 = bn0 + wn * 32 + nf * 8 + (lane & 3) * 2;
            float bz0 = bias ? bias[c0] : 0.f;
            float bz1 = bias ? bias[c0 + 1] : 0.f;
            #pragma unroll
            for (int half = 0; half < 2; half++) {
                int rr = r0 + half * 8;
                if (rr >= M) continue;
                float v0 = acc[mf][nf][half * 2]     + bz0;
                float v1 = acc[mf][nf][half * 2 + 1] + bz1;
                if (store_mode & 1) {
                    Cext[(size_t)rr * N + c0]     = v0;
                    Cext[(size_t)rr * N + c0 + 1] = v1;
                }
                __half h0 = __float2half_rn(v0);
                __half h1 = __float2half_rn(v1);
                if (store_mode & 2) {
                    __half hp[2] = {h0, h1};
                    *(uint32_t*)&g_fth[(size_t)rr * N + c0] = *(uint32_t*)hp;
                }
                if (split_off >= 0) {
                    __half l0 = __float2half_rn(v0 - __half2float(h0));
                    __half l1 = __float2half_rn(v1 - __half2float(h1));
                    __half hp[2] = {h0, h1}, lp[2] = {l0, l1};
                    *(uint32_t*)&g_ah[split_off + (size_t)rr * N + c0] = *(uint32_t*)hp;
                    *(uint32_t*)&g_al[split_off + (size_t)rr * N + c0] = *(uint32_t*)lp;
                }
            }
        }
    }
    // fused el/er (H=8 layers: block col tile == one head)
    if (attn_al) {
        int h = bn0 >> 6;
        float pl[2][2] = {{0.f, 0.f}, {0.f, 0.f}};
        float pr[2][2] = {{0.f, 0.f}, {0.f, 0.f}};
        #pragma unroll
        for (int mf = 0; mf < 2; mf++)
            #pragma unroll
            for (int nf = 0; nf < 4; nf++)
                #pragma unroll
                for (int s = 0; s < 2; s++) {
                    int d = wn * 32 + nf * 8 + (lane & 3) * 2 + s;
                    float wl = attn_al[h * 64 + d];
                    float wr = attn_ar[h * 64 + d];
                    pl[mf][0] = fmaf(acc[mf][nf][s],     wl, pl[mf][0]);
                    pl[mf][1] = fmaf(acc[mf][nf][2 + s], wl, pl[mf][1]);
                    pr[mf][0] = fmaf(acc[mf][nf][s],     wr, pr[mf][0]);
                    pr[mf][1] = fmaf(acc[mf][nf][2 + s], wr, pr[mf][1]);
                }
        #pragma unroll
        for (int mf = 0; mf < 2; mf++)
            #pragma unroll
            for (int hf = 0; hf < 2; hf++) {
                float vl = pl[mf][hf], vr = pr[mf][hf];
                vl += __shfl_xor_sync(0xffffffffu, vl, 1);
                vl += __shfl_xor_sync(0xffffffffu, vl, 2);
                vr += __shfl_xor_sync(0xffffffffu, vr, 1);
                vr += __shfl_xor_sync(0xffffffffu, vr, 2);
                if ((lane & 3) == 0) {
                    int rl = wm * 32 + mf * 16 + hf * 8 + (lane >> 2);
                    sl[rl][wn] = vl;
                    sr[rl][wn] = vr;
                }
            }
        __syncthreads();
        if (tid < 128) {
            int row = bm0 + tid;
            if (row < M) {
                g_el[row * 8 + h] = sl[tid][0] + sl[tid][1];
                g_er[row * 8 + h] = sr[tid][0] + sr[tid][1];
            }
        }
    }
}

// ---------------- fused edge-logit + segment softmax (no max pass; shift-invariant) ----------------
template <int H>
__global__ void k_attn(const int* __restrict__ src)
{
    int t = blockIdx.x * blockDim.x + threadIdx.x;
    if (t >= NNODES * H) return;
    int n = t / H, h = t % H;
    int s0 = g_rowoff[n], s1 = g_rowoff[n + 1];
    float ern = g_er[n * H + h];
    float sum = 0.f;
    for (int p = s0; p < s1; p++) {
        int eid = g_eid[p];
        float x = g_el[src[eid] * H + h] + ern;
        x = (x >= 0.f) ? x : 0.2f * x;
        float ex = expf(x);
        g_e[(size_t)eid * H + h] = ex;
        sum += ex;
    }
    float inv = 1.f / (sum + 1e-16f);
    for (int p = s0; p < s1; p++) g_e[(size_t)g_eid[p] * H + h] *= inv;
}

// ---------------- aggregation, F=512, H=8: fp16-hi gather from g_fth ----------------
__global__ __launch_bounds__(128) void k_agg512(
    const int* __restrict__ src,
    const float* __restrict__ bias, int use_resid, int write_split,
    float* __restrict__ out_ext)
{
    float* out = out_ext ? out_ext : g_h1;
    int n = blockIdx.x;
    int t = threadIdx.x;
    int f = t * 4;
    int h = f >> 6;
    float4 acc = *(const float4*)&bias[f];
    if (use_resid) {
        float4 r = *(const float4*)&g_h1[(size_t)n * 512 + f];
        acc.x += r.x; acc.y += r.y; acc.z += r.z; acc.w += r.w;
    }
    int s0 = g_rowoff[n], s1 = g_rowoff[n + 1];
    for (int p = s0; p < s1; p++) {
        int eid = g_eid[p];
        float w = g_e[(size_t)eid * 8 + h];
        int s = src[eid];
        uint2 hv = *(const uint2*)&g_fth[(size_t)s * 512 + f];
        float2 f0 = __half22float2(*(__half2*)&hv.x);
        float2 f1 = __half22float2(*(__half2*)&hv.y);
        acc.x = fmaf(w, f0.x, acc.x);
        acc.y = fmaf(w, f0.y, acc.y);
        acc.z = fmaf(w, f1.x, acc.z);
        acc.w = fmaf(w, f1.y, acc.w);
    }
    acc.x = (acc.x > 0.f) ? acc.x : expm1f(acc.x);
    acc.y = (acc.y > 0.f) ? acc.y : expm1f(acc.y);
    acc.z = (acc.z > 0.f) ? acc.z : expm1f(acc.z);
    acc.w = (acc.w > 0.f) ? acc.w : expm1f(acc.w);
    *(float4*)&out[(size_t)n * 512 + f] = acc;
    if (write_split) {
        float vv[4] = {acc.x, acc.y, acc.z, acc.w};
        __half hs[4], ls[4];
        #pragma unroll
        for (int j = 0; j < 4; j++) {
            hs[j] = __float2half_rn(vv[j]);
            ls[j] = __float2half_rn(vv[j] - __half2float(hs[j]));
        }
        *(uint2*)&g_ah[(size_t)n * 512 + f] = *(uint2*)hs;
        *(uint2*)&g_al[(size_t)n * 512 + f] = *(uint2*)ls;
    }
}

// ---------------- layer-2 projections (tiled, smem weight reuse) ----------------
__global__ __launch_bounds__(128) void k_l2proj2(
    const float* __restrict__ h2, const float* __restrict__ W2,
    const float* __restrict__ resW2, const float* __restrict__ al2,
    const float* __restrict__ ar2)
{
    __shared__ float sW[64 * 16];
    __shared__ float sR[64 * 16];
    int n = blockIdx.x * 128 + threadIdx.x;
    int nc = (n < NNODES) ? n : (NNODES - 1);
    const float* hr = h2 + (size_t)nc * 512;

    float a1[16], a2[16];
    #pragma unroll
    for (int c = 0; c < 16; c++) { a1[c] = 0.f; a2[c] = 0.f; }

    for (int k0 = 0; k0 < 512; k0 += 64) {
        __syncthreads();
        #pragma unroll
        for (int i = 0; i < 8; i++) {
            int idx = threadIdx.x + i * 128;
            sW[idx] = W2[k0 * 16 + idx];
            sR[idx] = resW2[k0 * 16 + idx];
        }
        __syncthreads();
        #pragma unroll
        for (int kk = 0; kk < 64; kk += 4) {
            float4 hv4 = *(const float4*)&hr[k0 + kk];
            float hv[4] = {hv4.x, hv4.y, hv4.z, hv4.w};
            #pragma unroll
            for (int q = 0; q < 4; q++) {
                float hq = hv[q];
                const float4* w4 = (const float4*)&sW[(kk + q) * 16];
                const float4* r4 = (const float4*)&sR[(kk + q) * 16];
                #pragma unroll
                for (int v = 0; v < 4; v++) {
                    float4 wv = w4[v], rv = r4[v];
                    a1[v * 4 + 0] = fmaf(hq, wv.x, a1[v * 4 + 0]);
                    a1[v * 4 + 1] = fmaf(hq, wv.y, a1[v * 4 + 1]);
                    a1[v * 4 + 2] = fmaf(hq, wv.z, a1[v * 4 + 2]);
                    a1[v * 4 + 3] = fmaf(hq, wv.w, a1[v * 4 + 3]);
                    a2[v * 4 + 0] = fmaf(hq, rv.x, a2[v * 4 + 0]);
                    a2[v * 4 + 1] = fmaf(hq, rv.y, a2[v * 4 + 1]);
                    a2[v * 4 + 2] = fmaf(hq, rv.z, a2[v * 4 + 2]);
                    a2[v * 4 + 3] = fmaf(hq, rv.w, a2[v * 4 + 3]);
                }
            }
        }
    }
    if (n < NNODES) {
        float el = 0.f, er = 0.f;
        #pragma unroll
        for (int c = 0; c < 16; c++) {
            el = fmaf(a1[c], al2[c], el);
            er = fmaf(a1[c], ar2[c], er);
        }
        g_el[n] = el;
        g_er[n] = er;
        #pragma unroll
        for (int v = 0; v < 4; v++) {
            *(float4*)&g_ft2[n * 16 + v * 4]  = make_float4(a1[v*4], a1[v*4+1], a1[v*4+2], a1[v*4+3]);
            *(float4*)&g_res2[n * 16 + v * 4] = make_float4(a2[v*4], a2[v*4+1], a2[v*4+2], a2[v*4+3]);
        }
    }
}

// ---------------- aggregation F=16, H=1 ----------------
__global__ __launch_bounds__(32) void k_agg16(
    const int* __restrict__ src, const float* __restrict__ b2,
    float* __restrict__ logits)
{
    int n = blockIdx.x;
    int lane = threadIdx.x;
    if (lane >= 16) return;
    float acc = g_res2[n * 16 + lane] + b2[lane];
    int s0 = g_rowoff[n], s1 = g_rowoff[n + 1];
    for (int p = s0; p < s1; p++) {
        int eid = g_eid[p];
        float w = g_e[eid];
        int s = src[eid];
        acc = fmaf(w, g_ft2[s * 16 + lane], acc);
    }
    logits[n * 16 + lane] = acc;
}

// ---------------- launch (ONLY kernel launches — graph-capturable) ----------------
extern "C" void kernel_launch(void* const* d_in, const int* in_sizes, int n_in,
                              void* d_out, int out_size)
{
    const float* x0    = (const float*)d_in[0];
    const float* x1    = (const float*)d_in[1];
    const int*   src   = (const int*)d_in[2];
    const int*   dst   = (const int*)d_in[3];
    const float* fc0_W = (const float*)d_in[4];
    const float* fc0_b = (const float*)d_in[5];
    const float* fc1_W = (const float*)d_in[6];
    const float* fc1_b = (const float*)d_in[7];
    const float* W0  = (const float*)d_in[8];
    const float* al0 = (const float*)d_in[9];
    const float* ar0 = (const float*)d_in[10];
    const float* b0  = (const float*)d_in[11];
    const float* W1  = (const float*)d_in[12];
    const float* al1 = (const float*)d_in[13];
    const float* ar1 = (const float*)d_in[14];
    const float* b1  = (const float*)d_in[15];
    const float* W2  = (const float*)d_in[16];
    const float* al2 = (const float*)d_in[17];
    const float* ar2 = (const float*)d_in[18];
    const float* b2  = (const float*)d_in[19];
    const float* resW2 = (const float*)d_in[20];

    float* out    = (float*)d_out;
    float* logits = out;                         // [50000,16]
    float* enc    = out + (size_t)NNODES * 16;   // [50000,512]

    const int FC0_BT = 0, FC1_BT = 16384, W0_BT = 32768, W1_BT = 65536;
    const int NSCAN = (NNODES + 1023) / 1024;    // 49

    // launch order arranged so launch #5 (ncu -s 5) is a gemm_f16 instance.
    k_prep<<<(NNODES + 327680 + 255) / 256, 256>>>(fc0_W, fc1_W, W0, W1);          // 0
    k_split_x<<<(NNODES * 256 / 4 + 255) / 256, 256>>>(x0, x1);                     // 1
    k_count<<<(NEDGES + 255) / 256, 256>>>(dst);                                    // 2
    k_scanA<<<NSCAN, 1024>>>();                                                     // 3
    k_scanB<<<1, 64>>>();                                                           // 4
    {
        dim3 g(1, (NHALF + 127) / 128);
        // fc0: split-only output (L0 input), launch #5 for profiling
        gemm_f16<<<g, 256>>>(0, nullptr, 0, FC0_BT, NHALF, 64, 256, fc0_b,
                             nullptr, nullptr, (long long)L0SPLIT);                 // 5
    }
    k_scanC<<<NSCAN, 1024>>>();                                                     // 6
    k_scatter<<<(NEDGES + 255) / 256, 256>>>(dst);                                  // 7
    k_sortseg<<<(NNODES + 255) / 256, 256>>>();                                     // 8
    {
        dim3 g(1, (NHALF + 127) / 128);
        gemm_f16<<<g, 256>>>(NHALF * 256, nullptr, 0, FC1_BT, NHALF, 64, 256, fc1_b,
                             nullptr, nullptr, (long long)L0SPLIT + NHALF * 64);    // 9
    }

    // ---- layer 0: 64 -> 8x64 (el/er fused, fp16 feature out) ----
    {
        dim3 g(8, (NNODES + 127) / 128);
        gemm_f16<<<g, 256>>>(L0SPLIT, nullptr, 2, W0_BT, NNODES, 512, 64, nullptr,
                             al0, ar0, -1);
    }
    k_attn<8><<<(NNODES * 8 + 255) / 256, 256>>>(src);
    k_agg512<<<NNODES, 128>>>(src, b0, 0, 1, nullptr);   // -> g_h1 + split for L1 @0

    // ---- layer 1: 512 -> 8x64 (el/er fused, fp16 feature out) ----
    {
        dim3 g(8, (NNODES + 127) / 128);
        gemm_f16<<<g, 256>>>(0, nullptr, 2, W1_BT, NNODES, 512, 512, nullptr,
                             al1, ar1, -1);
    }
    k_attn<8><<<(NNODES * 8 + 255) / 256, 256>>>(src);
    k_agg512<<<NNODES, 128>>>(src, b1, 1, 0, enc);       // resid=g_h1 -> enc

    // ---- output layer: 512 -> 1x16, linear residual ----
    k_l2proj2<<<(NNODES + 127) / 128, 128>>>(enc, W2, resW2, al2, ar2);
    k_attn<1><<<(NNODES + 255) / 256, 256>>>(src);
    k_agg16<<<NNODES, 32>>>(src, b2, logits);
}

// round 15
// speedup vs baseline: 2.5582x; 1.1098x over previous
#include <cuda_runtime.h>
#include <cuda_fp16.h>
#include <math.h>
#include <stdint.h>

#define NNODES 50000
#define NHALF  25000
#define NEDGES 400000
#define L0SPLIT 12800000   // fc-output split region in g_ah/g_al (disjoint from x0/x1 splits)

// ---------------- scratch (device globals; no allocation allowed) ----------------
__device__ float g_h1[NNODES * 512];
__device__ float g_el[NNODES * 8];
__device__ float g_er[NNODES * 8];
__device__ float g_ft2[NNODES * 16];
__device__ float g_res2[NNODES * 16];
__device__ int   g_deg[NNODES];
__device__ int   g_cur[NNODES];
__device__ int   g_rowoff[NNODES + 1];
__device__ int   g_eid[NEDGES];
__device__ int   g_bsum[64];
// fp16 operands
__device__ __half g_ah[NNODES * 512];    // A hi (x splits, L0 input split, L1 input split)
__device__ __half g_al[NNODES * 512];    // A lo
__device__ __half g_bth[327680];         // weights [N,K]: fc0@0, fc1@16384, W0@32768, W1@65536
__device__ __half g_fth[NNODES * 512];   // fp16-hi feature tensor (GEMM out, gathered by agg)

// ---------------- CSR build ----------------
__global__ void k_count(const int* __restrict__ dst) {
    int i = blockIdx.x * blockDim.x + threadIdx.x;
    if (i < NEDGES) {
        int d = dst[i];
        if (d >= 0 && d < NNODES) atomicAdd(&g_deg[d], 1);
    }
}

__global__ void k_scanA() {
    __shared__ int ws[32];
    int t = threadIdx.x;
    int i = blockIdx.x * 1024 + t;
    int v = (i < NNODES) ? g_deg[i] : 0;
    int x = v;
    #pragma unroll
    for (int o = 1; o < 32; o <<= 1) {
        int y = __shfl_up_sync(0xffffffffu, x, o);
        if ((t & 31) >= o) x += y;
    }
    if ((t & 31) == 31) ws[t >> 5] = x;
    __syncthreads();
    if (t < 32) {
        int w = ws[t];
        #pragma unroll
        for (int o = 1; o < 32; o <<= 1) {
            int y = __shfl_up_sync(0xffffffffu, w, o);
            if (t >= o) w += y;
        }
        ws[t] = w;
    }
    __syncthreads();
    int incl = x + ((t >= 32) ? ws[(t >> 5) - 1] : 0);
    if (i < NNODES) g_rowoff[i] = incl - v;
    if (t == 1023) g_bsum[blockIdx.x] = incl;
}

__global__ void k_scanB() {
    __shared__ int s[64];
    int t = threadIdx.x;
    int nb = (NNODES + 1023) / 1024;
    int v = (t < nb) ? g_bsum[t] : 0;
    s[t] = v;
    __syncthreads();
    #pragma unroll
    for (int o = 1; o < 64; o <<= 1) {
        int y = (t >= o) ? s[t - o] : 0;
        __syncthreads();
        s[t] += y;
        __syncthreads();
    }
    if (t < nb) g_bsum[t] = s[t] - v;
    if (t == 63) g_rowoff[NNODES] = s[63];
}

__global__ void k_scanC() {
    int i = blockIdx.x * 1024 + threadIdx.x;
    if (i < NNODES) g_rowoff[i] += g_bsum[blockIdx.x];
}

__global__ void k_scatter(const int* __restrict__ dst) {
    int i = blockIdx.x * blockDim.x + threadIdx.x;
    if (i < NEDGES) {
        int d = dst[i];
        if (d >= 0 && d < NNODES) {
            int p = g_rowoff[d] + atomicAdd(&g_cur[d], 1);
            g_eid[p] = i;
        }
    }
}

__global__ void k_sortseg() {
    int n = blockIdx.x * blockDim.x + threadIdx.x;
    if (n >= NNODES) return;
    int s = g_rowoff[n], e = g_rowoff[n + 1];
    for (int i = s + 1; i < e; i++) {
        int key = g_eid[i];
        int j = i - 1;
        while (j >= s && g_eid[j] > key) { g_eid[j + 1] = g_eid[j]; j--; }
        g_eid[j + 1] = key;
    }
}

// ---------------- merged prep: zero counts + all weight converts ----------------
__global__ void k_prep(const float* __restrict__ fc0_W, const float* __restrict__ fc1_W,
                       const float* __restrict__ W0, const float* __restrict__ W1)
{
    int i = blockIdx.x * blockDim.x + threadIdx.x;
    if (i < NNODES) { g_deg[i] = 0; g_cur[i] = 0; }
    int idx = i - NNODES;
    const float* W;
    int K, N, b_off;
    if (idx < 0) return;
    if (idx < 16384)        { W = fc0_W; K = 256; N = 64;  b_off = 0;     }
    else if (idx < 32768)   { W = fc1_W; K = 256; N = 64;  b_off = 16384; idx -= 16384; }
    else if (idx < 65536)   { W = W0;    K = 64;  N = 512; b_off = 32768; idx -= 32768; }
    else if (idx < 327680)  { W = W1;    K = 512; N = 512; b_off = 65536; idx -= 65536; }
    else return;
    int k = idx / N, n = idx % N;
    g_bth[b_off + n * K + k] = __float2half_rn(W[k * N + n]);
}

// ---------------- fp16 split of both inputs (x0 then x1) ----------------
__global__ void k_split_x(const float* __restrict__ x0, const float* __restrict__ x1)
{
    int i = (blockIdx.x * blockDim.x + threadIdx.x) * 4;
    if (i >= NNODES * 256) return;
    const float* X = (i < NHALF * 256) ? (x0 + i) : (x1 + (i - NHALF * 256));
    float4 v = *(const float4*)X;
    float xs[4] = {v.x, v.y, v.z, v.w};
    __half hs[4], ls[4];
    #pragma unroll
    for (int j = 0; j < 4; j++) {
        hs[j] = __float2half_rn(xs[j]);
        ls[j] = __float2half_rn(xs[j] - __half2float(hs[j]));
    }
    *(uint2*)&g_ah[i] = *(uint2*)hs;
    *(uint2*)&g_al[i] = *(uint2*)ls;
}

// ---------------- fp16 2-term tensor-core GEMM, BK=64, reg-prefetch pipeline ----------------
// store_mode: bit0 = store fp32 C (Cext), bit1 = store fp16-hi to g_fth (N must be 512)
__device__ __forceinline__ void mma_f16(float* c, const uint32_t* a, const uint32_t* b) {
    asm("mma.sync.aligned.m16n8k16.row.col.f32.f16.f16.f32 "
        "{%0,%1,%2,%3}, {%4,%5,%6,%7}, {%8,%9}, {%0,%1,%2,%3};"
        : "+f"(c[0]), "+f"(c[1]), "+f"(c[2]), "+f"(c[3])
        : "r"(a[0]), "r"(a[1]), "r"(a[2]), "r"(a[3]), "r"(b[0]), "r"(b[1]));
}

__global__ __launch_bounds__(256) void gemm_f16(
    int a_off, float* __restrict__ Cext, int store_mode,
    int b_off, int M, int N, int K,
    const float* __restrict__ bias,
    const float* __restrict__ attn_al, const float* __restrict__ attn_ar,
    long long split_off)
{
    __shared__ uint32_t As[2][4096];
    __shared__ uint32_t Bs[2048];
    __shared__ float sl[128][2], sr[128][2];

    const __half* Ah = g_ah + a_off;
    const __half* Al = g_al + a_off;
    const __half* Bth = g_bth + b_off;

    int tid  = threadIdx.x;
    int lane = tid & 31;
    int w    = tid >> 5;
    int wm   = w & 3;
    int wn   = w >> 2;
    int bm0  = blockIdx.y * 128;
    int bn0  = blockIdx.x * 64;

    float acc[2][4][4];
    #pragma unroll
    for (int mf = 0; mf < 2; mf++)
        #pragma unroll
        for (int nf = 0; nf < 4; nf++)
            #pragma unroll
            for (int i = 0; i < 4; i++) acc[mf][nf][i] = 0.f;

    int a_r[4], a_j[4];
    #pragma unroll
    for (int i = 0; i < 4; i++) {
        int idx = tid + i * 256;
        a_r[i] = idx >> 3;
        a_j[i] = idx & 7;
    }
    int b_r[2], b_j[2];
    #pragma unroll
    for (int i = 0; i < 2; i++) {
        int idx = tid + i * 256;
        b_r[i] = idx >> 3;
        b_j[i] = idx & 7;
    }

    uint4 a_hi[4], a_lo[4], b_hi[2];

    #pragma unroll
    for (int i = 0; i < 4; i++) {
        int gr = bm0 + a_r[i];
        if (gr < M) {
            size_t off = (size_t)gr * K + a_j[i] * 8;
            a_hi[i] = *(const uint4*)&Ah[off];
            a_lo[i] = *(const uint4*)&Al[off];
        } else {
            a_hi[i] = make_uint4(0, 0, 0, 0);
            a_lo[i] = make_uint4(0, 0, 0, 0);
        }
    }
    #pragma unroll
    for (int i = 0; i < 2; i++) {
        size_t off = (size_t)(bn0 + b_r[i]) * K + b_j[i] * 8;
        b_hi[i] = *(const uint4*)&Bth[off];
    }

    for (int k0 = 0; k0 < K; k0 += 64) {
        __syncthreads();
        #pragma unroll
        for (int i = 0; i < 4; i++) {
            int r = a_r[i], j = a_j[i];
            int ks  = j >> 1;
            int reg = ((r >> 3) & 1) | ((j & 1) << 1);
            int base = (((r >> 4) * 4 + ks) * 32 + (r & 7) * 4) * 4 + reg;
            uint32_t vh[4] = {a_hi[i].x, a_hi[i].y, a_hi[i].z, a_hi[i].w};
            uint32_t vl[4] = {a_lo[i].x, a_lo[i].y, a_lo[i].z, a_lo[i].w};
            #pragma unroll
            for (int p = 0; p < 4; p++) {
                As[0][base + p * 4] = vh[p];
                As[1][base + p * 4] = vl[p];
            }
        }
        #pragma unroll
        for (int i = 0; i < 2; i++) {
            int r = b_r[i], j = b_j[i];
            int ks  = j >> 1;
            int reg = j & 1;
            int base = (((r >> 3) * 4 + ks) * 32 + (r & 7) * 4) * 2 + reg;
            uint32_t vh[4] = {b_hi[i].x, b_hi[i].y, b_hi[i].z, b_hi[i].w};
            #pragma unroll
            for (int p = 0; p < 4; p++)
                Bs[base + p * 2] = vh[p];
        }
        __syncthreads();
        int kn = k0 + 64;
        if (kn < K) {
            #pragma unroll
            for (int i = 0; i < 4; i++) {
                int gr = bm0 + a_r[i];
                if (gr < M) {
                    size_t off = (size_t)gr * K + kn + a_j[i] * 8;
                    a_hi[i] = *(const uint4*)&Ah[off];
                    a_lo[i] = *(const uint4*)&Al[off];
                } else {
                    a_hi[i] = make_uint4(0, 0, 0, 0);
                    a_lo[i] = make_uint4(0, 0, 0, 0);
                }
            }
            #pragma unroll
            for (int i = 0; i < 2; i++) {
                size_t off = (size_t)(bn0 + b_r[i]) * K + kn + b_j[i] * 8;
                b_hi[i] = *(const uint4*)&Bth[off];
            }
        }
        #pragma unroll
        for (int ks = 0; ks < 4; ks++) {
            uint32_t ah[2][4], al2_[2][4], bh[4][2];
            #pragma unroll
            for (int mf = 0; mf < 2; mf++) {
                int off = (((wm * 2 + mf) * 4 + ks) * 32 + lane) * 4;
                uint4 h = *(const uint4*)&As[0][off];
                uint4 l = *(const uint4*)&As[1][off];
                ah[mf][0] = h.x; ah[mf][1] = h.y; ah[mf][2] = h.z; ah[mf][3] = h.w;
                al2_[mf][0] = l.x; al2_[mf][1] = l.y; al2_[mf][2] = l.z; al2_[mf][3] = l.w;
            }
            #pragma unroll
            for (int nf = 0; nf < 4; nf++) {
                int off = (((wn * 4 + nf) * 4 + ks) * 32 + lane) * 2;
                uint2 h = *(const uint2*)&Bs[off];
                bh[nf][0] = h.x; bh[nf][1] = h.y;
            }
            #pragma unroll
            for (int mf = 0; mf < 2; mf++)
                #pragma unroll
                for (int nf = 0; nf < 4; nf++) {
                    mma_f16(acc[mf][nf], ah[mf], bh[nf]);
                    mma_f16(acc[mf][nf], al2_[mf], bh[nf]);
                }
        }
    }
    // epilogue
    #pragma unroll
    for (int mf = 0; mf < 2; mf++) {
        int r0 = bm0 + wm * 32 + mf * 16 + (lane >> 2);
        #pragma unroll
        for (int nf = 0; nf < 4; nf++) {
            int c0 = bn0 + wn * 32 + nf * 8 + (lane & 3) * 2;
            float bz0 = bias ? bias[c0] : 0.f;
            float bz1 = bias ? bias[c0 + 1] : 0.f;
            #pragma unroll
            for (int half = 0; half < 2; half++) {
                int rr = r0 + half * 8;
                if (rr >= M) continue;
                float v0 = acc[mf][nf][half * 2]     + bz0;
                float v1 = acc[mf][nf][half * 2 + 1] + bz1;
                if (store_mode & 1) {
                    Cext[(size_t)rr * N + c0]     = v0;
                    Cext[(size_t)rr * N + c0 + 1] = v1;
                }
                __half h0 = __float2half_rn(v0);
                __half h1 = __float2half_rn(v1);
                if (store_mode & 2) {
                    __half hp[2] = {h0, h1};
                    *(uint32_t*)&g_fth[(size_t)rr * N + c0] = *(uint32_t*)hp;
                }
                if (split_off >= 0) {
                    __half l0 = __float2half_rn(v0 - __half2float(h0));
                    __half l1 = __float2half_rn(v1 - __half2float(h1));
                    __half hp[2] = {h0, h1}, lp[2] = {l0, l1};
                    *(uint32_t*)&g_ah[split_off + (size_t)rr * N + c0] = *(uint32_t*)hp;
                    *(uint32_t*)&g_al[split_off + (size_t)rr * N + c0] = *(uint32_t*)lp;
                }
            }
        }
    }
    // fused el/er (H=8 layers: block col tile == one head)
    if (attn_al) {
        int h = bn0 >> 6;
        float pl[2][2] = {{0.f, 0.f}, {0.f, 0.f}};
        float pr[2][2] = {{0.f, 0.f}, {0.f, 0.f}};
        #pragma unroll
        for (int mf = 0; mf < 2; mf++)
            #pragma unroll
            for (int nf = 0; nf < 4; nf++)
                #pragma unroll
                for (int s = 0; s < 2; s++) {
                    int d = wn * 32 + nf * 8 + (lane & 3) * 2 + s;
                    float wl = attn_al[h * 64 + d];
                    float wr = attn_ar[h * 64 + d];
                    pl[mf][0] = fmaf(acc[mf][nf][s],     wl, pl[mf][0]);
                    pl[mf][1] = fmaf(acc[mf][nf][2 + s], wl, pl[mf][1]);
                    pr[mf][0] = fmaf(acc[mf][nf][s],     wr, pr[mf][0]);
                    pr[mf][1] = fmaf(acc[mf][nf][2 + s], wr, pr[mf][1]);
                }
        #pragma unroll
        for (int mf = 0; mf < 2; mf++)
            #pragma unroll
            for (int hf = 0; hf < 2; hf++) {
                float vl = pl[mf][hf], vr = pr[mf][hf];
                vl += __shfl_xor_sync(0xffffffffu, vl, 1);
                vl += __shfl_xor_sync(0xffffffffu, vl, 2);
                vr += __shfl_xor_sync(0xffffffffu, vr, 1);
                vr += __shfl_xor_sync(0xffffffffu, vr, 2);
                if ((lane & 3) == 0) {
                    int rl = wm * 32 + mf * 16 + hf * 8 + (lane >> 2);
                    sl[rl][wn] = vl;
                    sr[rl][wn] = vr;
                }
            }
        __syncthreads();
        if (tid < 128) {
            int row = bm0 + tid;
            if (row < M) {
                g_el[row * 8 + h] = sl[tid][0] + sl[tid][1];
                g_er[row * 8 + h] = sr[tid][0] + sr[tid][1];
            }
        }
    }
}

// ---------------- fused softmax + aggregation, F=512, H=8 ----------------
// Unnormalized exp accumulated; divide by per-head sum at the end.
__global__ __launch_bounds__(128) void k_agg512(
    const int* __restrict__ src,
    const float* __restrict__ bias, int use_resid, int write_split,
    float* __restrict__ out_ext)
{
    __shared__ float s_ex[16][8];
    __shared__ int   s_src[16];
    __shared__ float s_er[8];
    float* out = out_ext ? out_ext : g_h1;
    int n = blockIdx.x;
    int t = threadIdx.x;
    int f = t * 4;
    int h = f >> 6;
    if (t < 8) s_er[t] = g_er[n * 8 + t];
    int s0 = g_rowoff[n], s1 = g_rowoff[n + 1];
    float4 acc = make_float4(0.f, 0.f, 0.f, 0.f);
    float sumh = 0.f;
    __syncthreads();
    for (int base = s0; base < s1; base += 16) {
        int cnt = min(16, s1 - base);
        if (t < cnt * 8) {
            int e_ = t >> 3, hh = t & 7;
            int eid = g_eid[base + e_];
            int s = src[eid];
            if (hh == 0) s_src[e_] = s;
            float x = g_el[s * 8 + hh] + s_er[hh];
            x = (x >= 0.f) ? x : 0.2f * x;
            s_ex[e_][hh] = expf(x);
        }
        __syncthreads();
        for (int e = 0; e < cnt; e++) {
            float wgt = s_ex[e][h];
            int s = s_src[e];
            sumh += wgt;
            uint2 hv = *(const uint2*)&g_fth[(size_t)s * 512 + f];
            float2 f0 = __half22float2(*(__half2*)&hv.x);
            float2 f1 = __half22float2(*(__half2*)&hv.y);
            acc.x = fmaf(wgt, f0.x, acc.x);
            acc.y = fmaf(wgt, f0.y, acc.y);
            acc.z = fmaf(wgt, f1.x, acc.z);
            acc.w = fmaf(wgt, f1.y, acc.w);
        }
        __syncthreads();
    }
    float inv = 1.f / (sumh + 1e-16f);
    float4 bz = *(const float4*)&bias[f];
    acc.x = acc.x * inv + bz.x;
    acc.y = acc.y * inv + bz.y;
    acc.z = acc.z * inv + bz.z;
    acc.w = acc.w * inv + bz.w;
    if (use_resid) {
        float4 r = *(const float4*)&g_h1[(size_t)n * 512 + f];
        acc.x += r.x; acc.y += r.y; acc.z += r.z; acc.w += r.w;
    }
    acc.x = (acc.x > 0.f) ? acc.x : expm1f(acc.x);
    acc.y = (acc.y > 0.f) ? acc.y : expm1f(acc.y);
    acc.z = (acc.z > 0.f) ? acc.z : expm1f(acc.z);
    acc.w = (acc.w > 0.f) ? acc.w : expm1f(acc.w);
    *(float4*)&out[(size_t)n * 512 + f] = acc;
    if (write_split) {
        float vv[4] = {acc.x, acc.y, acc.z, acc.w};
        __half hs[4], ls[4];
        #pragma unroll
        for (int j = 0; j < 4; j++) {
            hs[j] = __float2half_rn(vv[j]);
            ls[j] = __float2half_rn(vv[j] - __half2float(hs[j]));
        }
        *(uint2*)&g_ah[(size_t)n * 512 + f] = *(uint2*)hs;
        *(uint2*)&g_al[(size_t)n * 512 + f] = *(uint2*)ls;
    }
}

// ---------------- layer-2 projections (tiled, smem weight reuse) ----------------
__global__ __launch_bounds__(128) void k_l2proj2(
    const float* __restrict__ h2, const float* __restrict__ W2,
    const float* __restrict__ resW2, const float* __restrict__ al2,
    const float* __restrict__ ar2)
{
    __shared__ float sW[64 * 16];
    __shared__ float sR[64 * 16];
    int n = blockIdx.x * 128 + threadIdx.x;
    int nc = (n < NNODES) ? n : (NNODES - 1);
    const float* hr = h2 + (size_t)nc * 512;

    float a1[16], a2[16];
    #pragma unroll
    for (int c = 0; c < 16; c++) { a1[c] = 0.f; a2[c] = 0.f; }

    for (int k0 = 0; k0 < 512; k0 += 64) {
        __syncthreads();
        #pragma unroll
        for (int i = 0; i < 8; i++) {
            int idx = threadIdx.x + i * 128;
            sW[idx] = W2[k0 * 16 + idx];
            sR[idx] = resW2[k0 * 16 + idx];
        }
        __syncthreads();
        #pragma unroll
        for (int kk = 0; kk < 64; kk += 4) {
            float4 hv4 = *(const float4*)&hr[k0 + kk];
            float hv[4] = {hv4.x, hv4.y, hv4.z, hv4.w};
            #pragma unroll
            for (int q = 0; q < 4; q++) {
                float hq = hv[q];
                const float4* w4 = (const float4*)&sW[(kk + q) * 16];
                const float4* r4 = (const float4*)&sR[(kk + q) * 16];
                #pragma unroll
                for (int v = 0; v < 4; v++) {
                    float4 wv = w4[v], rv = r4[v];
                    a1[v * 4 + 0] = fmaf(hq, wv.x, a1[v * 4 + 0]);
                    a1[v * 4 + 1] = fmaf(hq, wv.y, a1[v * 4 + 1]);
                    a1[v * 4 + 2] = fmaf(hq, wv.z, a1[v * 4 + 2]);
                    a1[v * 4 + 3] = fmaf(hq, wv.w, a1[v * 4 + 3]);
                    a2[v * 4 + 0] = fmaf(hq, rv.x, a2[v * 4 + 0]);
                    a2[v * 4 + 1] = fmaf(hq, rv.y, a2[v * 4 + 1]);
                    a2[v * 4 + 2] = fmaf(hq, rv.z, a2[v * 4 + 2]);
                    a2[v * 4 + 3] = fmaf(hq, rv.w, a2[v * 4 + 3]);
                }
            }
        }
    }
    if (n < NNODES) {
        float el = 0.f, er = 0.f;
        #pragma unroll
        for (int c = 0; c < 16; c++) {
            el = fmaf(a1[c], al2[c], el);
            er = fmaf(a1[c], ar2[c], er);
        }
        g_el[n] = el;
        g_er[n] = er;
        #pragma unroll
        for (int v = 0; v < 4; v++) {
            *(float4*)&g_ft2[n * 16 + v * 4]  = make_float4(a1[v*4], a1[v*4+1], a1[v*4+2], a1[v*4+3]);
            *(float4*)&g_res2[n * 16 + v * 4] = make_float4(a2[v*4], a2[v*4+1], a2[v*4+2], a2[v*4+3]);
        }
    }
}

// ---------------- fused softmax + aggregation F=16, H=1 ----------------
__global__ __launch_bounds__(32) void k_agg16(
    const int* __restrict__ src, const float* __restrict__ b2,
    float* __restrict__ logits)
{
    int n = blockIdx.x;
    int lane = threadIdx.x;
    int li = lane & 15;                      // lanes 16..31 mirror 0..15 (no OOB)
    float ern = g_er[n];
    int s0 = g_rowoff[n], s1 = g_rowoff[n + 1];
    float acc = 0.f, sum = 0.f;
    for (int base = s0; base < s1; base += 16) {
        int cnt = min(16, s1 - base);
        float ex = 0.f;
        int sv = 0;
        if (lane < cnt) {                    // only lanes 0..15 can satisfy this
            int eid = g_eid[base + lane];
            sv = src[eid];
            float x = g_el[sv] + ern;
            x = (x >= 0.f) ? x : 0.2f * x;
            ex = expf(x);
        }
        for (int e = 0; e < cnt; e++) {
            float wgt = __shfl_sync(0xffffffffu, ex, e);
            int s     = __shfl_sync(0xffffffffu, sv, e);
            sum += wgt;
            acc = fmaf(wgt, g_ft2[s * 16 + li], acc);
        }
    }
    if (lane < 16) {
        float inv = 1.f / (sum + 1e-16f);
        logits[n * 16 + lane] = g_res2[n * 16 + lane] + b2[lane] + acc * inv;
    }
}

// ---------------- launch (ONLY kernel launches — graph-capturable) ----------------
extern "C" void kernel_launch(void* const* d_in, const int* in_sizes, int n_in,
                              void* d_out, int out_size)
{
    const float* x0    = (const float*)d_in[0];
    const float* x1    = (const float*)d_in[1];
    const int*   src   = (const int*)d_in[2];
    const int*   dst   = (const int*)d_in[3];
    const float* fc0_W = (const float*)d_in[4];
    const float* fc0_b = (const float*)d_in[5];
    const float* fc1_W = (const float*)d_in[6];
    const float* fc1_b = (const float*)d_in[7];
    const float* W0  = (const float*)d_in[8];
    const float* al0 = (const float*)d_in[9];
    const float* ar0 = (const float*)d_in[10];
    const float* b0  = (const float*)d_in[11];
    const float* W1  = (const float*)d_in[12];
    const float* al1 = (const float*)d_in[13];
    const float* ar1 = (const float*)d_in[14];
    const float* b1  = (const float*)d_in[15];
    const float* W2  = (const float*)d_in[16];
    const float* al2 = (const float*)d_in[17];
    const float* ar2 = (const float*)d_in[18];
    const float* b2  = (const float*)d_in[19];
    const float* resW2 = (const float*)d_in[20];

    float* out    = (float*)d_out;
    float* logits = out;                         // [50000,16]
    float* enc    = out + (size_t)NNODES * 16;   // [50000,512]

    const int FC0_BT = 0, FC1_BT = 16384, W0_BT = 32768, W1_BT = 65536;
    const int NSCAN = (NNODES + 1023) / 1024;    // 49

    k_prep<<<(NNODES + 327680 + 255) / 256, 256>>>(fc0_W, fc1_W, W0, W1);
    k_split_x<<<(NNODES * 256 / 4 + 255) / 256, 256>>>(x0, x1);
    k_count<<<(NEDGES + 255) / 256, 256>>>(dst);
    k_scanA<<<NSCAN, 1024>>>();
    k_scanB<<<1, 64>>>();
    {
        dim3 g(1, (NHALF + 127) / 128);
        gemm_f16<<<g, 256>>>(0, nullptr, 0, FC0_BT, NHALF, 64, 256, fc0_b,
                             nullptr, nullptr, (long long)L0SPLIT);
    }
    k_scanC<<<NSCAN, 1024>>>();
    k_scatter<<<(NEDGES + 255) / 256, 256>>>(dst);
    k_sortseg<<<(NNODES + 255) / 256, 256>>>();
    {
        dim3 g(1, (NHALF + 127) / 128);
        gemm_f16<<<g, 256>>>(NHALF * 256, nullptr, 0, FC1_BT, NHALF, 64, 256, fc1_b,
                             nullptr, nullptr, (long long)L0SPLIT + NHALF * 64);
    }

    // ---- layer 0: 64 -> 8x64 (el/er fused, fp16 feature out) ----
    {
        dim3 g(8, (NNODES + 127) / 128);
        gemm_f16<<<g, 256>>>(L0SPLIT, nullptr, 2, W0_BT, NNODES, 512, 64, nullptr,
                             al0, ar0, -1);
    }
    k_agg512<<<NNODES, 128>>>(src, b0, 0, 1, nullptr);   // softmax+agg -> g_h1 + split @0

    // ---- layer 1: 512 -> 8x64 (el/er fused, fp16 feature out) ----
    {
        dim3 g(8, (NNODES + 127) / 128);
        gemm_f16<<<g, 256>>>(0, nullptr, 2, W1_BT, NNODES, 512, 512, nullptr,
                             al1, ar1, -1);
    }
    k_agg512<<<NNODES, 128>>>(src, b1, 1, 0, enc);       // softmax+agg, resid -> enc

    // ---- output layer: 512 -> 1x16, linear residual ----
    k_l2proj2<<<(NNODES + 127) / 128, 128>>>(enc, W2, resW2, al2, ar2);
    k_agg16<<<NNODES, 32>>>(src, b2, logits);
}

// round 16
// speedup vs baseline: 2.8211x; 1.1028x over previous
#include <cuda_runtime.h>
#include <cuda_fp16.h>
#include <math.h>
#include <stdint.h>

#define NNODES 50000
#define NHALF  25000
#define NEDGES 400000
#define L0SPLIT 12800000   // fc-output split region in g_ah/g_al (disjoint from x0/x1 splits)

// ---------------- scratch (device globals; no allocation allowed) ----------------
__device__ float g_h1[NNODES * 512];
__device__ float g_el[NNODES * 8];
__device__ float g_er[NNODES * 8];
__device__ float g_ft2[NNODES * 16];
__device__ float g_res2[NNODES * 16];
__device__ int   g_deg[NNODES];
__device__ int   g_cur[NNODES];
__device__ int   g_rowoff[NNODES + 1];
__device__ int   g_eid[NEDGES];
__device__ int   g_bsum[64];
// fp16 operands
__device__ __half g_ah[NNODES * 512];    // A hi (x splits, L0 input split, L1 input split)
__device__ __half g_al[NNODES * 512];    // A lo
__device__ __half g_bth[327680];         // weights [N,K]: fc0@0, fc1@16384, W0@32768, W1@65536
__device__ __half g_fth[NNODES * 512];   // fp16-hi feature tensor (GEMM out, gathered by agg)

// ---------------- CSR build ----------------
__global__ void k_count(const int* __restrict__ dst) {
    int i = blockIdx.x * blockDim.x + threadIdx.x;
    if (i < NEDGES) {
        int d = dst[i];
        if (d >= 0 && d < NNODES) atomicAdd(&g_deg[d], 1);
    }
}

__global__ void k_scanA() {
    __shared__ int ws[32];
    int t = threadIdx.x;
    int i = blockIdx.x * 1024 + t;
    int v = (i < NNODES) ? g_deg[i] : 0;
    int x = v;
    #pragma unroll
    for (int o = 1; o < 32; o <<= 1) {
        int y = __shfl_up_sync(0xffffffffu, x, o);
        if ((t & 31) >= o) x += y;
    }
    if ((t & 31) == 31) ws[t >> 5] = x;
    __syncthreads();
    if (t < 32) {
        int w = ws[t];
        #pragma unroll
        for (int o = 1; o < 32; o <<= 1) {
            int y = __shfl_up_sync(0xffffffffu, w, o);
            if (t >= o) w += y;
        }
        ws[t] = w;
    }
    __syncthreads();
    int incl = x + ((t >= 32) ? ws[(t >> 5) - 1] : 0);
    if (i < NNODES) g_rowoff[i] = incl - v;
    if (t == 1023) g_bsum[blockIdx.x] = incl;
}

__global__ void k_scanB() {
    __shared__ int s[64];
    int t = threadIdx.x;
    int nb = (NNODES + 1023) / 1024;
    int v = (t < nb) ? g_bsum[t] : 0;
    s[t] = v;
    __syncthreads();
    #pragma unroll
    for (int o = 1; o < 64; o <<= 1) {
        int y = (t >= o) ? s[t - o] : 0;
        __syncthreads();
        s[t] += y;
        __syncthreads();
    }
    if (t < nb) g_bsum[t] = s[t] - v;
    if (t == 63) g_rowoff[NNODES] = s[63];
}

__global__ void k_scanC() {
    int i = blockIdx.x * 1024 + threadIdx.x;
    if (i < NNODES) g_rowoff[i] += g_bsum[blockIdx.x];
}

__global__ void k_scatter(const int* __restrict__ dst) {
    int i = blockIdx.x * blockDim.x + threadIdx.x;
    if (i < NEDGES) {
        int d = dst[i];
        if (d >= 0 && d < NNODES) {
            int p = g_rowoff[d] + atomicAdd(&g_cur[d], 1);
            g_eid[p] = i;
        }
    }
}

__global__ void k_sortseg() {
    int n = blockIdx.x * blockDim.x + threadIdx.x;
    if (n >= NNODES) return;
    int s = g_rowoff[n], e = g_rowoff[n + 1];
    for (int i = s + 1; i < e; i++) {
        int key = g_eid[i];
        int j = i - 1;
        while (j >= s && g_eid[j] > key) { g_eid[j + 1] = g_eid[j]; j--; }
        g_eid[j + 1] = key;
    }
}

// ---------------- merged prep: zero counts + all weight converts ----------------
__global__ void k_prep(const float* __restrict__ fc0_W, const float* __restrict__ fc1_W,
                       const float* __restrict__ W0, const float* __restrict__ W1)
{
    int i = blockIdx.x * blockDim.x + threadIdx.x;
    if (i < NNODES) { g_deg[i] = 0; g_cur[i] = 0; }
    int idx = i - NNODES;
    const float* W;
    int K, N, b_off;
    if (idx < 0) return;
    if (idx < 16384)        { W = fc0_W; K = 256; N = 64;  b_off = 0;     }
    else if (idx < 32768)   { W = fc1_W; K = 256; N = 64;  b_off = 16384; idx -= 16384; }
    else if (idx < 65536)   { W = W0;    K = 64;  N = 512; b_off = 32768; idx -= 32768; }
    else if (idx < 327680)  { W = W1;    K = 512; N = 512; b_off = 65536; idx -= 65536; }
    else return;
    int k = idx / N, n = idx % N;
    g_bth[b_off + n * K + k] = __float2half_rn(W[k * N + n]);
}

// ---------------- fp16 split of both inputs (x0 then x1) ----------------
__global__ void k_split_x(const float* __restrict__ x0, const float* __restrict__ x1)
{
    int i = (blockIdx.x * blockDim.x + threadIdx.x) * 4;
    if (i >= NNODES * 256) return;
    const float* X = (i < NHALF * 256) ? (x0 + i) : (x1 + (i - NHALF * 256));
    float4 v = *(const float4*)X;
    float xs[4] = {v.x, v.y, v.z, v.w};
    __half hs[4], ls[4];
    #pragma unroll
    for (int j = 0; j < 4; j++) {
        hs[j] = __float2half_rn(xs[j]);
        ls[j] = __float2half_rn(xs[j] - __half2float(hs[j]));
    }
    *(uint2*)&g_ah[i] = *(uint2*)hs;
    *(uint2*)&g_al[i] = *(uint2*)ls;
}

__device__ __forceinline__ void mma_f16(float* c, const uint32_t* a, const uint32_t* b) {
    asm("mma.sync.aligned.m16n8k16.row.col.f32.f16.f16.f32 "
        "{%0,%1,%2,%3}, {%4,%5,%6,%7}, {%8,%9}, {%0,%1,%2,%3};"
        : "+f"(c[0]), "+f"(c[1]), "+f"(c[2]), "+f"(c[3])
        : "r"(a[0]), "r"(a[1]), "r"(a[2]), "r"(a[3]), "r"(b[0]), "r"(b[1]));
}

// ---------------- fc GEMM (256 thr, 128x64 tile) — N=64 path, split-only output ----------------
__global__ __launch_bounds__(256) void gemm_f16(
    int a_off, int b_off, int M, int N, int K,
    const float* __restrict__ bias, long long split_off)
{
    __shared__ uint32_t As[2][4096];
    __shared__ uint32_t Bs[2048];

    const __half* Ah = g_ah + a_off;
    const __half* Al = g_al + a_off;
    const __half* Bth = g_bth + b_off;

    int tid  = threadIdx.x;
    int lane = tid & 31;
    int w    = tid >> 5;
    int wm   = w & 3;
    int wn   = w >> 2;
    int bm0  = blockIdx.y * 128;
    int bn0  = blockIdx.x * 64;

    float acc[2][4][4];
    #pragma unroll
    for (int mf = 0; mf < 2; mf++)
        #pragma unroll
        for (int nf = 0; nf < 4; nf++)
            #pragma unroll
            for (int i = 0; i < 4; i++) acc[mf][nf][i] = 0.f;

    int a_r[4], a_j[4];
    #pragma unroll
    for (int i = 0; i < 4; i++) {
        int idx = tid + i * 256;
        a_r[i] = idx >> 3;
        a_j[i] = idx & 7;
    }
    int b_r[2], b_j[2];
    #pragma unroll
    for (int i = 0; i < 2; i++) {
        int idx = tid + i * 256;
        b_r[i] = idx >> 3;
        b_j[i] = idx & 7;
    }

    uint4 a_hi[4], a_lo[4], b_hi[2];
    #pragma unroll
    for (int i = 0; i < 4; i++) {
        int gr = bm0 + a_r[i];
        if (gr < M) {
            size_t off = (size_t)gr * K + a_j[i] * 8;
            a_hi[i] = *(const uint4*)&Ah[off];
            a_lo[i] = *(const uint4*)&Al[off];
        } else {
            a_hi[i] = make_uint4(0, 0, 0, 0);
            a_lo[i] = make_uint4(0, 0, 0, 0);
        }
    }
    #pragma unroll
    for (int i = 0; i < 2; i++) {
        size_t off = (size_t)(bn0 + b_r[i]) * K + b_j[i] * 8;
        b_hi[i] = *(const uint4*)&Bth[off];
    }

    for (int k0 = 0; k0 < K; k0 += 64) {
        __syncthreads();
        #pragma unroll
        for (int i = 0; i < 4; i++) {
            int r = a_r[i], j = a_j[i];
            int ks  = j >> 1;
            int reg = ((r >> 3) & 1) | ((j & 1) << 1);
            int base = (((r >> 4) * 4 + ks) * 32 + (r & 7) * 4) * 4 + reg;
            uint32_t vh[4] = {a_hi[i].x, a_hi[i].y, a_hi[i].z, a_hi[i].w};
            uint32_t vl[4] = {a_lo[i].x, a_lo[i].y, a_lo[i].z, a_lo[i].w};
            #pragma unroll
            for (int p = 0; p < 4; p++) {
                As[0][base + p * 4] = vh[p];
                As[1][base + p * 4] = vl[p];
            }
        }
        #pragma unroll
        for (int i = 0; i < 2; i++) {
            int r = b_r[i], j = b_j[i];
            int ks  = j >> 1;
            int reg = j & 1;
            int base = (((r >> 3) * 4 + ks) * 32 + (r & 7) * 4) * 2 + reg;
            uint32_t vh[4] = {b_hi[i].x, b_hi[i].y, b_hi[i].z, b_hi[i].w};
            #pragma unroll
            for (int p = 0; p < 4; p++)
                Bs[base + p * 2] = vh[p];
        }
        __syncthreads();
        int kn = k0 + 64;
        if (kn < K) {
            #pragma unroll
            for (int i = 0; i < 4; i++) {
                int gr = bm0 + a_r[i];
                if (gr < M) {
                    size_t off = (size_t)gr * K + kn + a_j[i] * 8;
                    a_hi[i] = *(const uint4*)&Ah[off];
                    a_lo[i] = *(const uint4*)&Al[off];
                } else {
                    a_hi[i] = make_uint4(0, 0, 0, 0);
                    a_lo[i] = make_uint4(0, 0, 0, 0);
                }
            }
            #pragma unroll
            for (int i = 0; i < 2; i++) {
                size_t off = (size_t)(bn0 + b_r[i]) * K + kn + b_j[i] * 8;
                b_hi[i] = *(const uint4*)&Bth[off];
            }
        }
        #pragma unroll
        for (int ks = 0; ks < 4; ks++) {
            uint32_t ah[2][4], al2_[2][4], bh[4][2];
            #pragma unroll
            for (int mf = 0; mf < 2; mf++) {
                int off = (((wm * 2 + mf) * 4 + ks) * 32 + lane) * 4;
                uint4 h = *(const uint4*)&As[0][off];
                uint4 l = *(const uint4*)&As[1][off];
                ah[mf][0] = h.x; ah[mf][1] = h.y; ah[mf][2] = h.z; ah[mf][3] = h.w;
                al2_[mf][0] = l.x; al2_[mf][1] = l.y; al2_[mf][2] = l.z; al2_[mf][3] = l.w;
            }
            #pragma unroll
            for (int nf = 0; nf < 4; nf++) {
                int off = (((wn * 4 + nf) * 4 + ks) * 32 + lane) * 2;
                uint2 h = *(const uint2*)&Bs[off];
                bh[nf][0] = h.x; bh[nf][1] = h.y;
            }
            #pragma unroll
            for (int mf = 0; mf < 2; mf++)
                #pragma unroll
                for (int nf = 0; nf < 4; nf++) {
                    mma_f16(acc[mf][nf], ah[mf], bh[nf]);
                    mma_f16(acc[mf][nf], al2_[mf], bh[nf]);
                }
        }
    }
    // epilogue: fp16 split store only
    #pragma unroll
    for (int mf = 0; mf < 2; mf++) {
        int r0 = bm0 + wm * 32 + mf * 16 + (lane >> 2);
        #pragma unroll
        for (int nf = 0; nf < 4; nf++) {
            int c0 = bn0 + wn * 32 + nf * 8 + (lane & 3) * 2;
            float bz0 = bias[c0];
            float bz1 = bias[c0 + 1];
            #pragma unroll
            for (int half = 0; half < 2; half++) {
                int rr = r0 + half * 8;
                if (rr >= M) continue;
                float v0 = acc[mf][nf][half * 2]     + bz0;
                float v1 = acc[mf][nf][half * 2 + 1] + bz1;
                __half h0 = __float2half_rn(v0);
                __half h1 = __float2half_rn(v1);
                __half l0 = __float2half_rn(v0 - __half2float(h0));
                __half l1 = __float2half_rn(v1 - __half2float(h1));
                __half hp[2] = {h0, h1}, lp[2] = {l0, l1};
                *(uint32_t*)&g_ah[split_off + (size_t)rr * N + c0] = *(uint32_t*)hp;
                *(uint32_t*)&g_al[split_off + (size_t)rr * N + c0] = *(uint32_t*)lp;
            }
        }
    }
}

// ---------------- wide feature GEMM (512 thr, 128x128 tile) — N=512, fp16 out + el/er ----------------
__global__ __launch_bounds__(512) void gemm_f16w(
    int a_off, int b_off, int M, int K,
    const float* __restrict__ attn_al, const float* __restrict__ attn_ar)
{
    __shared__ uint32_t As[2][4096];   // 32 KB
    __shared__ uint32_t Bs[4096];      // 16 KB  (total 48 KB; el/er scratch aliases As)

    const int N = 512;
    const __half* Ah = g_ah + a_off;
    const __half* Al = g_al + a_off;
    const __half* Bth = g_bth + b_off;

    int tid  = threadIdx.x;
    int lane = tid & 31;
    int w    = tid >> 5;       // 0..15
    int wm   = w & 3;
    int wn   = w >> 2;         // 0..3
    int bm0  = blockIdx.y * 128;
    int bn0  = blockIdx.x * 128;

    float acc[2][4][4];
    #pragma unroll
    for (int mf = 0; mf < 2; mf++)
        #pragma unroll
        for (int nf = 0; nf < 4; nf++)
            #pragma unroll
            for (int i = 0; i < 4; i++) acc[mf][nf][i] = 0.f;

    int a_r[2], a_j[2], b_r[2], b_j[2];
    #pragma unroll
    for (int i = 0; i < 2; i++) {
        int idx = tid + i * 512;
        a_r[i] = idx >> 3;     // 0..127
        a_j[i] = idx & 7;
        b_r[i] = idx >> 3;     // 0..127
        b_j[i] = idx & 7;
    }

    uint4 a_hi[2], a_lo[2], b_hi[2];
    #pragma unroll
    for (int i = 0; i < 2; i++) {
        int gr = bm0 + a_r[i];
        if (gr < M) {
            size_t off = (size_t)gr * K + a_j[i] * 8;
            a_hi[i] = *(const uint4*)&Ah[off];
            a_lo[i] = *(const uint4*)&Al[off];
        } else {
            a_hi[i] = make_uint4(0, 0, 0, 0);
            a_lo[i] = make_uint4(0, 0, 0, 0);
        }
        size_t boff = (size_t)(bn0 + b_r[i]) * K + b_j[i] * 8;
        b_hi[i] = *(const uint4*)&Bth[boff];
    }

    for (int k0 = 0; k0 < K; k0 += 64) {
        __syncthreads();
        #pragma unroll
        for (int i = 0; i < 2; i++) {
            int r = a_r[i], j = a_j[i];
            int ks  = j >> 1;
            int reg = ((r >> 3) & 1) | ((j & 1) << 1);
            int base = (((r >> 4) * 4 + ks) * 32 + (r & 7) * 4) * 4 + reg;
            uint32_t vh[4] = {a_hi[i].x, a_hi[i].y, a_hi[i].z, a_hi[i].w};
            uint32_t vl[4] = {a_lo[i].x, a_lo[i].y, a_lo[i].z, a_lo[i].w};
            #pragma unroll
            for (int p = 0; p < 4; p++) {
                As[0][base + p * 4] = vh[p];
                As[1][base + p * 4] = vl[p];
            }
        }
        #pragma unroll
        for (int i = 0; i < 2; i++) {
            int r = b_r[i], j = b_j[i];
            int ks  = j >> 1;
            int reg = j & 1;
            int base = (((r >> 3) * 4 + ks) * 32 + (r & 7) * 4) * 2 + reg;
            uint32_t vh[4] = {b_hi[i].x, b_hi[i].y, b_hi[i].z, b_hi[i].w};
            #pragma unroll
            for (int p = 0; p < 4; p++)
                Bs[base + p * 2] = vh[p];
        }
        __syncthreads();
        int kn = k0 + 64;
        if (kn < K) {
            #pragma unroll
            for (int i = 0; i < 2; i++) {
                int gr = bm0 + a_r[i];
                if (gr < M) {
                    size_t off = (size_t)gr * K + kn + a_j[i] * 8;
                    a_hi[i] = *(const uint4*)&Ah[off];
                    a_lo[i] = *(const uint4*)&Al[off];
                } else {
                    a_hi[i] = make_uint4(0, 0, 0, 0);
                    a_lo[i] = make_uint4(0, 0, 0, 0);
                }
                size_t boff = (size_t)(bn0 + b_r[i]) * K + kn + b_j[i] * 8;
                b_hi[i] = *(const uint4*)&Bth[boff];
            }
        }
        #pragma unroll
        for (int ks = 0; ks < 4; ks++) {
            uint32_t ah[2][4], al2_[2][4], bh[4][2];
            #pragma unroll
            for (int mf = 0; mf < 2; mf++) {
                int off = (((wm * 2 + mf) * 4 + ks) * 32 + lane) * 4;
                uint4 h = *(const uint4*)&As[0][off];
                uint4 l = *(const uint4*)&As[1][off];
                ah[mf][0] = h.x; ah[mf][1] = h.y; ah[mf][2] = h.z; ah[mf][3] = h.w;
                al2_[mf][0] = l.x; al2_[mf][1] = l.y; al2_[mf][2] = l.z; al2_[mf][3] = l.w;
            }
            #pragma unroll
            for (int nf = 0; nf < 4; nf++) {
                int off = (((wn * 4 + nf) * 4 + ks) * 32 + lane) * 2;
                uint2 h = *(const uint2*)&Bs[off];
                bh[nf][0] = h.x; bh[nf][1] = h.y;
            }
            #pragma unroll
            for (int mf = 0; mf < 2; mf++)
                #pragma unroll
                for (int nf = 0; nf < 4; nf++) {
                    mma_f16(acc[mf][nf], ah[mf], bh[nf]);
                    mma_f16(acc[mf][nf], al2_[mf], bh[nf]);
                }
        }
    }
    // epilogue: fp16-hi feature store
    #pragma unroll
    for (int mf = 0; mf < 2; mf++) {
        int r0 = bm0 + wm * 32 + mf * 16 + (lane >> 2);
        #pragma unroll
        for (int nf = 0; nf < 4; nf++) {
            int c0 = bn0 + wn * 32 + nf * 8 + (lane & 3) * 2;
            #pragma unroll
            for (int half = 0; half < 2; half++) {
                int rr = r0 + half * 8;
                if (rr >= M) continue;
                __half hp[2] = {__float2half_rn(acc[mf][nf][half * 2]),
                                __float2half_rn(acc[mf][nf][half * 2 + 1])};
                *(uint32_t*)&g_fth[(size_t)rr * N + c0] = *(uint32_t*)hp;
            }
        }
    }
    // fused el/er over the 2 heads of this block; scratch aliases As (dead now)
    __syncthreads();
    float* sl = (float*)&As[0][0];        // [128][2 heads][2 wn-halves] = 512 floats
    float* sr = sl + 512;
    {
        int hg = wn >> 1;                 // head group within block (0/1)
        int hb = (bn0 >> 6) + hg;         // absolute head
        float pl[2][2] = {{0.f, 0.f}, {0.f, 0.f}};
        float pr[2][2] = {{0.f, 0.f}, {0.f, 0.f}};
        #pragma unroll
        for (int mf = 0; mf < 2; mf++)
            #pragma unroll
            for (int nf = 0; nf < 4; nf++)
                #pragma unroll
                for (int s = 0; s < 2; s++) {
                    int d = (wn & 1) * 32 + nf * 8 + (lane & 3) * 2 + s;
                    float wl = attn_al[hb * 64 + d];
                    float wr = attn_ar[hb * 64 + d];
                    pl[mf][0] = fmaf(acc[mf][nf][s],     wl, pl[mf][0]);
                    pl[mf][1] = fmaf(acc[mf][nf][2 + s], wl, pl[mf][1]);
                    pr[mf][0] = fmaf(acc[mf][nf][s],     wr, pr[mf][0]);
                    pr[mf][1] = fmaf(acc[mf][nf][2 + s], wr, pr[mf][1]);
                }
        #pragma unroll
        for (int mf = 0; mf < 2; mf++)
            #pragma unroll
            for (int hf = 0; hf < 2; hf++) {
                float vl = pl[mf][hf], vr = pr[mf][hf];
                vl += __shfl_xor_sync(0xffffffffu, vl, 1);
                vl += __shfl_xor_sync(0xffffffffu, vl, 2);
                vr += __shfl_xor_sync(0xffffffffu, vr, 1);
                vr += __shfl_xor_sync(0xffffffffu, vr, 2);
                if ((lane & 3) == 0) {
                    int rl = wm * 32 + mf * 16 + hf * 8 + (lane >> 2);
                    sl[(rl * 2 + hg) * 2 + (wn & 1)] = vl;
                    sr[(rl * 2 + hg) * 2 + (wn & 1)] = vr;
                }
            }
        __syncthreads();
        if (tid < 128) {
            int row = bm0 + tid;
            if (row < M) {
                int hb0 = bn0 >> 6;
                #pragma unroll
                for (int g = 0; g < 2; g++) {
                    g_el[row * 8 + hb0 + g] = sl[(tid * 2 + g) * 2] + sl[(tid * 2 + g) * 2 + 1];
                    g_er[row * 8 + hb0 + g] = sr[(tid * 2 + g) * 2] + sr[(tid * 2 + g) * 2 + 1];
                }
            }
        }
    }
}

// ---------------- fused softmax + aggregation, F=512, H=8 ----------------
__global__ __launch_bounds__(128) void k_agg512(
    const int* __restrict__ src,
    const float* __restrict__ bias, int use_resid, int write_split,
    float* __restrict__ out_ext)
{
    __shared__ float s_ex[16][8];
    __shared__ int   s_src[16];
    __shared__ float s_er[8];
    float* out = out_ext ? out_ext : g_h1;
    int n = blockIdx.x;
    int t = threadIdx.x;
    int f = t * 4;
    int h = f >> 6;
    if (t < 8) s_er[t] = g_er[n * 8 + t];
    int s0 = g_rowoff[n], s1 = g_rowoff[n + 1];
    float4 acc = make_float4(0.f, 0.f, 0.f, 0.f);
    float sumh = 0.f;
    __syncthreads();
    for (int base = s0; base < s1; base += 16) {
        int cnt = min(16, s1 - base);
        if (t < cnt * 8) {
            int e_ = t >> 3, hh = t & 7;
            int eid = g_eid[base + e_];
            int s = src[eid];
            if (hh == 0) s_src[e_] = s;
            float x = g_el[s * 8 + hh] + s_er[hh];
            x = (x >= 0.f) ? x : 0.2f * x;
            s_ex[e_][hh] = expf(x);
        }
        __syncthreads();
        for (int e = 0; e < cnt; e++) {
            float wgt = s_ex[e][h];
            int s = s_src[e];
            sumh += wgt;
            uint2 hv = *(const uint2*)&g_fth[(size_t)s * 512 + f];
            float2 f0 = __half22float2(*(__half2*)&hv.x);
            float2 f1 = __half22float2(*(__half2*)&hv.y);
            acc.x = fmaf(wgt, f0.x, acc.x);
            acc.y = fmaf(wgt, f0.y, acc.y);
            acc.z = fmaf(wgt, f1.x, acc.z);
            acc.w = fmaf(wgt, f1.y, acc.w);
        }
        __syncthreads();
    }
    float inv = 1.f / (sumh + 1e-16f);
    float4 bz = *(const float4*)&bias[f];
    acc.x = acc.x * inv + bz.x;
    acc.y = acc.y * inv + bz.y;
    acc.z = acc.z * inv + bz.z;
    acc.w = acc.w * inv + bz.w;
    if (use_resid) {
        float4 r = *(const float4*)&g_h1[(size_t)n * 512 + f];
        acc.x += r.x; acc.y += r.y; acc.z += r.z; acc.w += r.w;
    }
    acc.x = (acc.x > 0.f) ? acc.x : expm1f(acc.x);
    acc.y = (acc.y > 0.f) ? acc.y : expm1f(acc.y);
    acc.z = (acc.z > 0.f) ? acc.z : expm1f(acc.z);
    acc.w = (acc.w > 0.f) ? acc.w : expm1f(acc.w);
    *(float4*)&out[(size_t)n * 512 + f] = acc;
    if (write_split) {
        float vv[4] = {acc.x, acc.y, acc.z, acc.w};
        __half hs[4], ls[4];
        #pragma unroll
        for (int j = 0; j < 4; j++) {
            hs[j] = __float2half_rn(vv[j]);
            ls[j] = __float2half_rn(vv[j] - __half2float(hs[j]));
        }
        *(uint2*)&g_ah[(size_t)n * 512 + f] = *(uint2*)hs;
        *(uint2*)&g_al[(size_t)n * 512 + f] = *(uint2*)ls;
    }
}

// ---------------- layer-2 projections (tiled, smem weight reuse) ----------------
__global__ __launch_bounds__(128) void k_l2proj2(
    const float* __restrict__ h2, const float* __restrict__ W2,
    const float* __restrict__ resW2, const float* __restrict__ al2,
    const float* __restrict__ ar2)
{
    __shared__ float sW[64 * 16];
    __shared__ float sR[64 * 16];
    int n = blockIdx.x * 128 + threadIdx.x;
    int nc = (n < NNODES) ? n : (NNODES - 1);
    const float* hr = h2 + (size_t)nc * 512;

    float a1[16], a2[16];
    #pragma unroll
    for (int c = 0; c < 16; c++) { a1[c] = 0.f; a2[c] = 0.f; }

    for (int k0 = 0; k0 < 512; k0 += 64) {
        __syncthreads();
        #pragma unroll
        for (int i = 0; i < 8; i++) {
            int idx = threadIdx.x + i * 128;
            sW[idx] = W2[k0 * 16 + idx];
            sR[idx] = resW2[k0 * 16 + idx];
        }
        __syncthreads();
        #pragma unroll
        for (int kk = 0; kk < 64; kk += 4) {
            float4 hv4 = *(const float4*)&hr[k0 + kk];
            float hv[4] = {hv4.x, hv4.y, hv4.z, hv4.w};
            #pragma unroll
            for (int q = 0; q < 4; q++) {
                float hq = hv[q];
                const float4* w4 = (const float4*)&sW[(kk + q) * 16];
                const float4* r4 = (const float4*)&sR[(kk + q) * 16];
                #pragma unroll
                for (int v = 0; v < 4; v++) {
                    float4 wv = w4[v], rv = r4[v];
                    a1[v * 4 + 0] = fmaf(hq, wv.x, a1[v * 4 + 0]);
                    a1[v * 4 + 1] = fmaf(hq, wv.y, a1[v * 4 + 1]);
                    a1[v * 4 + 2] = fmaf(hq, wv.z, a1[v * 4 + 2]);
                    a1[v * 4 + 3] = fmaf(hq, wv.w, a1[v * 4 + 3]);
                    a2[v * 4 + 0] = fmaf(hq, rv.x, a2[v * 4 + 0]);
                    a2[v * 4 + 1] = fmaf(hq, rv.y, a2[v * 4 + 1]);
                    a2[v * 4 + 2] = fmaf(hq, rv.z, a2[v * 4 + 2]);
                    a2[v * 4 + 3] = fmaf(hq, rv.w, a2[v * 4 + 3]);
                }
            }
        }
    }
    if (n < NNODES) {
        float el = 0.f, er = 0.f;
        #pragma unroll
        for (int c = 0; c < 16; c++) {
            el = fmaf(a1[c], al2[c], el);
            er = fmaf(a1[c], ar2[c], er);
        }
        g_el[n] = el;
        g_er[n] = er;
        #pragma unroll
        for (int v = 0; v < 4; v++) {
            *(float4*)&g_ft2[n * 16 + v * 4]  = make_float4(a1[v*4], a1[v*4+1], a1[v*4+2], a1[v*4+3]);
            *(float4*)&g_res2[n * 16 + v * 4] = make_float4(a2[v*4], a2[v*4+1], a2[v*4+2], a2[v*4+3]);
        }
    }
}

// ---------------- fused softmax + aggregation F=16, H=1 ----------------
__global__ __launch_bounds__(32) void k_agg16(
    const int* __restrict__ src, const float* __restrict__ b2,
    float* __restrict__ logits)
{
    int n = blockIdx.x;
    int lane = threadIdx.x;
    int li = lane & 15;
    float ern = g_er[n];
    int s0 = g_rowoff[n], s1 = g_rowoff[n + 1];
    float acc = 0.f, sum = 0.f;
    for (int base = s0; base < s1; base += 16) {
        int cnt = min(16, s1 - base);
        float ex = 0.f;
        int sv = 0;
        if (lane < cnt) {
            int eid = g_eid[base + lane];
            sv = src[eid];
            float x = g_el[sv] + ern;
            x = (x >= 0.f) ? x : 0.2f * x;
            ex = expf(x);
        }
        for (int e = 0; e < cnt; e++) {
            float wgt = __shfl_sync(0xffffffffu, ex, e);
            int s     = __shfl_sync(0xffffffffu, sv, e);
            sum += wgt;
            acc = fmaf(wgt, g_ft2[s * 16 + li], acc);
        }
    }
    if (lane < 16) {
        float inv = 1.f / (sum + 1e-16f);
        logits[n * 16 + lane] = g_res2[n * 16 + lane] + b2[lane] + acc * inv;
    }
}

// ---------------- launch (ONLY kernel launches — graph-capturable) ----------------
extern "C" void kernel_launch(void* const* d_in, const int* in_sizes, int n_in,
                              void* d_out, int out_size)
{
    const float* x0    = (const float*)d_in[0];
    const float* x1    = (const float*)d_in[1];
    const int*   src   = (const int*)d_in[2];
    const int*   dst   = (const int*)d_in[3];
    const float* fc0_W = (const float*)d_in[4];
    const float* fc0_b = (const float*)d_in[5];
    const float* fc1_W = (const float*)d_in[6];
    const float* fc1_b = (const float*)d_in[7];
    const float* W0  = (const float*)d_in[8];
    const float* al0 = (const float*)d_in[9];
    const float* ar0 = (const float*)d_in[10];
    const float* b0  = (const float*)d_in[11];
    const float* W1  = (const float*)d_in[12];
    const float* al1 = (const float*)d_in[13];
    const float* ar1 = (const float*)d_in[14];
    const float* b1  = (const float*)d_in[15];
    const float* W2  = (const float*)d_in[16];
    const float* al2 = (const float*)d_in[17];
    const float* ar2 = (const float*)d_in[18];
    const float* b2  = (const float*)d_in[19];
    const float* resW2 = (const float*)d_in[20];

    float* out    = (float*)d_out;
    float* logits = out;                         // [50000,16]
    float* enc    = out + (size_t)NNODES * 16;   // [50000,512]

    const int FC0_BT = 0, FC1_BT = 16384, W0_BT = 32768, W1_BT = 65536;
    const int NSCAN = (NNODES + 1023) / 1024;    // 49

    k_prep<<<(NNODES + 327680 + 255) / 256, 256>>>(fc0_W, fc1_W, W0, W1);
    k_split_x<<<(NNODES * 256 / 4 + 255) / 256, 256>>>(x0, x1);
    k_count<<<(NEDGES + 255) / 256, 256>>>(dst);
    k_scanA<<<NSCAN, 1024>>>();
    k_scanB<<<1, 64>>>();
    {
        dim3 g(1, (NHALF + 127) / 128);
        gemm_f16<<<g, 256>>>(0, FC0_BT, NHALF, 64, 256, fc0_b, (long long)L0SPLIT);
    }
    k_scanC<<<NSCAN, 1024>>>();
    k_scatter<<<(NEDGES + 255) / 256, 256>>>(dst);
    k_sortseg<<<(NNODES + 255) / 256, 256>>>();
    {
        dim3 g(1, (NHALF + 127) / 128);
        gemm_f16<<<g, 256>>>(NHALF * 256, FC1_BT, NHALF, 64, 256, fc1_b,
                             (long long)L0SPLIT + NHALF * 64);
    }

    // ---- layer 0: 64 -> 8x64 (wide GEMM, el/er fused, fp16 feature out) ----
    {
        dim3 g(4, (NNODES + 127) / 128);
        gemm_f16w<<<g, 512>>>(L0SPLIT, W0_BT, NNODES, 64, al0, ar0);
    }
    k_agg512<<<NNODES, 128>>>(src, b0, 0, 1, nullptr);   // softmax+agg -> g_h1 + split @0

    // ---- layer 1: 512 -> 8x64 (wide GEMM, el/er fused, fp16 feature out) ----
    {
        dim3 g(4, (NNODES + 127) / 128);
        gemm_f16w<<<g, 512>>>(0, W1_BT, NNODES, 512, al1, ar1);
    }
    k_agg512<<<NNODES, 128>>>(src, b1, 1, 0, enc);       // softmax+agg, resid -> enc

    // ---- output layer: 512 -> 1x16, linear residual ----
    k_l2proj2<<<(NNODES + 127) / 128, 128>>>(enc, W2, resW2, al2, ar2);
    k_agg16<<<NNODES, 32>>>(src, b2, logits);
}

// round 17
// speedup vs baseline: 3.3533x; 1.1886x over previous
#include <cuda_runtime.h>
#include <cuda_fp16.h>
#include <math.h>
#include <stdint.h>

#define NNODES 50000
#define NHALF  25000
#define NEDGES 400000
#define L0SPLIT 12800000   // fc-output region in g_ah (disjoint from x0/x1 splits)

// ---------------- scratch (device globals; no allocation allowed) ----------------
__device__ float g_h1[NNODES * 512];
__device__ float g_el[NNODES * 8];
__device__ float g_er[NNODES * 8];
__device__ float g_ft2[NNODES * 16];
__device__ float g_res2[NNODES * 16];
__device__ int   g_deg[NNODES];
__device__ int   g_cur[NNODES];
__device__ int   g_rowoff[NNODES + 1];
__device__ int   g_eid[NEDGES];
__device__ int   g_bsum[64];
// fp16 operands
__device__ __half g_ah[NNODES * 512];    // A hi (x splits, L0 input, L1 input)
__device__ __half g_al[NNODES * 512];    // A lo (x splits only; fc GEMM 2-term)
__device__ __half g_bth[327680];         // weights [N,K]: fc0@0, fc1@16384, W0@32768, W1@65536
__device__ __half g_fth[NNODES * 512];   // fp16-hi feature tensor (GEMM out, gathered by agg)

// ---------------- CSR build ----------------
__global__ void k_count(const int* __restrict__ dst) {
    int i = blockIdx.x * blockDim.x + threadIdx.x;
    if (i < NEDGES) {
        int d = dst[i];
        if (d >= 0 && d < NNODES) atomicAdd(&g_deg[d], 1);
    }
}

__global__ void k_scanA() {
    __shared__ int ws[32];
    int t = threadIdx.x;
    int i = blockIdx.x * 1024 + t;
    int v = (i < NNODES) ? g_deg[i] : 0;
    int x = v;
    #pragma unroll
    for (int o = 1; o < 32; o <<= 1) {
        int y = __shfl_up_sync(0xffffffffu, x, o);
        if ((t & 31) >= o) x += y;
    }
    if ((t & 31) == 31) ws[t >> 5] = x;
    __syncthreads();
    if (t < 32) {
        int w = ws[t];
        #pragma unroll
        for (int o = 1; o < 32; o <<= 1) {
            int y = __shfl_up_sync(0xffffffffu, w, o);
            if (t >= o) w += y;
        }
        ws[t] = w;
    }
    __syncthreads();
    int incl = x + ((t >= 32) ? ws[(t >> 5) - 1] : 0);
    if (i < NNODES) g_rowoff[i] = incl - v;
    if (t == 1023) g_bsum[blockIdx.x] = incl;
}

__global__ void k_scanB() {
    __shared__ int s[64];
    int t = threadIdx.x;
    int nb = (NNODES + 1023) / 1024;
    int v = (t < nb) ? g_bsum[t] : 0;
    s[t] = v;
    __syncthreads();
    #pragma unroll
    for (int o = 1; o < 64; o <<= 1) {
        int y = (t >= o) ? s[t - o] : 0;
        __syncthreads();
        s[t] += y;
        __syncthreads();
    }
    if (t < nb) g_bsum[t] = s[t] - v;
    if (t == 63) g_rowoff[NNODES] = s[63];
}

__global__ void k_scanC() {
    int i = blockIdx.x * 1024 + threadIdx.x;
    if (i < NNODES) g_rowoff[i] += g_bsum[blockIdx.x];
}

__global__ void k_scatter(const int* __restrict__ dst) {
    int i = blockIdx.x * blockDim.x + threadIdx.x;
    if (i < NEDGES) {
        int d = dst[i];
        if (d >= 0 && d < NNODES) {
            int p = g_rowoff[d] + atomicAdd(&g_cur[d], 1);
            g_eid[p] = i;
        }
    }
}

__global__ void k_sortseg() {
    int n = blockIdx.x * blockDim.x + threadIdx.x;
    if (n >= NNODES) return;
    int s = g_rowoff[n], e = g_rowoff[n + 1];
    for (int i = s + 1; i < e; i++) {
        int key = g_eid[i];
        int j = i - 1;
        while (j >= s && g_eid[j] > key) { g_eid[j + 1] = g_eid[j]; j--; }
        g_eid[j + 1] = key;
    }
}

// ---------------- merged prep: zero counts + all weight converts ----------------
__global__ void k_prep(const float* __restrict__ fc0_W, const float* __restrict__ fc1_W,
                       const float* __restrict__ W0, const float* __restrict__ W1)
{
    int i = blockIdx.x * blockDim.x + threadIdx.x;
    if (i < NNODES) { g_deg[i] = 0; g_cur[i] = 0; }
    int idx = i - NNODES;
    const float* W;
    int K, N, b_off;
    if (idx < 0) return;
    if (idx < 16384)        { W = fc0_W; K = 256; N = 64;  b_off = 0;     }
    else if (idx < 32768)   { W = fc1_W; K = 256; N = 64;  b_off = 16384; idx -= 16384; }
    else if (idx < 65536)   { W = W0;    K = 64;  N = 512; b_off = 32768; idx -= 32768; }
    else if (idx < 327680)  { W = W1;    K = 512; N = 512; b_off = 65536; idx -= 65536; }
    else return;
    int k = idx / N, n = idx % N;
    g_bth[b_off + n * K + k] = __float2half_rn(W[k * N + n]);
}

// ---------------- fp16 split of both inputs (x0 then x1) ----------------
__global__ void k_split_x(const float* __restrict__ x0, const float* __restrict__ x1)
{
    int i = (blockIdx.x * blockDim.x + threadIdx.x) * 4;
    if (i >= NNODES * 256) return;
    const float* X = (i < NHALF * 256) ? (x0 + i) : (x1 + (i - NHALF * 256));
    float4 v = *(const float4*)X;
    float xs[4] = {v.x, v.y, v.z, v.w};
    __half hs[4], ls[4];
    #pragma unroll
    for (int j = 0; j < 4; j++) {
        hs[j] = __float2half_rn(xs[j]);
        ls[j] = __float2half_rn(xs[j] - __half2float(hs[j]));
    }
    *(uint2*)&g_ah[i] = *(uint2*)hs;
    *(uint2*)&g_al[i] = *(uint2*)ls;
}

__device__ __forceinline__ void mma_f16(float* c, const uint32_t* a, const uint32_t* b) {
    asm("mma.sync.aligned.m16n8k16.row.col.f32.f16.f16.f32 "
        "{%0,%1,%2,%3}, {%4,%5,%6,%7}, {%8,%9}, {%0,%1,%2,%3};"
        : "+f"(c[0]), "+f"(c[1]), "+f"(c[2]), "+f"(c[3])
        : "r"(a[0]), "r"(a[1]), "r"(a[2]), "r"(a[3]), "r"(b[0]), "r"(b[1]));
}

// ---------------- fc GEMM (256 thr, 128x64 tile, 2-term A) — hi-only split output ----------------
__global__ __launch_bounds__(256) void gemm_f16(
    int a_off, int b_off, int M, int N, int K,
    const float* __restrict__ bias, long long split_off)
{
    __shared__ uint32_t As[2][4096];
    __shared__ uint32_t Bs[2048];

    const __half* Ah = g_ah + a_off;
    const __half* Al = g_al + a_off;
    const __half* Bth = g_bth + b_off;

    int tid  = threadIdx.x;
    int lane = tid & 31;
    int w    = tid >> 5;
    int wm   = w & 3;
    int wn   = w >> 2;
    int bm0  = blockIdx.y * 128;
    int bn0  = blockIdx.x * 64;

    float acc[2][4][4];
    #pragma unroll
    for (int mf = 0; mf < 2; mf++)
        #pragma unroll
        for (int nf = 0; nf < 4; nf++)
            #pragma unroll
            for (int i = 0; i < 4; i++) acc[mf][nf][i] = 0.f;

    int a_r[4], a_j[4];
    #pragma unroll
    for (int i = 0; i < 4; i++) {
        int idx = tid + i * 256;
        a_r[i] = idx >> 3;
        a_j[i] = idx & 7;
    }
    int b_r[2], b_j[2];
    #pragma unroll
    for (int i = 0; i < 2; i++) {
        int idx = tid + i * 256;
        b_r[i] = idx >> 3;
        b_j[i] = idx & 7;
    }

    uint4 a_hi[4], a_lo[4], b_hi[2];
    #pragma unroll
    for (int i = 0; i < 4; i++) {
        int gr = bm0 + a_r[i];
        if (gr < M) {
            size_t off = (size_t)gr * K + a_j[i] * 8;
            a_hi[i] = *(const uint4*)&Ah[off];
            a_lo[i] = *(const uint4*)&Al[off];
        } else {
            a_hi[i] = make_uint4(0, 0, 0, 0);
            a_lo[i] = make_uint4(0, 0, 0, 0);
        }
    }
    #pragma unroll
    for (int i = 0; i < 2; i++) {
        size_t off = (size_t)(bn0 + b_r[i]) * K + b_j[i] * 8;
        b_hi[i] = *(const uint4*)&Bth[off];
    }

    for (int k0 = 0; k0 < K; k0 += 64) {
        __syncthreads();
        #pragma unroll
        for (int i = 0; i < 4; i++) {
            int r = a_r[i], j = a_j[i];
            int ks  = j >> 1;
            int reg = ((r >> 3) & 1) | ((j & 1) << 1);
            int base = (((r >> 4) * 4 + ks) * 32 + (r & 7) * 4) * 4 + reg;
            uint32_t vh[4] = {a_hi[i].x, a_hi[i].y, a_hi[i].z, a_hi[i].w};
            uint32_t vl[4] = {a_lo[i].x, a_lo[i].y, a_lo[i].z, a_lo[i].w};
            #pragma unroll
            for (int p = 0; p < 4; p++) {
                As[0][base + p * 4] = vh[p];
                As[1][base + p * 4] = vl[p];
            }
        }
        #pragma unroll
        for (int i = 0; i < 2; i++) {
            int r = b_r[i], j = b_j[i];
            int ks  = j >> 1;
            int reg = j & 1;
            int base = (((r >> 3) * 4 + ks) * 32 + (r & 7) * 4) * 2 + reg;
            uint32_t vh[4] = {b_hi[i].x, b_hi[i].y, b_hi[i].z, b_hi[i].w};
            #pragma unroll
            for (int p = 0; p < 4; p++)
                Bs[base + p * 2] = vh[p];
        }
        __syncthreads();
        int kn = k0 + 64;
        if (kn < K) {
            #pragma unroll
            for (int i = 0; i < 4; i++) {
                int gr = bm0 + a_r[i];
                if (gr < M) {
                    size_t off = (size_t)gr * K + kn + a_j[i] * 8;
                    a_hi[i] = *(const uint4*)&Ah[off];
                    a_lo[i] = *(const uint4*)&Al[off];
                } else {
                    a_hi[i] = make_uint4(0, 0, 0, 0);
                    a_lo[i] = make_uint4(0, 0, 0, 0);
                }
            }
            #pragma unroll
            for (int i = 0; i < 2; i++) {
                size_t off = (size_t)(bn0 + b_r[i]) * K + kn + b_j[i] * 8;
                b_hi[i] = *(const uint4*)&Bth[off];
            }
        }
        #pragma unroll
        for (int ks = 0; ks < 4; ks++) {
            uint32_t ah[2][4], al2_[2][4], bh[4][2];
            #pragma unroll
            for (int mf = 0; mf < 2; mf++) {
                int off = (((wm * 2 + mf) * 4 + ks) * 32 + lane) * 4;
                uint4 h = *(const uint4*)&As[0][off];
                uint4 l = *(const uint4*)&As[1][off];
                ah[mf][0] = h.x; ah[mf][1] = h.y; ah[mf][2] = h.z; ah[mf][3] = h.w;
                al2_[mf][0] = l.x; al2_[mf][1] = l.y; al2_[mf][2] = l.z; al2_[mf][3] = l.w;
            }
            #pragma unroll
            for (int nf = 0; nf < 4; nf++) {
                int off = (((wn * 4 + nf) * 4 + ks) * 32 + lane) * 2;
                uint2 h = *(const uint2*)&Bs[off];
                bh[nf][0] = h.x; bh[nf][1] = h.y;
            }
            #pragma unroll
            for (int mf = 0; mf < 2; mf++)
                #pragma unroll
                for (int nf = 0; nf < 4; nf++) {
                    mma_f16(acc[mf][nf], ah[mf], bh[nf]);
                    mma_f16(acc[mf][nf], al2_[mf], bh[nf]);
                }
        }
    }
    // epilogue: fp16-hi store only (feature GEMM consumes hi-only A)
    #pragma unroll
    for (int mf = 0; mf < 2; mf++) {
        int r0 = bm0 + wm * 32 + mf * 16 + (lane >> 2);
        #pragma unroll
        for (int nf = 0; nf < 4; nf++) {
            int c0 = bn0 + wn * 32 + nf * 8 + (lane & 3) * 2;
            float bz0 = bias[c0];
            float bz1 = bias[c0 + 1];
            #pragma unroll
            for (int half = 0; half < 2; half++) {
                int rr = r0 + half * 8;
                if (rr >= M) continue;
                __half hp[2] = {__float2half_rn(acc[mf][nf][half * 2] + bz0),
                                __float2half_rn(acc[mf][nf][half * 2 + 1] + bz1)};
                *(uint32_t*)&g_ah[split_off + (size_t)rr * N + c0] = *(uint32_t*)hp;
            }
        }
    }
}

// ---------------- wide feature GEMM (512 thr, 128x128 tile, 1-term A) ----------------
__global__ __launch_bounds__(512) void gemm_f16w(
    int a_off, int b_off, int M, int K,
    const float* __restrict__ attn_al, const float* __restrict__ attn_ar)
{
    __shared__ uint32_t As[4096];      // 16 KB
    __shared__ uint32_t Bs[4096];      // 16 KB (el/er scratch aliases As)

    const int N = 512;
    const __half* Ah = g_ah + a_off;
    const __half* Bth = g_bth + b_off;

    int tid  = threadIdx.x;
    int lane = tid & 31;
    int w    = tid >> 5;       // 0..15
    int wm   = w & 3;
    int wn   = w >> 2;         // 0..3
    int bm0  = blockIdx.y * 128;
    int bn0  = blockIdx.x * 128;

    float acc[2][4][4];
    #pragma unroll
    for (int mf = 0; mf < 2; mf++)
        #pragma unroll
        for (int nf = 0; nf < 4; nf++)
            #pragma unroll
            for (int i = 0; i < 4; i++) acc[mf][nf][i] = 0.f;

    int a_r[2], a_j[2], b_r[2], b_j[2];
    #pragma unroll
    for (int i = 0; i < 2; i++) {
        int idx = tid + i * 512;
        a_r[i] = idx >> 3;
        a_j[i] = idx & 7;
        b_r[i] = idx >> 3;
        b_j[i] = idx & 7;
    }

    uint4 a_hi[2], b_hi[2];
    #pragma unroll
    for (int i = 0; i < 2; i++) {
        int gr = bm0 + a_r[i];
        a_hi[i] = (gr < M) ? *(const uint4*)&Ah[(size_t)gr * K + a_j[i] * 8]
                           : make_uint4(0, 0, 0, 0);
        b_hi[i] = *(const uint4*)&Bth[(size_t)(bn0 + b_r[i]) * K + b_j[i] * 8];
    }

    for (int k0 = 0; k0 < K; k0 += 64) {
        __syncthreads();
        #pragma unroll
        for (int i = 0; i < 2; i++) {
            int r = a_r[i], j = a_j[i];
            int ks  = j >> 1;
            int reg = ((r >> 3) & 1) | ((j & 1) << 1);
            int base = (((r >> 4) * 4 + ks) * 32 + (r & 7) * 4) * 4 + reg;
            uint32_t vh[4] = {a_hi[i].x, a_hi[i].y, a_hi[i].z, a_hi[i].w};
            #pragma unroll
            for (int p = 0; p < 4; p++)
                As[base + p * 4] = vh[p];
        }
        #pragma unroll
        for (int i = 0; i < 2; i++) {
            int r = b_r[i], j = b_j[i];
            int ks  = j >> 1;
            int reg = j & 1;
            int base = (((r >> 3) * 4 + ks) * 32 + (r & 7) * 4) * 2 + reg;
            uint32_t vh[4] = {b_hi[i].x, b_hi[i].y, b_hi[i].z, b_hi[i].w};
            #pragma unroll
            for (int p = 0; p < 4; p++)
                Bs[base + p * 2] = vh[p];
        }
        __syncthreads();
        int kn = k0 + 64;
        if (kn < K) {
            #pragma unroll
            for (int i = 0; i < 2; i++) {
                int gr = bm0 + a_r[i];
                a_hi[i] = (gr < M) ? *(const uint4*)&Ah[(size_t)gr * K + kn + a_j[i] * 8]
                                   : make_uint4(0, 0, 0, 0);
                b_hi[i] = *(const uint4*)&Bth[(size_t)(bn0 + b_r[i]) * K + kn + b_j[i] * 8];
            }
        }
        #pragma unroll
        for (int ks = 0; ks < 4; ks++) {
            uint32_t ah[2][4], bh[4][2];
            #pragma unroll
            for (int mf = 0; mf < 2; mf++) {
                int off = (((wm * 2 + mf) * 4 + ks) * 32 + lane) * 4;
                uint4 h = *(const uint4*)&As[off];
                ah[mf][0] = h.x; ah[mf][1] = h.y; ah[mf][2] = h.z; ah[mf][3] = h.w;
            }
            #pragma unroll
            for (int nf = 0; nf < 4; nf++) {
                int off = (((wn * 4 + nf) * 4 + ks) * 32 + lane) * 2;
                uint2 h = *(const uint2*)&Bs[off];
                bh[nf][0] = h.x; bh[nf][1] = h.y;
            }
            #pragma unroll
            for (int mf = 0; mf < 2; mf++)
                #pragma unroll
                for (int nf = 0; nf < 4; nf++)
                    mma_f16(acc[mf][nf], ah[mf], bh[nf]);
        }
    }
    // epilogue: fp16-hi feature store
    #pragma unroll
    for (int mf = 0; mf < 2; mf++) {
        int r0 = bm0 + wm * 32 + mf * 16 + (lane >> 2);
        #pragma unroll
        for (int nf = 0; nf < 4; nf++) {
            int c0 = bn0 + wn * 32 + nf * 8 + (lane & 3) * 2;
            #pragma unroll
            for (int half = 0; half < 2; half++) {
                int rr = r0 + half * 8;
                if (rr >= M) continue;
                __half hp[2] = {__float2half_rn(acc[mf][nf][half * 2]),
                                __float2half_rn(acc[mf][nf][half * 2 + 1])};
                *(uint32_t*)&g_fth[(size_t)rr * N + c0] = *(uint32_t*)hp;
            }
        }
    }
    // fused el/er over the 2 heads of this block; scratch aliases As (dead now)
    __syncthreads();
    float* sl = (float*)&As[0];
    float* sr = sl + 512;
    {
        int hg = wn >> 1;
        int hb = (bn0 >> 6) + hg;
        float pl[2][2] = {{0.f, 0.f}, {0.f, 0.f}};
        float pr[2][2] = {{0.f, 0.f}, {0.f, 0.f}};
        #pragma unroll
        for (int mf = 0; mf < 2; mf++)
            #pragma unroll
            for (int nf = 0; nf < 4; nf++)
                #pragma unroll
                for (int s = 0; s < 2; s++) {
                    int d = (wn & 1) * 32 + nf * 8 + (lane & 3) * 2 + s;
                    float wl = attn_al[hb * 64 + d];
                    float wr = attn_ar[hb * 64 + d];
                    pl[mf][0] = fmaf(acc[mf][nf][s],     wl, pl[mf][0]);
                    pl[mf][1] = fmaf(acc[mf][nf][2 + s], wl, pl[mf][1]);
                    pr[mf][0] = fmaf(acc[mf][nf][s],     wr, pr[mf][0]);
                    pr[mf][1] = fmaf(acc[mf][nf][2 + s], wr, pr[mf][1]);
                }
        #pragma unroll
        for (int mf = 0; mf < 2; mf++)
            #pragma unroll
            for (int hf = 0; hf < 2; hf++) {
                float vl = pl[mf][hf], vr = pr[mf][hf];
                vl += __shfl_xor_sync(0xffffffffu, vl, 1);
                vl += __shfl_xor_sync(0xffffffffu, vl, 2);
                vr += __shfl_xor_sync(0xffffffffu, vr, 1);
                vr += __shfl_xor_sync(0xffffffffu, vr, 2);
                if ((lane & 3) == 0) {
                    int rl = wm * 32 + mf * 16 + hf * 8 + (lane >> 2);
                    sl[(rl * 2 + hg) * 2 + (wn & 1)] = vl;
                    sr[(rl * 2 + hg) * 2 + (wn & 1)] = vr;
                }
            }
        __syncthreads();
        if (tid < 128) {
            int row = bm0 + tid;
            if (row < M) {
                int hb0 = bn0 >> 6;
                #pragma unroll
                for (int g = 0; g < 2; g++) {
                    g_el[row * 8 + hb0 + g] = sl[(tid * 2 + g) * 2] + sl[(tid * 2 + g) * 2 + 1];
                    g_er[row * 8 + hb0 + g] = sr[(tid * 2 + g) * 2] + sr[(tid * 2 + g) * 2 + 1];
                }
            }
        }
    }
}

// ---------------- fused softmax + aggregation, F=512, H=8 ----------------
__global__ __launch_bounds__(128) void k_agg512(
    const int* __restrict__ src,
    const float* __restrict__ bias, int use_resid, int write_split,
    float* __restrict__ out_ext)
{
    __shared__ float s_ex[16][8];
    __shared__ int   s_src[16];
    __shared__ float s_er[8];
    float* out = out_ext ? out_ext : g_h1;
    int n = blockIdx.x;
    int t = threadIdx.x;
    int f = t * 4;
    int h = f >> 6;
    if (t < 8) s_er[t] = g_er[n * 8 + t];
    int s0 = g_rowoff[n], s1 = g_rowoff[n + 1];
    float4 acc = make_float4(0.f, 0.f, 0.f, 0.f);
    float sumh = 0.f;
    __syncthreads();
    for (int base = s0; base < s1; base += 16) {
        int cnt = min(16, s1 - base);
        if (t < cnt * 8) {
            int e_ = t >> 3, hh = t & 7;
            int eid = g_eid[base + e_];
            int s = src[eid];
            if (hh == 0) s_src[e_] = s;
            float x = g_el[s * 8 + hh] + s_er[hh];
            x = (x >= 0.f) ? x : 0.2f * x;
            s_ex[e_][hh] = expf(x);
        }
        __syncthreads();
        for (int e = 0; e < cnt; e++) {
            float wgt = s_ex[e][h];
            int s = s_src[e];
            sumh += wgt;
            uint2 hv = *(const uint2*)&g_fth[(size_t)s * 512 + f];
            float2 f0 = __half22float2(*(__half2*)&hv.x);
            float2 f1 = __half22float2(*(__half2*)&hv.y);
            acc.x = fmaf(wgt, f0.x, acc.x);
            acc.y = fmaf(wgt, f0.y, acc.y);
            acc.z = fmaf(wgt, f1.x, acc.z);
            acc.w = fmaf(wgt, f1.y, acc.w);
        }
        __syncthreads();
    }
    float inv = 1.f / (sumh + 1e-16f);
    float4 bz = *(const float4*)&bias[f];
    acc.x = acc.x * inv + bz.x;
    acc.y = acc.y * inv + bz.y;
    acc.z = acc.z * inv + bz.z;
    acc.w = acc.w * inv + bz.w;
    if (use_resid) {
        float4 r = *(const float4*)&g_h1[(size_t)n * 512 + f];
        acc.x += r.x; acc.y += r.y; acc.z += r.z; acc.w += r.w;
    }
    acc.x = (acc.x > 0.f) ? acc.x : expm1f(acc.x);
    acc.y = (acc.y > 0.f) ? acc.y : expm1f(acc.y);
    acc.z = (acc.z > 0.f) ? acc.z : expm1f(acc.z);
    acc.w = (acc.w > 0.f) ? acc.w : expm1f(acc.w);
    *(float4*)&out[(size_t)n * 512 + f] = acc;
    if (write_split) {
        __half hs[4] = {__float2half_rn(acc.x), __float2half_rn(acc.y),
                        __float2half_rn(acc.z), __float2half_rn(acc.w)};
        *(uint2*)&g_ah[(size_t)n * 512 + f] = *(uint2*)hs;
    }
}

// ---------------- layer-2 projections (tiled, smem weight reuse) ----------------
__global__ __launch_bounds__(128) void k_l2proj2(
    const float* __restrict__ h2, const float* __restrict__ W2,
    const float* __restrict__ resW2, const float* __restrict__ al2,
    const float* __restrict__ ar2)
{
    __shared__ float sW[64 * 16];
    __shared__ float sR[64 * 16];
    int n = blockIdx.x * 128 + threadIdx.x;
    int nc = (n < NNODES) ? n : (NNODES - 1);
    const float* hr = h2 + (size_t)nc * 512;

    float a1[16], a2[16];
    #pragma unroll
    for (int c = 0; c < 16; c++) { a1[c] = 0.f; a2[c] = 0.f; }

    for (int k0 = 0; k0 < 512; k0 += 64) {
        __syncthreads();
        #pragma unroll
        for (int i = 0; i < 8; i++) {
            int idx = threadIdx.x + i * 128;
            sW[idx] = W2[k0 * 16 + idx];
            sR[idx] = resW2[k0 * 16 + idx];
        }
        __syncthreads();
        #pragma unroll
        for (int kk = 0; kk < 64; kk += 4) {
            float4 hv4 = *(const float4*)&hr[k0 + kk];
            float hv[4] = {hv4.x, hv4.y, hv4.z, hv4.w};
            #pragma unroll
            for (int q = 0; q < 4; q++) {
                float hq = hv[q];
                const float4* w4 = (const float4*)&sW[(kk + q) * 16];
                const float4* r4 = (const float4*)&sR[(kk + q) * 16];
                #pragma unroll
                for (int v = 0; v < 4; v++) {
                    float4 wv = w4[v], rv = r4[v];
                    a1[v * 4 + 0] = fmaf(hq, wv.x, a1[v * 4 + 0]);
                    a1[v * 4 + 1] = fmaf(hq, wv.y, a1[v * 4 + 1]);
                    a1[v * 4 + 2] = fmaf(hq, wv.z, a1[v * 4 + 2]);
                    a1[v * 4 + 3] = fmaf(hq, wv.w, a1[v * 4 + 3]);
                    a2[v * 4 + 0] = fmaf(hq, rv.x, a2[v * 4 + 0]);
                    a2[v * 4 + 1] = fmaf(hq, rv.y, a2[v * 4 + 1]);
                    a2[v * 4 + 2] = fmaf(hq, rv.z, a2[v * 4 + 2]);
                    a2[v * 4 + 3] = fmaf(hq, rv.w, a2[v * 4 + 3]);
                }
            }
        }
    }
    if (n < NNODES) {
        float el = 0.f, er = 0.f;
        #pragma unroll
        for (int c = 0; c < 16; c++) {
            el = fmaf(a1[c], al2[c], el);
            er = fmaf(a1[c], ar2[c], er);
        }
        g_el[n] = el;
        g_er[n] = er;
        #pragma unroll
        for (int v = 0; v < 4; v++) {
            *(float4*)&g_ft2[n * 16 + v * 4]  = make_float4(a1[v*4], a1[v*4+1], a1[v*4+2], a1[v*4+3]);
            *(float4*)&g_res2[n * 16 + v * 4] = make_float4(a2[v*4], a2[v*4+1], a2[v*4+2], a2[v*4+3]);
        }
    }
}

// ---------------- fused softmax + aggregation F=16, H=1 ----------------
__global__ __launch_bounds__(32) void k_agg16(
    const int* __restrict__ src, const float* __restrict__ b2,
    float* __restrict__ logits)
{
    int n = blockIdx.x;
    int lane = threadIdx.x;
    int li = lane & 15;
    float ern = g_er[n];
    int s0 = g_rowoff[n], s1 = g_rowoff[n + 1];
    float acc = 0.f, sum = 0.f;
    for (int base = s0; base < s1; base += 16) {
        int cnt = min(16, s1 - base);
        float ex = 0.f;
        int sv = 0;
        if (lane < cnt) {
            int eid = g_eid[base + lane];
            sv = src[eid];
            float x = g_el[sv] + ern;
            x = (x >= 0.f) ? x : 0.2f * x;
            ex = expf(x);
        }
        for (int e = 0; e < cnt; e++) {
            float wgt = __shfl_sync(0xffffffffu, ex, e);
            int s     = __shfl_sync(0xffffffffu, sv, e);
            sum += wgt;
            acc = fmaf(wgt, g_ft2[s * 16 + li], acc);
        }
    }
    if (lane < 16) {
        float inv = 1.f / (sum + 1e-16f);
        logits[n * 16 + lane] = g_res2[n * 16 + lane] + b2[lane] + acc * inv;
    }
}

// ---------------- launch (ONLY kernel launches — graph-capturable) ----------------
extern "C" void kernel_launch(void* const* d_in, const int* in_sizes, int n_in,
                              void* d_out, int out_size)
{
    const float* x0    = (const float*)d_in[0];
    const float* x1    = (const float*)d_in[1];
    const int*   src   = (const int*)d_in[2];
    const int*   dst   = (const int*)d_in[3];
    const float* fc0_W = (const float*)d_in[4];
    const float* fc0_b = (const float*)d_in[5];
    const float* fc1_W = (const float*)d_in[6];
    const float* fc1_b = (const float*)d_in[7];
    const float* W0  = (const float*)d_in[8];
    const float* al0 = (const float*)d_in[9];
    const float* ar0 = (const float*)d_in[10];
    const float* b0  = (const float*)d_in[11];
    const float* W1  = (const float*)d_in[12];
    const float* al1 = (const float*)d_in[13];
    const float* ar1 = (const float*)d_in[14];
    const float* b1  = (const float*)d_in[15];
    const float* W2  = (const float*)d_in[16];
    const float* al2 = (const float*)d_in[17];
    const float* ar2 = (const float*)d_in[18];
    const float* b2  = (const float*)d_in[19];
    const float* resW2 = (const float*)d_in[20];

    float* out    = (float*)d_out;
    float* logits = out;                         // [50000,16]
    float* enc    = out + (size_t)NNODES * 16;   // [50000,512]

    const int FC0_BT = 0, FC1_BT = 16384, W0_BT = 32768, W1_BT = 65536;
    const int NSCAN = (NNODES + 1023) / 1024;    // 49

    k_prep<<<(NNODES + 327680 + 255) / 256, 256>>>(fc0_W, fc1_W, W0, W1);
    k_split_x<<<(NNODES * 256 / 4 + 255) / 256, 256>>>(x0, x1);
    k_count<<<(NEDGES + 255) / 256, 256>>>(dst);
    k_scanA<<<NSCAN, 1024>>>();
    k_scanB<<<1, 64>>>();
    {
        dim3 g(1, (NHALF + 127) / 128);
        gemm_f16<<<g, 256>>>(0, FC0_BT, NHALF, 64, 256, fc0_b, (long long)L0SPLIT);
    }
    k_scanC<<<NSCAN, 1024>>>();
    k_scatter<<<(NEDGES + 255) / 256, 256>>>(dst);
    k_sortseg<<<(NNODES + 255) / 256, 256>>>();
    {
        dim3 g(1, (NHALF + 127) / 128);
        gemm_f16<<<g, 256>>>(NHALF * 256, FC1_BT, NHALF, 64, 256, fc1_b,
                             (long long)L0SPLIT + NHALF * 64);
    }

    // ---- layer 0: 64 -> 8x64 (wide GEMM, 1-term A, el/er fused) ----
    {
        dim3 g(4, (NNODES + 127) / 128);
        gemm_f16w<<<g, 512>>>(L0SPLIT, W0_BT, NNODES, 64, al0, ar0);
    }
    k_agg512<<<NNODES, 128>>>(src, b0, 0, 1, nullptr);   // softmax+agg -> g_h1 + hi split @0

    // ---- layer 1: 512 -> 8x64 (wide GEMM, 1-term A, el/er fused) ----
    {
        dim3 g(4, (NNODES + 127) / 128);
        gemm_f16w<<<g, 512>>>(0, W1_BT, NNODES, 512, al1, ar1);
    }
    k_agg512<<<NNODES, 128>>>(src, b1, 1, 0, enc);       // softmax+agg, resid -> enc

    // ---- output layer: 512 -> 1x16, linear residual ----
    k_l2proj2<<<(NNODES + 127) / 128, 128>>>(enc, W2, resW2, al2, ar2);
    k_agg16<<<NNODES, 32>>>(src, b2, logits);
}